// round 1
// baseline (speedup 1.0000x reference)
#include <cuda_runtime.h>
#include <math.h>

#define BATCH 4
#define CDIM  256
#define HW    2304          // n = 48*48
#define MROWS (BATCH*HW)    // 9216
#define NHEAD 8
#define DHEAD 32
#define QT    128
#define KT    64

// Scratch (static device memory; no runtime allocation allowed)
__device__ float g_xs[MROWS*CDIM];
__device__ float g_q [MROWS*CDIM];
__device__ float g_k [MROWS*CDIM];
__device__ float g_v [MROWS*CDIM];
__device__ float g_ao[MROWS*CDIM];

// ---------------------------------------------------------------------------
// Kernel 1: x [b,c,h,w] -> xs [b,n,c] transpose + positional encoding
// pe[p][i] = (p==0) ? 0 : (i even ? sin : cos)( p / 10000^(2i/256) )
// ---------------------------------------------------------------------------
__global__ void k_transpose_pe(const float* __restrict__ x)
{
    __shared__ float tile[32][33];
    int b  = blockIdx.z;
    int p0 = blockIdx.x * 32;
    int c0 = blockIdx.y * 32;
    int tx = threadIdx.x, ty = threadIdx.y;

    #pragma unroll
    for (int i = 0; i < 4; i++) {
        int cc = c0 + ty + i * 8;
        tile[ty + i * 8][tx] = x[((size_t)(b * CDIM + cc)) * HW + p0 + tx];
    }
    __syncthreads();
    #pragma unroll
    for (int i = 0; i < 4; i++) {
        int p  = p0 + ty + i * 8;
        int cc = c0 + tx;
        float v = tile[tx][ty + i * 8];
        float pe = 0.0f;
        if (p != 0) {
            float ang = (float)p * powf(10000.0f, -2.0f * (float)cc / 256.0f);
            pe = (cc & 1) ? cosf(ang) : sinf(ang);
        }
        g_xs[((size_t)(b * HW + p)) * CDIM + cc] = v + pe;
    }
}

// ---------------------------------------------------------------------------
// GEMM body: out[m][n] = sum_k A[m][k] * W[n][k] + bias[n]
// 64x64 tile, BK=16, 16x16 threads, 4x4 micro-tile.
// trans_out: write out[(b*C+n)*HW + p] (final [b,c,h,w] layout)
// ---------------------------------------------------------------------------
__device__ __forceinline__ void gemm_body(const float* __restrict__ A,
                                          const float* __restrict__ W,
                                          const float* __restrict__ bias,
                                          float* __restrict__ out,
                                          bool trans_out)
{
    __shared__ float As[64][17];
    __shared__ float Bs[64][17];
    int m0 = blockIdx.y * 64;
    int n0 = blockIdx.x * 64;
    int tx = threadIdx.x, ty = threadIdx.y;
    int tid = ty * 16 + tx;
    int lr = tid >> 2;            // 0..63
    int lc = (tid & 3) << 2;      // 0,4,8,12

    float c[4][4];
    #pragma unroll
    for (int i = 0; i < 4; i++)
        #pragma unroll
        for (int j = 0; j < 4; j++) c[i][j] = 0.0f;

    for (int k0 = 0; k0 < CDIM; k0 += 16) {
        float4 a4 = *(const float4*)(A + (size_t)(m0 + lr) * CDIM + k0 + lc);
        float4 b4 = *(const float4*)(W + (size_t)(n0 + lr) * CDIM + k0 + lc);
        As[lr][lc] = a4.x; As[lr][lc+1] = a4.y; As[lr][lc+2] = a4.z; As[lr][lc+3] = a4.w;
        Bs[lr][lc] = b4.x; Bs[lr][lc+1] = b4.y; Bs[lr][lc+2] = b4.z; Bs[lr][lc+3] = b4.w;
        __syncthreads();
        #pragma unroll
        for (int kk = 0; kk < 16; kk++) {
            float a[4], b[4];
            #pragma unroll
            for (int i = 0; i < 4; i++) a[i] = As[ty * 4 + i][kk];
            #pragma unroll
            for (int j = 0; j < 4; j++) b[j] = Bs[tx * 4 + j][kk];
            #pragma unroll
            for (int i = 0; i < 4; i++)
                #pragma unroll
                for (int j = 0; j < 4; j++) c[i][j] += a[i] * b[j];
        }
        __syncthreads();
    }

    #pragma unroll
    for (int i = 0; i < 4; i++) {
        int mm = m0 + ty * 4 + i;
        #pragma unroll
        for (int j = 0; j < 4; j++) {
            int nn = n0 + tx * 4 + j;
            float v = c[i][j] + bias[nn];
            if (!trans_out) {
                out[(size_t)mm * CDIM + nn] = v;
            } else {
                int bb = mm / HW, pp = mm % HW;
                out[((size_t)(bb * CDIM + nn)) * HW + pp] = v;
            }
        }
    }
}

__global__ void k_gemm_qkv(const float* __restrict__ wq, const float* __restrict__ bq,
                           const float* __restrict__ wk, const float* __restrict__ bk,
                           const float* __restrict__ wv, const float* __restrict__ bv)
{
    const float* W; const float* bias; float* out;
    if (blockIdx.z == 0)      { W = wq; bias = bq; out = g_q; }
    else if (blockIdx.z == 1) { W = wk; bias = bk; out = g_k; }
    else                      { W = wv; bias = bv; out = g_v; }
    gemm_body(g_xs, W, bias, out, false);
}

__global__ void k_gemm_out(const float* __restrict__ wo, const float* __restrict__ bo,
                           float* __restrict__ out)
{
    gemm_body(g_ao, wo, bo, out, true);
}

// ---------------------------------------------------------------------------
// Kernel 3: flash attention. Block = (q_tile, b*H). One query row per thread.
// ---------------------------------------------------------------------------
__global__ void __launch_bounds__(128) k_attn()
{
    __shared__ float Ks[KT][DHEAD];
    __shared__ float Vs[KT][DHEAD];
    int b  = blockIdx.y >> 3;
    int h  = blockIdx.y & 7;
    int q0 = blockIdx.x * QT;
    int t  = threadIdx.x;

    const float scale = 0.17677669529663687f;   // 1/sqrt(32)

    float q[DHEAD];
    const float* qptr = g_q + ((size_t)(b * HW + q0 + t)) * CDIM + h * DHEAD;
    #pragma unroll
    for (int d = 0; d < DHEAD; d += 4) {
        float4 f = *(const float4*)(qptr + d);
        q[d] = f.x * scale; q[d+1] = f.y * scale;
        q[d+2] = f.z * scale; q[d+3] = f.w * scale;
    }

    float mrow = -1e30f, l = 0.0f;
    float acc[DHEAD];
    #pragma unroll
    for (int d = 0; d < DHEAD; d++) acc[d] = 0.0f;

    const float* kbase = g_k + ((size_t)b * HW) * CDIM + h * DHEAD;
    const float* vbase = g_v + ((size_t)b * HW) * CDIM + h * DHEAD;

    for (int k0 = 0; k0 < HW; k0 += KT) {
        __syncthreads();
        #pragma unroll
        for (int i = 0; i < 4; i++) {
            int idx = t + i * 128;         // 0..511 float4 slots
            int row = idx >> 3;            // 8 float4 per 32-float row
            int col = (idx & 7) << 2;
            *(float4*)&Ks[row][col] = *(const float4*)(kbase + (size_t)(k0 + row) * CDIM + col);
            *(float4*)&Vs[row][col] = *(const float4*)(vbase + (size_t)(k0 + row) * CDIM + col);
        }
        __syncthreads();

        #pragma unroll
        for (int jc = 0; jc < KT; jc += 16) {
            float s[16];
            float mt = mrow;
            #pragma unroll
            for (int j = 0; j < 16; j++) {
                float acc_s = 0.0f;
                #pragma unroll
                for (int d = 0; d < DHEAD; d++) acc_s += q[d] * Ks[jc + j][d];
                s[j] = acc_s;
                mt = fmaxf(mt, acc_s);
            }
            float corr = __expf(mrow - mt);
            mrow = mt;
            l *= corr;
            #pragma unroll
            for (int d = 0; d < DHEAD; d++) acc[d] *= corr;
            #pragma unroll
            for (int j = 0; j < 16; j++) {
                float p = __expf(s[j] - mrow);
                l += p;
                #pragma unroll
                for (int d = 0; d < DHEAD; d++) acc[d] += p * Vs[jc + j][d];
            }
        }
    }

    float inv = 1.0f / l;
    float* optr = g_ao + ((size_t)(b * HW + q0 + t)) * CDIM + h * DHEAD;
    #pragma unroll
    for (int d = 0; d < DHEAD; d += 4) {
        float4 f;
        f.x = acc[d] * inv; f.y = acc[d+1] * inv;
        f.z = acc[d+2] * inv; f.w = acc[d+3] * inv;
        *(float4*)(optr + d) = f;
    }
}

// ---------------------------------------------------------------------------
extern "C" void kernel_launch(void* const* d_in, const int* in_sizes, int n_in,
                              void* d_out, int out_size)
{
    const float* x  = (const float*)d_in[0];
    const float* wq = (const float*)d_in[1];
    const float* bq = (const float*)d_in[2];
    const float* wk = (const float*)d_in[3];
    const float* bk = (const float*)d_in[4];
    const float* wv = (const float*)d_in[5];
    const float* bv = (const float*)d_in[6];
    const float* wo = (const float*)d_in[7];
    const float* bo = (const float*)d_in[8];

    // 1) transpose + positional encoding
    {
        dim3 blk(32, 8);
        dim3 grd(HW / 32, CDIM / 32, BATCH);
        k_transpose_pe<<<grd, blk>>>(x);
    }
    // 2) fused QKV projections
    {
        dim3 blk(16, 16);
        dim3 grd(CDIM / 64, MROWS / 64, 3);
        k_gemm_qkv<<<grd, blk>>>(wq, bq, wk, bk, wv, bv);
    }
    // 3) flash attention
    {
        dim3 grd(HW / QT, BATCH * NHEAD);
        k_attn<<<grd, 128>>>();
    }
    // 4) output projection + transpose back to [b,c,h,w]
    {
        dim3 blk(16, 16);
        dim3 grd(CDIM / 64, MROWS / 64);
        k_gemm_out<<<grd, blk>>>(wo, bo, (float*)d_out);
    }
}

// round 2
// speedup vs baseline: 1.2873x; 1.2873x over previous
#include <cuda_runtime.h>
#include <math.h>

#define BATCH 4
#define CDIM  256
#define HW    2304          // n = 48*48
#define MROWS (BATCH*HW)    // 9216
#define NHEAD 8
#define DHEAD 32
#define KT    64            // attention key tile
#define QTILE 64            // attention query tile

typedef unsigned long long u64;

// Scratch (static device memory; no runtime allocation allowed)
__device__ float g_xs[MROWS*CDIM];
__device__ float g_q [MROWS*CDIM];
__device__ float g_k [MROWS*CDIM];
__device__ float g_v [MROWS*CDIM];
__device__ float g_ao[MROWS*CDIM];

// ---------------------------------------------------------------------------
// packed f32x2 helpers (sm_100a)
// ---------------------------------------------------------------------------
__device__ __forceinline__ u64 pack2(float lo, float hi) {
    u64 r; asm("mov.b64 %0, {%1, %2};" : "=l"(r) : "f"(lo), "f"(hi)); return r;
}
__device__ __forceinline__ void unpack2(u64 v, float& lo, float& hi) {
    asm("mov.b64 {%0, %1}, %2;" : "=f"(lo), "=f"(hi) : "l"(v));
}
__device__ __forceinline__ void ffma2(u64& d, u64 a, u64 b) {
    asm("fma.rn.f32x2 %0, %1, %2, %0;" : "+l"(d) : "l"(a), "l"(b));
}
__device__ __forceinline__ void fmul2(u64& d, u64 a) {
    asm("mul.rn.f32x2 %0, %0, %1;" : "+l"(d) : "l"(a));
}

// ---------------------------------------------------------------------------
// Kernel 1: x [b,c,h,w] -> xs [b,n,c] transpose + positional encoding
// ---------------------------------------------------------------------------
__global__ void k_transpose_pe(const float* __restrict__ x)
{
    __shared__ float tile[32][33];
    int b  = blockIdx.z;
    int p0 = blockIdx.x * 32;
    int c0 = blockIdx.y * 32;
    int tx = threadIdx.x, ty = threadIdx.y;

    #pragma unroll
    for (int i = 0; i < 4; i++) {
        int cc = c0 + ty + i * 8;
        tile[ty + i * 8][tx] = x[((size_t)(b * CDIM + cc)) * HW + p0 + tx];
    }
    __syncthreads();
    #pragma unroll
    for (int i = 0; i < 4; i++) {
        int p  = p0 + ty + i * 8;
        int cc = c0 + tx;
        float v = tile[tx][ty + i * 8];
        float pe = 0.0f;
        if (p != 0) {
            float ang = (float)p * powf(10000.0f, -2.0f * (float)cc / 256.0f);
            pe = (cc & 1) ? cosf(ang) : sinf(ang);
        }
        g_xs[((size_t)(b * HW + p)) * CDIM + cc] = v + pe;
    }
}

// ---------------------------------------------------------------------------
// GEMM: out[m][n] = sum_k A[m][k] * W[n][k] + bias[n]
// 128x64 tile, BK=16, 16x16 threads, 8x4 micro-tile, f32x2 packed FMA.
// ---------------------------------------------------------------------------
__device__ __forceinline__ void gemm_body(const float* __restrict__ A,
                                          const float* __restrict__ W,
                                          const float* __restrict__ bias,
                                          float* __restrict__ out,
                                          bool trans_out)
{
    __shared__ float As[16][132];   // k-major, 128 m + pad
    __shared__ float Bs[16][68];    // k-major, 64 n + pad

    int m0 = blockIdx.y * 128;
    int n0 = blockIdx.x * 64;
    int tx = threadIdx.x, ty = threadIdx.y;
    int t = ty * 16 + tx;

    // accumulators: row-pairs packed. c2[i2][j]: rows (ty*8+2*i2, +1), col tx*4+j
    u64 c2[4][4];
    #pragma unroll
    for (int i = 0; i < 4; i++)
        #pragma unroll
        for (int j = 0; j < 4; j++) c2[i][j] = 0ull;

    for (int k0 = 0; k0 < CDIM; k0 += 16) {
        // load A tile (128x16) transposed into As[k][m]
        #pragma unroll
        for (int s = t; s < 512; s += 256) {
            int row = s >> 2, kc = (s & 3) * 4;
            float4 a4 = *(const float4*)(A + (size_t)(m0 + row) * CDIM + k0 + kc);
            As[kc][row] = a4.x; As[kc+1][row] = a4.y;
            As[kc+2][row] = a4.z; As[kc+3][row] = a4.w;
        }
        // load B tile (64x16) transposed into Bs[k][n]
        {
            int row = t >> 2, kc = (t & 3) * 4;
            float4 b4 = *(const float4*)(W + (size_t)(n0 + row) * CDIM + k0 + kc);
            Bs[kc][row] = b4.x; Bs[kc+1][row] = b4.y;
            Bs[kc+2][row] = b4.z; Bs[kc+3][row] = b4.w;
        }
        __syncthreads();

        #pragma unroll
        for (int kk = 0; kk < 16; kk++) {
            ulonglong2 a01 = *(const ulonglong2*)&As[kk][ty * 8];
            ulonglong2 a23 = *(const ulonglong2*)&As[kk][ty * 8 + 4];
            float4 b = *(const float4*)&Bs[kk][tx * 4];
            u64 br0 = pack2(b.x, b.x), br1 = pack2(b.y, b.y);
            u64 br2 = pack2(b.z, b.z), br3 = pack2(b.w, b.w);
            ffma2(c2[0][0], a01.x, br0); ffma2(c2[0][1], a01.x, br1);
            ffma2(c2[0][2], a01.x, br2); ffma2(c2[0][3], a01.x, br3);
            ffma2(c2[1][0], a01.y, br0); ffma2(c2[1][1], a01.y, br1);
            ffma2(c2[1][2], a01.y, br2); ffma2(c2[1][3], a01.y, br3);
            ffma2(c2[2][0], a23.x, br0); ffma2(c2[2][1], a23.x, br1);
            ffma2(c2[2][2], a23.x, br2); ffma2(c2[2][3], a23.x, br3);
            ffma2(c2[3][0], a23.y, br0); ffma2(c2[3][1], a23.y, br1);
            ffma2(c2[3][2], a23.y, br2); ffma2(c2[3][3], a23.y, br3);
        }
        __syncthreads();
    }

    float4 bi = *(const float4*)(bias + n0 + tx * 4);
    #pragma unroll
    for (int i2 = 0; i2 < 4; i2++) {
        float vlo[4], vhi[4];
        #pragma unroll
        for (int j = 0; j < 4; j++) unpack2(c2[i2][j], vlo[j], vhi[j]);
        int r0 = m0 + ty * 8 + 2 * i2;
        float4 f0 = make_float4(vlo[0] + bi.x, vlo[1] + bi.y, vlo[2] + bi.z, vlo[3] + bi.w);
        float4 f1 = make_float4(vhi[0] + bi.x, vhi[1] + bi.y, vhi[2] + bi.z, vhi[3] + bi.w);
        if (!trans_out) {
            *(float4*)(out + (size_t)r0 * CDIM + n0 + tx * 4) = f0;
            *(float4*)(out + (size_t)(r0 + 1) * CDIM + n0 + tx * 4) = f1;
        } else {
            int bb0 = r0 / HW, pp0 = r0 % HW;
            int bb1 = (r0 + 1) / HW, pp1 = (r0 + 1) % HW;
            const float* v0 = &f0.x; const float* v1 = &f1.x;
            #pragma unroll
            for (int j = 0; j < 4; j++) {
                int nn = n0 + tx * 4 + j;
                out[((size_t)(bb0 * CDIM + nn)) * HW + pp0] = v0[j];
                out[((size_t)(bb1 * CDIM + nn)) * HW + pp1] = v1[j];
            }
        }
    }
}

__global__ void __launch_bounds__(256) k_gemm_qkv(
    const float* __restrict__ wq, const float* __restrict__ bq,
    const float* __restrict__ wk, const float* __restrict__ bk,
    const float* __restrict__ wv, const float* __restrict__ bv)
{
    const float* W; const float* bias; float* out;
    if (blockIdx.z == 0)      { W = wq; bias = bq; out = g_q; }
    else if (blockIdx.z == 1) { W = wk; bias = bk; out = g_k; }
    else                      { W = wv; bias = bv; out = g_v; }
    gemm_body(g_xs, W, bias, out, false);
}

__global__ void __launch_bounds__(256) k_gemm_out(
    const float* __restrict__ wo, const float* __restrict__ bo,
    float* __restrict__ out)
{
    gemm_body(g_ao, wo, bo, out, true);
}

// ---------------------------------------------------------------------------
// Kernel 3: flash attention, GEMM-style with f32x2.
// Block: 16x16 threads. Q-tile 64, K-tile 64. Grid (HW/64, BATCH*NHEAD).
// Thread (ty,tx): scores rows ty*4..+3 (queries), cols tx*4..+3 (keys);
//                 output rows ty*4..+3, dims tx*2..+1.
// ---------------------------------------------------------------------------
__global__ void __launch_bounds__(256) k_attn()
{
    __shared__ float Qs[DHEAD][68];   // d-major (scaled)
    __shared__ float Ks[DHEAD][68];   // d-major
    __shared__ float Vs[KT][36];      // key-major
    __shared__ float Ps[KT][68];      // key-major: Ps[key][query]

    int b = blockIdx.y >> 3, h = blockIdx.y & 7;
    int q0 = blockIdx.x * QTILE;
    int tx = threadIdx.x, ty = threadIdx.y;
    int t = ty * 16 + tx;
    const float scale = 0.17677669529663687f;   // 1/sqrt(32)

    // load Q once (scaled, transposed)
    const float* qg = g_q + ((size_t)(b * HW + q0)) * CDIM + h * DHEAD;
    #pragma unroll
    for (int s = t; s < 512; s += 256) {
        int row = s >> 3, dc = (s & 7) * 4;
        float4 f = *(const float4*)(qg + (size_t)row * CDIM + dc);
        Qs[dc][row]   = f.x * scale; Qs[dc+1][row] = f.y * scale;
        Qs[dc+2][row] = f.z * scale; Qs[dc+3][row] = f.w * scale;
    }

    float m[4], l[4];
    u64 acc2[2][2];
    #pragma unroll
    for (int i = 0; i < 4; i++) { m[i] = -1e30f; l[i] = 0.0f; }
    acc2[0][0] = acc2[0][1] = acc2[1][0] = acc2[1][1] = 0ull;

    const float* kg = g_k + ((size_t)(b * HW)) * CDIM + h * DHEAD;
    const float* vg = g_v + ((size_t)(b * HW)) * CDIM + h * DHEAD;

    for (int kt = 0; kt < HW; kt += KT) {
        __syncthreads();
        // load K (transposed) and V (row-major) tiles
        #pragma unroll
        for (int s = t; s < 512; s += 256) {
            int row = s >> 3, dc = (s & 7) * 4;
            float4 fk = *(const float4*)(kg + (size_t)(kt + row) * CDIM + dc);
            Ks[dc][row]   = fk.x; Ks[dc+1][row] = fk.y;
            Ks[dc+2][row] = fk.z; Ks[dc+3][row] = fk.w;
            float4 fv = *(const float4*)(vg + (size_t)(kt + row) * CDIM + dc);
            *(float4*)&Vs[row][dc] = fv;
        }
        __syncthreads();

        // ---- S = Q K^T (key-pairs packed) ----
        u64 s2[4][2];
        #pragma unroll
        for (int i = 0; i < 4; i++) { s2[i][0] = 0ull; s2[i][1] = 0ull; }
        #pragma unroll
        for (int dd = 0; dd < DHEAD; dd++) {
            float4 a = *(const float4*)&Qs[dd][ty * 4];
            ulonglong2 bk = *(const ulonglong2*)&Ks[dd][tx * 4];
            u64 ar;
            ar = pack2(a.x, a.x); ffma2(s2[0][0], ar, bk.x); ffma2(s2[0][1], ar, bk.y);
            ar = pack2(a.y, a.y); ffma2(s2[1][0], ar, bk.x); ffma2(s2[1][1], ar, bk.y);
            ar = pack2(a.z, a.z); ffma2(s2[2][0], ar, bk.x); ffma2(s2[2][1], ar, bk.y);
            ar = pack2(a.w, a.w); ffma2(s2[3][0], ar, bk.x); ffma2(s2[3][1], ar, bk.y);
        }
        float sc[4][4];
        #pragma unroll
        for (int i = 0; i < 4; i++) {
            unpack2(s2[i][0], sc[i][0], sc[i][1]);
            unpack2(s2[i][1], sc[i][2], sc[i][3]);
        }

        // ---- online softmax (row reduce across the 16 tx lanes) ----
        float corr[4];
        #pragma unroll
        for (int i = 0; i < 4; i++) {
            float mt = fmaxf(fmaxf(sc[i][0], sc[i][1]), fmaxf(sc[i][2], sc[i][3]));
            #pragma unroll
            for (int w = 1; w < 16; w <<= 1)
                mt = fmaxf(mt, __shfl_xor_sync(0xffffffffu, mt, w));
            float mnew = fmaxf(m[i], mt);
            corr[i] = __expf(m[i] - mnew);
            m[i] = mnew;
            float rs = 0.0f;
            #pragma unroll
            for (int j = 0; j < 4; j++) {
                sc[i][j] = __expf(sc[i][j] - mnew);
                rs += sc[i][j];
            }
            #pragma unroll
            for (int w = 1; w < 16; w <<= 1)
                rs += __shfl_xor_sync(0xffffffffu, rs, w);
            l[i] = l[i] * corr[i] + rs;
        }
        u64 c01 = pack2(corr[0], corr[1]);
        u64 c23 = pack2(corr[2], corr[3]);
        fmul2(acc2[0][0], c01); fmul2(acc2[0][1], c01);
        fmul2(acc2[1][0], c23); fmul2(acc2[1][1], c23);

        // store P (adjacent-query float2 pairs, so PV reads come pre-packed)
        #pragma unroll
        for (int j = 0; j < 4; j++) {
            *(float2*)&Ps[tx * 4 + j][ty * 4]     = make_float2(sc[0][j], sc[1][j]);
            *(float2*)&Ps[tx * 4 + j][ty * 4 + 2] = make_float2(sc[2][j], sc[3][j]);
        }
        __syncthreads();

        // ---- O += P V (query-pairs packed) ----
        #pragma unroll
        for (int kk = 0; kk < KT; kk++) {
            ulonglong2 p2 = *(const ulonglong2*)&Ps[kk][ty * 4];
            float2 v = *(const float2*)&Vs[kk][tx * 2];
            u64 v0 = pack2(v.x, v.x), v1 = pack2(v.y, v.y);
            ffma2(acc2[0][0], p2.x, v0); ffma2(acc2[0][1], p2.x, v1);
            ffma2(acc2[1][0], p2.y, v0); ffma2(acc2[1][1], p2.y, v1);
        }
    }

    // epilogue
    float inv[4];
    #pragma unroll
    for (int i = 0; i < 4; i++) inv[i] = 1.0f / l[i];
    float* og = g_ao + ((size_t)(b * HW + q0)) * CDIM + h * DHEAD;
    #pragma unroll
    for (int i2 = 0; i2 < 2; i2++) {
        float a0l, a0h, a1l, a1h;
        unpack2(acc2[i2][0], a0l, a0h);
        unpack2(acc2[i2][1], a1l, a1h);
        int r0 = 2 * i2, r1 = 2 * i2 + 1;
        float2 f0 = make_float2(a0l * inv[r0], a1l * inv[r0]);
        float2 f1 = make_float2(a0h * inv[r1], a1h * inv[r1]);
        *(float2*)(og + (size_t)(ty * 4 + r0) * CDIM + tx * 2) = f0;
        *(float2*)(og + (size_t)(ty * 4 + r1) * CDIM + tx * 2) = f1;
    }
}

// ---------------------------------------------------------------------------
extern "C" void kernel_launch(void* const* d_in, const int* in_sizes, int n_in,
                              void* d_out, int out_size)
{
    const float* x  = (const float*)d_in[0];
    const float* wq = (const float*)d_in[1];
    const float* bq = (const float*)d_in[2];
    const float* wk = (const float*)d_in[3];
    const float* bk = (const float*)d_in[4];
    const float* wv = (const float*)d_in[5];
    const float* bv = (const float*)d_in[6];
    const float* wo = (const float*)d_in[7];
    const float* bo = (const float*)d_in[8];

    {   // 1) transpose + positional encoding
        dim3 blk(32, 8);
        dim3 grd(HW / 32, CDIM / 32, BATCH);
        k_transpose_pe<<<grd, blk>>>(x);
    }
    {   // 2) fused QKV projections
        dim3 blk(16, 16);
        dim3 grd(CDIM / 64, MROWS / 128, 3);
        k_gemm_qkv<<<grd, blk>>>(wq, bq, wk, bk, wv, bv);
    }
    {   // 3) flash attention
        dim3 blk(16, 16);
        dim3 grd(HW / QTILE, BATCH * NHEAD);
        k_attn<<<grd, blk>>>();
    }
    {   // 4) output projection + transpose back to [b,c,h,w]
        dim3 blk(16, 16);
        dim3 grd(CDIM / 64, MROWS / 128);
        k_gemm_out<<<grd, blk>>>(wo, bo, (float*)d_out);
    }
}

// round 5
// speedup vs baseline: 2.8311x; 2.1992x over previous
#include <cuda_runtime.h>
#include <cuda_bf16.h>
#include <math.h>
#include <stdint.h>

#define BATCH 4
#define CDIM  256
#define HW    2304          // n = 48*48
#define MROWS (BATCH*HW)    // 9216
#define NHEAD 8
#define DHEAD 32

typedef unsigned long long u64;
typedef unsigned int u32;
typedef unsigned short u16;

// Scratch (static device memory; no runtime allocation allowed)
__device__ float g_xs[MROWS*CDIM];
__device__ float g_q [MROWS*CDIM];
__device__ float g_k [MROWS*CDIM];
__device__ float g_v [MROWS*CDIM];
__device__ float g_ao[MROWS*CDIM];

// ---------------------------------------------------------------------------
// helpers
// ---------------------------------------------------------------------------
__device__ __forceinline__ u64 pack2(float lo, float hi) {
    u64 r; asm("mov.b64 %0, {%1, %2};" : "=l"(r) : "f"(lo), "f"(hi)); return r;
}
__device__ __forceinline__ void unpack2(u64 v, float& lo, float& hi) {
    asm("mov.b64 {%0, %1}, %2;" : "=f"(lo), "=f"(hi) : "l"(v));
}
__device__ __forceinline__ void ffma2(u64& d, u64 a, u64 b) {
    asm("fma.rn.f32x2 %0, %1, %2, %0;" : "+l"(d) : "l"(a), "l"(b));
}

// pack two floats as bf16x2: r.lo = lo, r.hi = hi
__device__ __forceinline__ u32 bf2(float lo, float hi) {
    u32 r; asm("cvt.rn.bf16x2.f32 %0, %1, %2;" : "=r"(r) : "f"(hi), "f"(lo));
    return r;
}
// split pair (x0,x1) into bf16 hi + bf16 residual lo (packed)
__device__ __forceinline__ void bsplit2(float x0, float x1, u32& h, u32& l) {
    h = bf2(x0, x1);
    float h0 = __uint_as_float(h << 16);
    float h1 = __uint_as_float(h & 0xFFFF0000u);
    l = bf2(x0 - h0, x1 - h1);
}

__device__ __forceinline__ void mma16816(float d[4], const u32 a[4], u32 b0, u32 b1) {
    asm volatile("mma.sync.aligned.m16n8k16.row.col.f32.bf16.bf16.f32 "
        "{%0,%1,%2,%3}, {%4,%5,%6,%7}, {%8,%9}, {%0,%1,%2,%3};"
        : "+f"(d[0]), "+f"(d[1]), "+f"(d[2]), "+f"(d[3])
        : "r"(a[0]), "r"(a[1]), "r"(a[2]), "r"(a[3]), "r"(b0), "r"(b1));
}

// ---------------------------------------------------------------------------
// Kernel 1: x [b,c,h,w] -> xs [b,n,c] transpose + positional encoding
// ---------------------------------------------------------------------------
__global__ void k_transpose_pe(const float* __restrict__ x)
{
    __shared__ float tile[32][33];
    int b  = blockIdx.z;
    int p0 = blockIdx.x * 32;
    int c0 = blockIdx.y * 32;
    int tx = threadIdx.x, ty = threadIdx.y;

    #pragma unroll
    for (int i = 0; i < 4; i++) {
        int cc = c0 + ty + i * 8;
        tile[ty + i * 8][tx] = x[((size_t)(b * CDIM + cc)) * HW + p0 + tx];
    }
    __syncthreads();
    #pragma unroll
    for (int i = 0; i < 4; i++) {
        int p  = p0 + ty + i * 8;
        int cc = c0 + tx;
        float v = tile[tx][ty + i * 8];
        float pe = 0.0f;
        if (p != 0) {
            float ang = (float)p * powf(10000.0f, -2.0f * (float)cc / 256.0f);
            pe = (cc & 1) ? cosf(ang) : sinf(ang);
        }
        g_xs[((size_t)(b * HW + p)) * CDIM + cc] = v + pe;
    }
}

// ---------------------------------------------------------------------------
// FFMA2 GEMM: out[m][n] = sum_k A[m][k] * W[n][k] + bias[n]   (R2, passing)
// ---------------------------------------------------------------------------
__device__ __forceinline__ void gemm_body(const float* __restrict__ A,
                                          const float* __restrict__ W,
                                          const float* __restrict__ bias,
                                          float* __restrict__ out,
                                          bool trans_out)
{
    __shared__ float As[16][132];
    __shared__ float Bs[16][68];

    int m0 = blockIdx.y * 128;
    int n0 = blockIdx.x * 64;
    int tx = threadIdx.x, ty = threadIdx.y;
    int t = ty * 16 + tx;

    u64 c2[4][4];
    #pragma unroll
    for (int i = 0; i < 4; i++)
        #pragma unroll
        for (int j = 0; j < 4; j++) c2[i][j] = 0ull;

    for (int k0 = 0; k0 < CDIM; k0 += 16) {
        #pragma unroll
        for (int s = t; s < 512; s += 256) {
            int row = s >> 2, kc = (s & 3) * 4;
            float4 a4 = *(const float4*)(A + (size_t)(m0 + row) * CDIM + k0 + kc);
            As[kc][row] = a4.x; As[kc+1][row] = a4.y;
            As[kc+2][row] = a4.z; As[kc+3][row] = a4.w;
        }
        {
            int row = t >> 2, kc = (t & 3) * 4;
            float4 b4 = *(const float4*)(W + (size_t)(n0 + row) * CDIM + k0 + kc);
            Bs[kc][row] = b4.x; Bs[kc+1][row] = b4.y;
            Bs[kc+2][row] = b4.z; Bs[kc+3][row] = b4.w;
        }
        __syncthreads();

        #pragma unroll
        for (int kk = 0; kk < 16; kk++) {
            ulonglong2 a01 = *(const ulonglong2*)&As[kk][ty * 8];
            ulonglong2 a23 = *(const ulonglong2*)&As[kk][ty * 8 + 4];
            float4 b = *(const float4*)&Bs[kk][tx * 4];
            u64 br0 = pack2(b.x, b.x), br1 = pack2(b.y, b.y);
            u64 br2 = pack2(b.z, b.z), br3 = pack2(b.w, b.w);
            ffma2(c2[0][0], a01.x, br0); ffma2(c2[0][1], a01.x, br1);
            ffma2(c2[0][2], a01.x, br2); ffma2(c2[0][3], a01.x, br3);
            ffma2(c2[1][0], a01.y, br0); ffma2(c2[1][1], a01.y, br1);
            ffma2(c2[1][2], a01.y, br2); ffma2(c2[1][3], a01.y, br3);
            ffma2(c2[2][0], a23.x, br0); ffma2(c2[2][1], a23.x, br1);
            ffma2(c2[2][2], a23.x, br2); ffma2(c2[2][3], a23.x, br3);
            ffma2(c2[3][0], a23.y, br0); ffma2(c2[3][1], a23.y, br1);
            ffma2(c2[3][2], a23.y, br2); ffma2(c2[3][3], a23.y, br3);
        }
        __syncthreads();
    }

    float4 bi = *(const float4*)(bias + n0 + tx * 4);
    #pragma unroll
    for (int i2 = 0; i2 < 4; i2++) {
        float vlo[4], vhi[4];
        #pragma unroll
        for (int j = 0; j < 4; j++) unpack2(c2[i2][j], vlo[j], vhi[j]);
        int r0 = m0 + ty * 8 + 2 * i2;
        float4 f0 = make_float4(vlo[0] + bi.x, vlo[1] + bi.y, vlo[2] + bi.z, vlo[3] + bi.w);
        float4 f1 = make_float4(vhi[0] + bi.x, vhi[1] + bi.y, vhi[2] + bi.z, vhi[3] + bi.w);
        if (!trans_out) {
            *(float4*)(out + (size_t)r0 * CDIM + n0 + tx * 4) = f0;
            *(float4*)(out + (size_t)(r0 + 1) * CDIM + n0 + tx * 4) = f1;
        } else {
            int bb0 = r0 / HW, pp0 = r0 % HW;
            int bb1 = (r0 + 1) / HW, pp1 = (r0 + 1) % HW;
            const float* v0 = &f0.x; const float* v1 = &f1.x;
            #pragma unroll
            for (int j = 0; j < 4; j++) {
                int nn = n0 + tx * 4 + j;
                out[((size_t)(bb0 * CDIM + nn)) * HW + pp0] = v0[j];
                out[((size_t)(bb1 * CDIM + nn)) * HW + pp1] = v1[j];
            }
        }
    }
}

__global__ void __launch_bounds__(256) k_gemm_qkv(
    const float* __restrict__ wq, const float* __restrict__ bq,
    const float* __restrict__ wk, const float* __restrict__ bk,
    const float* __restrict__ wv, const float* __restrict__ bv)
{
    const float* W; const float* bias; float* out;
    if (blockIdx.z == 0)      { W = wq; bias = bq; out = g_q; }
    else if (blockIdx.z == 1) { W = wk; bias = bk; out = g_k; }
    else                      { W = wv; bias = bv; out = g_v; }
    gemm_body(g_xs, W, bias, out, false);
}

__global__ void __launch_bounds__(256) k_gemm_out(
    const float* __restrict__ wo, const float* __restrict__ bo,
    float* __restrict__ out)
{
    gemm_body(g_ao, wo, bo, out, true);
}

// ---------------------------------------------------------------------------
// Kernel 3: flash attention on mma.sync bf16 (split hi/lo, 3-pass per GEMM).
// Block = 256 threads = 8 warps; warp w owns queries q0+16w..+15.
// K-tile = 64 keys. No max-subtraction (scores bounded); fp32 row sums.
// ---------------------------------------------------------------------------
#define KSTRIDE 40   // halves per K smem row (bank-conflict-free, 16B-aligned)
#define VSTRIDE 72   // halves per Vt smem row

__global__ void __launch_bounds__(256, 2) k_attn_mma()
{
    __shared__ u16 Khi[64 * KSTRIDE];
    __shared__ u16 Klo[64 * KSTRIDE];
    __shared__ u16 Vthi[32 * VSTRIDE];
    __shared__ u16 Vtlo[32 * VSTRIDE];

    int tid = threadIdx.x;
    int w = tid >> 5, lane = tid & 31;
    int r = lane >> 2, c2 = (lane & 3) * 2;
    int b = blockIdx.y >> 3, h = blockIdx.y & 7;
    int q0 = blockIdx.x * 128;
    const float scale = 0.17677669529663687f;   // 1/sqrt(32)

    // ---- Q a-fragments (scaled, split hi/lo), 2 k-chunks of 16 dims ----
    u32 qh[2][4], ql[2][4];
    {
        const float* qbase = g_q + ((size_t)(b * HW + q0 + w * 16)) * CDIM + h * DHEAD;
        #pragma unroll
        for (int kc = 0; kc < 2; kc++)
            #pragma unroll
            for (int i = 0; i < 4; i++) {
                int rr = r + (i & 1) * 8;
                int cc = kc * 16 + c2 + (i >> 1) * 8;
                float2 f = *(const float2*)(qbase + (size_t)rr * CDIM + cc);
                bsplit2(f.x * scale, f.y * scale, qh[kc][i], ql[kc][i]);
            }
    }

    float o[4][4];
    #pragma unroll
    for (int i = 0; i < 4; i++)
        #pragma unroll
        for (int j = 0; j < 4; j++) o[i][j] = 0.0f;
    float lsum0 = 0.0f, lsum1 = 0.0f;

    const float* kg = g_k + ((size_t)(b * HW)) * CDIM + h * DHEAD;
    const float* vg = g_v + ((size_t)(b * HW)) * CDIM + h * DHEAD;

    for (int kt = 0; kt < HW / 64; kt++) {
        __syncthreads();
        // ---- stage K tile: thread t -> key t>>2, dims (t&3)*8..+7 ----
        {
            int key = tid >> 2, d0 = (tid & 3) * 8;
            const float* src = kg + (size_t)(kt * 64 + key) * CDIM + d0;
            float4 f0 = *(const float4*)(src);
            float4 f1 = *(const float4*)(src + 4);
            u32 hh[4], ll[4];
            bsplit2(f0.x, f0.y, hh[0], ll[0]);
            bsplit2(f0.z, f0.w, hh[1], ll[1]);
            bsplit2(f1.x, f1.y, hh[2], ll[2]);
            bsplit2(f1.z, f1.w, hh[3], ll[3]);
            *(uint4*)&Khi[key * KSTRIDE + d0] = make_uint4(hh[0], hh[1], hh[2], hh[3]);
            *(uint4*)&Klo[key * KSTRIDE + d0] = make_uint4(ll[0], ll[1], ll[2], ll[3]);
        }
        // ---- stage V tile transposed: thread t -> key t&63, dims (t>>6)*8..+7 ----
        {
            int key = tid & 63, d0 = (tid >> 6) * 8;
            const float* src = vg + (size_t)(kt * 64 + key) * CDIM + d0;
            float4 f0 = *(const float4*)(src);
            float4 f1 = *(const float4*)(src + 4);
            float vv[8] = { f0.x, f0.y, f0.z, f0.w, f1.x, f1.y, f1.z, f1.w };
            #pragma unroll
            for (int j = 0; j < 8; j++) {
                __nv_bfloat16 hb = __float2bfloat16_rn(vv[j]);
                float hf = __bfloat162float(hb);
                __nv_bfloat16 lb = __float2bfloat16_rn(vv[j] - hf);
                Vthi[(d0 + j) * VSTRIDE + key] = *(u16*)&hb;
                Vtlo[(d0 + j) * VSTRIDE + key] = *(u16*)&lb;
            }
        }
        __syncthreads();

        // ---- S = Q K^T : 8 key-chunks x 2 d-chunks x 3 passes ----
        float s[8][4];
        #pragma unroll
        for (int i = 0; i < 8; i++)
            #pragma unroll
            for (int j = 0; j < 4; j++) s[i][j] = 0.0f;

        #pragma unroll
        for (int kc = 0; kc < 2; kc++)
            #pragma unroll
            for (int nc = 0; nc < 8; nc++) {
                int key = nc * 8 + r;
                int off = key * KSTRIDE + kc * 16 + c2;
                u32 bh0 = *(const u32*)&Khi[off];
                u32 bh1 = *(const u32*)&Khi[off + 8];
                u32 bl0 = *(const u32*)&Klo[off];
                u32 bl1 = *(const u32*)&Klo[off + 8];
                mma16816(s[nc], qh[kc], bh0, bh1);
                mma16816(s[nc], qh[kc], bl0, bl1);
                mma16816(s[nc], ql[kc], bh0, bh1);
            }

        // ---- softmax (no max-sub; exact fp32 sums) + split P to bf16 ----
        u32 ph[4][4], pl[4][4];
        #pragma unroll
        for (int j = 0; j < 8; j++) {
            float p0 = __expf(s[j][0]);
            float p1 = __expf(s[j][1]);
            float p2 = __expf(s[j][2]);
            float p3 = __expf(s[j][3]);
            lsum0 += p0 + p1;
            lsum1 += p2 + p3;
            int kc2 = j >> 1, hl = (j & 1) * 1;
            bsplit2(p0, p1, ph[kc2][hl * 2 + 0], pl[kc2][hl * 2 + 0]);
            bsplit2(p2, p3, ph[kc2][hl * 2 + 1], pl[kc2][hl * 2 + 1]);
        }

        // ---- O += P V : 4 k-chunks x 4 d-chunks x 3 passes ----
        #pragma unroll
        for (int kc2 = 0; kc2 < 4; kc2++)
            #pragma unroll
            for (int nc2 = 0; nc2 < 4; nc2++) {
                int d = nc2 * 8 + r;
                int off = d * VSTRIDE + kc2 * 16 + c2;
                u32 vh0 = *(const u32*)&Vthi[off];
                u32 vh1 = *(const u32*)&Vthi[off + 8];
                u32 vl0 = *(const u32*)&Vtlo[off];
                u32 vl1 = *(const u32*)&Vtlo[off + 8];
                mma16816(o[nc2], ph[kc2], vh0, vh1);
                mma16816(o[nc2], ph[kc2], vl0, vl1);
                mma16816(o[nc2], pl[kc2], vh0, vh1);
            }
    }

    // ---- epilogue: normalize rows, write g_ao ----
    lsum0 += __shfl_xor_sync(0xffffffffu, lsum0, 1);
    lsum0 += __shfl_xor_sync(0xffffffffu, lsum0, 2);
    lsum1 += __shfl_xor_sync(0xffffffffu, lsum1, 1);
    lsum1 += __shfl_xor_sync(0xffffffffu, lsum1, 2);
    float inv0 = 1.0f / lsum0, inv1 = 1.0f / lsum1;

    int row0 = q0 + w * 16 + r;
    float* og0 = g_ao + ((size_t)(b * HW + row0)) * CDIM + h * DHEAD;
    float* og1 = og0 + 8 * CDIM;
    #pragma unroll
    for (int nc2 = 0; nc2 < 4; nc2++) {
        *(float2*)(og0 + nc2 * 8 + c2) = make_float2(o[nc2][0] * inv0, o[nc2][1] * inv0);
        *(float2*)(og1 + nc2 * 8 + c2) = make_float2(o[nc2][2] * inv1, o[nc2][3] * inv1);
    }
}

// ---------------------------------------------------------------------------
extern "C" void kernel_launch(void* const* d_in, const int* in_sizes, int n_in,
                              void* d_out, int out_size)
{
    const float* x  = (const float*)d_in[0];
    const float* wq = (const float*)d_in[1];
    const float* bq = (const float*)d_in[2];
    const float* wk = (const float*)d_in[3];
    const float* bk = (const float*)d_in[4];
    const float* wv = (const float*)d_in[5];
    const float* bv = (const float*)d_in[6];
    const float* wo = (const float*)d_in[7];
    const float* bo = (const float*)d_in[8];

    {   // 1) transpose + positional encoding
        dim3 blk(32, 8);
        dim3 grd(HW / 32, CDIM / 32, BATCH);
        k_transpose_pe<<<grd, blk>>>(x);
    }
    {   // 2) fused QKV projections
        dim3 blk(16, 16);
        dim3 grd(CDIM / 64, MROWS / 128, 3);
        k_gemm_qkv<<<grd, blk>>>(wq, bq, wk, bk, wv, bv);
    }
    {   // 3) flash attention on tensor cores (mma.sync bf16 split)
        dim3 grd(HW / 128, BATCH * NHEAD);
        k_attn_mma<<<grd, 256>>>();
    }
    {   // 4) output projection + transpose back to [b,c,h,w]
        dim3 blk(16, 16);
        dim3 grd(CDIM / 64, MROWS / 128);
        k_gemm_out<<<grd, blk>>>(wo, bo, (float*)d_out);
    }
}

// round 6
// speedup vs baseline: 3.3818x; 1.1945x over previous
#include <cuda_runtime.h>
#include <cuda_bf16.h>
#include <math.h>
#include <stdint.h>

#define BATCH 4
#define CDIM  256
#define HW    2304          // n = 48*48
#define MROWS (BATCH*HW)    // 9216
#define NHEAD 8
#define DHEAD 32

typedef unsigned long long u64;
typedef unsigned int u32;
typedef unsigned short u16;

// Scratch (static device memory; no runtime allocation allowed)
__device__ float g_xs[MROWS*CDIM];
__device__ float g_q [MROWS*CDIM];
__device__ float g_k [MROWS*CDIM];
__device__ float g_v [MROWS*CDIM];
__device__ float g_ao[MROWS*CDIM];

// ---------------------------------------------------------------------------
// helpers
// ---------------------------------------------------------------------------
// pack two floats as bf16x2: r.lo = lo, r.hi = hi
__device__ __forceinline__ u32 bf2(float lo, float hi) {
    u32 r; asm("cvt.rn.bf16x2.f32 %0, %1, %2;" : "=r"(r) : "f"(hi), "f"(lo));
    return r;
}
// split pair (x0,x1) into bf16 hi + bf16 residual lo (packed)
__device__ __forceinline__ void bsplit2(float x0, float x1, u32& h, u32& l) {
    h = bf2(x0, x1);
    float h0 = __uint_as_float(h << 16);
    float h1 = __uint_as_float(h & 0xFFFF0000u);
    l = bf2(x0 - h0, x1 - h1);
}

__device__ __forceinline__ void mma16816(float d[4], const u32 a[4], u32 b0, u32 b1) {
    asm volatile("mma.sync.aligned.m16n8k16.row.col.f32.bf16.bf16.f32 "
        "{%0,%1,%2,%3}, {%4,%5,%6,%7}, {%8,%9}, {%0,%1,%2,%3};"
        : "+f"(d[0]), "+f"(d[1]), "+f"(d[2]), "+f"(d[3])
        : "r"(a[0]), "r"(a[1]), "r"(a[2]), "r"(a[3]), "r"(b0), "r"(b1));
}

// ---------------------------------------------------------------------------
// Kernel 1: x [b,c,h,w] -> xs [b,n,c] transpose + positional encoding
// ---------------------------------------------------------------------------
__global__ void k_transpose_pe(const float* __restrict__ x)
{
    __shared__ float tile[32][33];
    int b  = blockIdx.z;
    int p0 = blockIdx.x * 32;
    int c0 = blockIdx.y * 32;
    int tx = threadIdx.x, ty = threadIdx.y;

    #pragma unroll
    for (int i = 0; i < 4; i++) {
        int cc = c0 + ty + i * 8;
        tile[ty + i * 8][tx] = x[((size_t)(b * CDIM + cc)) * HW + p0 + tx];
    }
    __syncthreads();
    #pragma unroll
    for (int i = 0; i < 4; i++) {
        int p  = p0 + ty + i * 8;
        int cc = c0 + tx;
        float v = tile[tx][ty + i * 8];
        float pe = 0.0f;
        if (p != 0) {
            float ang = (float)p * powf(10000.0f, -2.0f * (float)cc / 256.0f);
            pe = (cc & 1) ? cosf(ang) : sinf(ang);
        }
        g_xs[((size_t)(b * HW + p)) * CDIM + cc] = v + pe;
    }
}

// ---------------------------------------------------------------------------
// Projection GEMM on mma.sync bf16 split (3 passes): out = A @ W^T + bias
// Block = 256 thr = 8 warps; tile 128m x 64n; K chunks of 64 staged (W only).
// A fragments loaded directly from gmem (each element touched once / block).
// ---------------------------------------------------------------------------
#define PJSTRIDE 72   // halves per W smem row (64 + 8 pad) — LDS conflict-free

__device__ __forceinline__ void proj_mma_body(const float* __restrict__ A,
                                              const float* __restrict__ W,
                                              const float* __restrict__ bias,
                                              float* __restrict__ out,
                                              bool trans_out)
{
    __shared__ u16 Whi[64 * PJSTRIDE];
    __shared__ u16 Wlo[64 * PJSTRIDE];

    int tid = threadIdx.x;
    int w = tid >> 5, lane = tid & 31;
    int r = lane >> 2, c2 = (lane & 3) * 2;
    int m0 = blockIdx.y * 128;
    int n0 = blockIdx.x * 64;

    float o[8][4];
    #pragma unroll
    for (int i = 0; i < 8; i++)
        #pragma unroll
        for (int j = 0; j < 4; j++) o[i][j] = 0.0f;

    const float* arow0 = A + (size_t)(m0 + w * 16 + r) * CDIM;
    const float* arow1 = arow0 + 8 * CDIM;

    for (int k0 = 0; k0 < CDIM; k0 += 64) {
        __syncthreads();
        // ---- stage + split W[n0..+63][k0..+63]: thread -> row tid>>2, 16 cols ----
        {
            int row = tid >> 2, col0 = (tid & 3) * 16;
            const float* src = W + (size_t)(n0 + row) * CDIM + k0 + col0;
            float4 f0 = *(const float4*)(src);
            float4 f1 = *(const float4*)(src + 4);
            float4 f2 = *(const float4*)(src + 8);
            float4 f3 = *(const float4*)(src + 12);
            u32 hh[8], ll[8];
            bsplit2(f0.x, f0.y, hh[0], ll[0]);
            bsplit2(f0.z, f0.w, hh[1], ll[1]);
            bsplit2(f1.x, f1.y, hh[2], ll[2]);
            bsplit2(f1.z, f1.w, hh[3], ll[3]);
            bsplit2(f2.x, f2.y, hh[4], ll[4]);
            bsplit2(f2.z, f2.w, hh[5], ll[5]);
            bsplit2(f3.x, f3.y, hh[6], ll[6]);
            bsplit2(f3.z, f3.w, hh[7], ll[7]);
            int ws = row * PJSTRIDE + col0;
            *(uint4*)&Whi[ws]     = make_uint4(hh[0], hh[1], hh[2], hh[3]);
            *(uint4*)&Whi[ws + 8] = make_uint4(hh[4], hh[5], hh[6], hh[7]);
            *(uint4*)&Wlo[ws]     = make_uint4(ll[0], ll[1], ll[2], ll[3]);
            *(uint4*)&Wlo[ws + 8] = make_uint4(ll[4], ll[5], ll[6], ll[7]);
        }
        __syncthreads();

        #pragma unroll
        for (int kc = 0; kc < 4; kc++) {
            // A fragments straight from gmem, split in registers
            u32 ah[4], al[4];
            int cb = k0 + kc * 16 + c2;
            float2 f;
            f = *(const float2*)(arow0 + cb);     bsplit2(f.x, f.y, ah[0], al[0]);
            f = *(const float2*)(arow1 + cb);     bsplit2(f.x, f.y, ah[1], al[1]);
            f = *(const float2*)(arow0 + cb + 8); bsplit2(f.x, f.y, ah[2], al[2]);
            f = *(const float2*)(arow1 + cb + 8); bsplit2(f.x, f.y, ah[3], al[3]);
            #pragma unroll
            for (int nc = 0; nc < 8; nc++) {
                int off = (nc * 8 + r) * PJSTRIDE + kc * 16 + c2;
                u32 bh0 = *(const u32*)&Whi[off];
                u32 bh1 = *(const u32*)&Whi[off + 8];
                u32 bl0 = *(const u32*)&Wlo[off];
                u32 bl1 = *(const u32*)&Wlo[off + 8];
                mma16816(o[nc], ah, bh0, bh1);
                mma16816(o[nc], ah, bl0, bl1);
                mma16816(o[nc], al, bh0, bh1);
            }
        }
    }

    // ---- epilogue: bias + store ----
    int mr0 = m0 + w * 16 + r;
    int mr1 = mr0 + 8;
    if (!trans_out) {
        float* og0 = out + (size_t)mr0 * CDIM + n0;
        float* og1 = out + (size_t)mr1 * CDIM + n0;
        #pragma unroll
        for (int nc = 0; nc < 8; nc++) {
            float2 bi = *(const float2*)(bias + n0 + nc * 8 + c2);
            *(float2*)(og0 + nc * 8 + c2) = make_float2(o[nc][0] + bi.x, o[nc][1] + bi.y);
            *(float2*)(og1 + nc * 8 + c2) = make_float2(o[nc][2] + bi.x, o[nc][3] + bi.y);
        }
    } else {
        int bb0 = mr0 / HW, pp0 = mr0 % HW;
        int bb1 = mr1 / HW, pp1 = mr1 % HW;
        #pragma unroll
        for (int nc = 0; nc < 8; nc++) {
            float2 bi = *(const float2*)(bias + n0 + nc * 8 + c2);
            int nn = n0 + nc * 8 + c2;
            out[((size_t)(bb0 * CDIM + nn)) * HW + pp0]     = o[nc][0] + bi.x;
            out[((size_t)(bb0 * CDIM + nn + 1)) * HW + pp0] = o[nc][1] + bi.y;
            out[((size_t)(bb1 * CDIM + nn)) * HW + pp1]     = o[nc][2] + bi.x;
            out[((size_t)(bb1 * CDIM + nn + 1)) * HW + pp1] = o[nc][3] + bi.y;
        }
    }
}

__global__ void __launch_bounds__(256) k_proj_qkv(
    const float* __restrict__ wq, const float* __restrict__ bq,
    const float* __restrict__ wk, const float* __restrict__ bk,
    const float* __restrict__ wv, const float* __restrict__ bv)
{
    const float* W; const float* bias; float* out;
    if (blockIdx.z == 0)      { W = wq; bias = bq; out = g_q; }
    else if (blockIdx.z == 1) { W = wk; bias = bk; out = g_k; }
    else                      { W = wv; bias = bv; out = g_v; }
    proj_mma_body(g_xs, W, bias, out, false);
}

__global__ void __launch_bounds__(256) k_proj_out(
    const float* __restrict__ wo, const float* __restrict__ bo,
    float* __restrict__ out)
{
    proj_mma_body(g_ao, wo, bo, out, true);
}

// ---------------------------------------------------------------------------
// Kernel 3: flash attention on mma.sync bf16 (split hi/lo, 3-pass per GEMM).
// Block = 256 threads = 8 warps; warp w owns queries q0+16w..+15.
// K-tile = 64 keys. No max-subtraction (scores bounded); fp32 row sums.
// ---------------------------------------------------------------------------
#define KSTRIDE 40   // halves per K smem row (bank-conflict-free, 16B-aligned)
#define VSTRIDE 72   // halves per Vt smem row

__global__ void __launch_bounds__(256, 2) k_attn_mma()
{
    __shared__ u16 Khi[64 * KSTRIDE];
    __shared__ u16 Klo[64 * KSTRIDE];
    __shared__ u16 Vthi[32 * VSTRIDE];
    __shared__ u16 Vtlo[32 * VSTRIDE];

    int tid = threadIdx.x;
    int w = tid >> 5, lane = tid & 31;
    int r = lane >> 2, c2 = (lane & 3) * 2;
    int b = blockIdx.y >> 3, h = blockIdx.y & 7;
    int q0 = blockIdx.x * 128;
    const float scale = 0.17677669529663687f;   // 1/sqrt(32)

    // ---- Q a-fragments (scaled, split hi/lo), 2 k-chunks of 16 dims ----
    u32 qh[2][4], ql[2][4];
    {
        const float* qbase = g_q + ((size_t)(b * HW + q0 + w * 16)) * CDIM + h * DHEAD;
        #pragma unroll
        for (int kc = 0; kc < 2; kc++)
            #pragma unroll
            for (int i = 0; i < 4; i++) {
                int rr = r + (i & 1) * 8;
                int cc = kc * 16 + c2 + (i >> 1) * 8;
                float2 f = *(const float2*)(qbase + (size_t)rr * CDIM + cc);
                bsplit2(f.x * scale, f.y * scale, qh[kc][i], ql[kc][i]);
            }
    }

    float o[4][4];
    #pragma unroll
    for (int i = 0; i < 4; i++)
        #pragma unroll
        for (int j = 0; j < 4; j++) o[i][j] = 0.0f;
    float lsum0 = 0.0f, lsum1 = 0.0f;

    const float* kg = g_k + ((size_t)(b * HW)) * CDIM + h * DHEAD;
    const float* vg = g_v + ((size_t)(b * HW)) * CDIM + h * DHEAD;

    for (int kt = 0; kt < HW / 64; kt++) {
        __syncthreads();
        // ---- stage K tile: thread t -> key t>>2, dims (t&3)*8..+7 ----
        {
            int key = tid >> 2, d0 = (tid & 3) * 8;
            const float* src = kg + (size_t)(kt * 64 + key) * CDIM + d0;
            float4 f0 = *(const float4*)(src);
            float4 f1 = *(const float4*)(src + 4);
            u32 hh[4], ll[4];
            bsplit2(f0.x, f0.y, hh[0], ll[0]);
            bsplit2(f0.z, f0.w, hh[1], ll[1]);
            bsplit2(f1.x, f1.y, hh[2], ll[2]);
            bsplit2(f1.z, f1.w, hh[3], ll[3]);
            *(uint4*)&Khi[key * KSTRIDE + d0] = make_uint4(hh[0], hh[1], hh[2], hh[3]);
            *(uint4*)&Klo[key * KSTRIDE + d0] = make_uint4(ll[0], ll[1], ll[2], ll[3]);
        }
        // ---- stage V tile transposed: thread t -> key t&63, dims (t>>6)*8..+7 ----
        {
            int key = tid & 63, d0 = (tid >> 6) * 8;
            const float* src = vg + (size_t)(kt * 64 + key) * CDIM + d0;
            float4 f0 = *(const float4*)(src);
            float4 f1 = *(const float4*)(src + 4);
            float vv[8] = { f0.x, f0.y, f0.z, f0.w, f1.x, f1.y, f1.z, f1.w };
            #pragma unroll
            for (int j = 0; j < 8; j++) {
                __nv_bfloat16 hb = __float2bfloat16_rn(vv[j]);
                float hf = __bfloat162float(hb);
                __nv_bfloat16 lb = __float2bfloat16_rn(vv[j] - hf);
                Vthi[(d0 + j) * VSTRIDE + key] = *(u16*)&hb;
                Vtlo[(d0 + j) * VSTRIDE + key] = *(u16*)&lb;
            }
        }
        __syncthreads();

        // ---- S = Q K^T : 8 key-chunks x 2 d-chunks x 3 passes ----
        float s[8][4];
        #pragma unroll
        for (int i = 0; i < 8; i++)
            #pragma unroll
            for (int j = 0; j < 4; j++) s[i][j] = 0.0f;

        #pragma unroll
        for (int kc = 0; kc < 2; kc++)
            #pragma unroll
            for (int nc = 0; nc < 8; nc++) {
                int key = nc * 8 + r;
                int off = key * KSTRIDE + kc * 16 + c2;
                u32 bh0 = *(const u32*)&Khi[off];
                u32 bh1 = *(const u32*)&Khi[off + 8];
                u32 bl0 = *(const u32*)&Klo[off];
                u32 bl1 = *(const u32*)&Klo[off + 8];
                mma16816(s[nc], qh[kc], bh0, bh1);
                mma16816(s[nc], qh[kc], bl0, bl1);
                mma16816(s[nc], ql[kc], bh0, bh1);
            }

        // ---- softmax (no max-sub; exact fp32 sums) + split P to bf16 ----
        u32 ph[4][4], pl[4][4];
        #pragma unroll
        for (int j = 0; j < 8; j++) {
            float p0 = __expf(s[j][0]);
            float p1 = __expf(s[j][1]);
            float p2 = __expf(s[j][2]);
            float p3 = __expf(s[j][3]);
            lsum0 += p0 + p1;
            lsum1 += p2 + p3;
            int kc2 = j >> 1, hl = (j & 1) * 1;
            bsplit2(p0, p1, ph[kc2][hl * 2 + 0], pl[kc2][hl * 2 + 0]);
            bsplit2(p2, p3, ph[kc2][hl * 2 + 1], pl[kc2][hl * 2 + 1]);
        }

        // ---- O += P V : 4 k-chunks x 4 d-chunks x 3 passes ----
        #pragma unroll
        for (int kc2 = 0; kc2 < 4; kc2++)
            #pragma unroll
            for (int nc2 = 0; nc2 < 4; nc2++) {
                int d = nc2 * 8 + r;
                int off = d * VSTRIDE + kc2 * 16 + c2;
                u32 vh0 = *(const u32*)&Vthi[off];
                u32 vh1 = *(const u32*)&Vthi[off + 8];
                u32 vl0 = *(const u32*)&Vtlo[off];
                u32 vl1 = *(const u32*)&Vtlo[off + 8];
                mma16816(o[nc2], ph[kc2], vh0, vh1);
                mma16816(o[nc2], ph[kc2], vl0, vl1);
                mma16816(o[nc2], pl[kc2], vh0, vh1);
            }
    }

    // ---- epilogue: normalize rows, write g_ao ----
    lsum0 += __shfl_xor_sync(0xffffffffu, lsum0, 1);
    lsum0 += __shfl_xor_sync(0xffffffffu, lsum0, 2);
    lsum1 += __shfl_xor_sync(0xffffffffu, lsum1, 1);
    lsum1 += __shfl_xor_sync(0xffffffffu, lsum1, 2);
    float inv0 = 1.0f / lsum0, inv1 = 1.0f / lsum1;

    int row0 = q0 + w * 16 + r;
    float* og0 = g_ao + ((size_t)(b * HW + row0)) * CDIM + h * DHEAD;
    float* og1 = og0 + 8 * CDIM;
    #pragma unroll
    for (int nc2 = 0; nc2 < 4; nc2++) {
        *(float2*)(og0 + nc2 * 8 + c2) = make_float2(o[nc2][0] * inv0, o[nc2][1] * inv0);
        *(float2*)(og1 + nc2 * 8 + c2) = make_float2(o[nc2][2] * inv1, o[nc2][3] * inv1);
    }
}

// ---------------------------------------------------------------------------
extern "C" void kernel_launch(void* const* d_in, const int* in_sizes, int n_in,
                              void* d_out, int out_size)
{
    const float* x  = (const float*)d_in[0];
    const float* wq = (const float*)d_in[1];
    const float* bq = (const float*)d_in[2];
    const float* wk = (const float*)d_in[3];
    const float* bk = (const float*)d_in[4];
    const float* wv = (const float*)d_in[5];
    const float* bv = (const float*)d_in[6];
    const float* wo = (const float*)d_in[7];
    const float* bo = (const float*)d_in[8];

    {   // 1) transpose + positional encoding
        dim3 blk(32, 8);
        dim3 grd(HW / 32, CDIM / 32, BATCH);
        k_transpose_pe<<<grd, blk>>>(x);
    }
    {   // 2) QKV projections on tensor cores
        dim3 grd(CDIM / 64, MROWS / 128, 3);
        k_proj_qkv<<<grd, 256>>>(wq, bq, wk, bk, wv, bv);
    }
    {   // 3) flash attention on tensor cores (mma.sync bf16 split)
        dim3 grd(HW / 128, BATCH * NHEAD);
        k_attn_mma<<<grd, 256>>>();
    }
    {   // 4) output projection on tensor cores + transpose to [b,c,h,w]
        dim3 grd(CDIM / 64, MROWS / 128);
        k_proj_out<<<grd, 256>>>(wo, bo, (float*)d_out);
    }
}

// round 8
// speedup vs baseline: 4.0727x; 1.2043x over previous
#include <cuda_runtime.h>
#include <cuda_bf16.h>
#include <math.h>
#include <stdint.h>

#define BATCH 4
#define CDIM  256
#define HW    2304          // n = 48*48
#define MROWS (BATCH*HW)    // 9216
#define NHEAD 8
#define DHEAD 32

typedef unsigned long long u64;
typedef unsigned int u32;
typedef unsigned short u16;

// Scratch (static device memory; no runtime allocation allowed)
__device__ float g_xs[MROWS*CDIM];
__device__ float g_ao[MROWS*CDIM];
// pre-split bf16 hi/lo Q (scaled), K, V
__device__ u16 g_qh[MROWS*CDIM];
__device__ u16 g_ql[MROWS*CDIM];
__device__ u16 g_kh[MROWS*CDIM];
__device__ u16 g_kl[MROWS*CDIM];
__device__ u16 g_vh[MROWS*CDIM];
__device__ u16 g_vl[MROWS*CDIM];

// ---------------------------------------------------------------------------
// helpers
// ---------------------------------------------------------------------------
__device__ __forceinline__ u32 bf2(float lo, float hi) {
    u32 r; asm("cvt.rn.bf16x2.f32 %0, %1, %2;" : "=r"(r) : "f"(hi), "f"(lo));
    return r;
}
__device__ __forceinline__ void bsplit2(float x0, float x1, u32& h, u32& l) {
    h = bf2(x0, x1);
    float h0 = __uint_as_float(h << 16);
    float h1 = __uint_as_float(h & 0xFFFF0000u);
    l = bf2(x0 - h0, x1 - h1);
}
__device__ __forceinline__ void mma16816(float d[4], const u32 a[4], u32 b0, u32 b1) {
    asm volatile("mma.sync.aligned.m16n8k16.row.col.f32.bf16.bf16.f32 "
        "{%0,%1,%2,%3}, {%4,%5,%6,%7}, {%8,%9}, {%0,%1,%2,%3};"
        : "+f"(d[0]), "+f"(d[1]), "+f"(d[2]), "+f"(d[3])
        : "r"(a[0]), "r"(a[1]), "r"(a[2]), "r"(a[3]), "r"(b0), "r"(b1));
}
__device__ __forceinline__ u32 smem_u32_(const void* p) {
    u32 a; asm("{ .reg .u64 t; cvta.to.shared.u64 t, %1; cvt.u32.u64 %0, t; }"
               : "=r"(a) : "l"(p)); return a;
}
__device__ __forceinline__ void cpa16(u32 dst, const void* src) {
    asm volatile("cp.async.cg.shared.global [%0], [%1], 16;"
                 :: "r"(dst), "l"(src) : "memory");
}
#define CP_COMMIT() asm volatile("cp.async.commit_group;" ::: "memory")
#define CP_WAIT0()  asm volatile("cp.async.wait_group 0;" ::: "memory")
__device__ __forceinline__ void ldmat4t(u32 r[4], u32 addr) {
    asm volatile("ldmatrix.sync.aligned.m8n8.x4.trans.shared.b16 {%0,%1,%2,%3}, [%4];"
        : "=r"(r[0]), "=r"(r[1]), "=r"(r[2]), "=r"(r[3]) : "r"(addr));
}

// ---------------------------------------------------------------------------
// Kernel 1: x [b,c,h,w] -> xs [b,n,c] transpose + positional encoding
// ---------------------------------------------------------------------------
__global__ void k_transpose_pe(const float* __restrict__ x)
{
    __shared__ float tile[32][33];
    int b  = blockIdx.z;
    int p0 = blockIdx.x * 32;
    int c0 = blockIdx.y * 32;
    int tx = threadIdx.x, ty = threadIdx.y;

    #pragma unroll
    for (int i = 0; i < 4; i++) {
        int cc = c0 + ty + i * 8;
        tile[ty + i * 8][tx] = x[((size_t)(b * CDIM + cc)) * HW + p0 + tx];
    }
    __syncthreads();
    #pragma unroll
    for (int i = 0; i < 4; i++) {
        int p  = p0 + ty + i * 8;
        int cc = c0 + tx;
        float v = tile[tx][ty + i * 8];
        float pe = 0.0f;
        if (p != 0) {
            float ang = (float)p * powf(10000.0f, -2.0f * (float)cc / 256.0f);
            pe = (cc & 1) ? cosf(ang) : sinf(ang);
        }
        g_xs[((size_t)(b * HW + p)) * CDIM + cc] = v + pe;
    }
}

// ---------------------------------------------------------------------------
// QKV projection: out = split_bf16((A @ W^T + bias) * qs) -> (outh, outl)
// Block = 256 thr = 8 warps; tile 128m x 64n; mma.sync bf16 3-pass.
// ---------------------------------------------------------------------------
#define PJSTRIDE 72

__global__ void __launch_bounds__(256) k_proj_qkv(
    const float* __restrict__ wq, const float* __restrict__ bq,
    const float* __restrict__ wk, const float* __restrict__ bk,
    const float* __restrict__ wv, const float* __restrict__ bv)
{
    const float* W; const float* bias; u16* outh; u16* outl; float qs;
    if (blockIdx.z == 0)      { W = wq; bias = bq; outh = g_qh; outl = g_ql; qs = 0.17677669529663687f; }
    else if (blockIdx.z == 1) { W = wk; bias = bk; outh = g_kh; outl = g_kl; qs = 1.0f; }
    else                      { W = wv; bias = bv; outh = g_vh; outl = g_vl; qs = 1.0f; }
    const float* A = g_xs;

    __shared__ u16 Whi[64 * PJSTRIDE];
    __shared__ u16 Wlo[64 * PJSTRIDE];

    int tid = threadIdx.x;
    int w = tid >> 5, lane = tid & 31;
    int r = lane >> 2, c2 = (lane & 3) * 2;
    int m0 = blockIdx.y * 128;
    int n0 = blockIdx.x * 64;

    float o[8][4];
    #pragma unroll
    for (int i = 0; i < 8; i++)
        #pragma unroll
        for (int j = 0; j < 4; j++) o[i][j] = 0.0f;

    const float* arow0 = A + (size_t)(m0 + w * 16 + r) * CDIM;
    const float* arow1 = arow0 + 8 * CDIM;

    for (int k0 = 0; k0 < CDIM; k0 += 64) {
        __syncthreads();
        {
            int row = tid >> 2, col0 = (tid & 3) * 16;
            const float* src = W + (size_t)(n0 + row) * CDIM + k0 + col0;
            float4 f0 = *(const float4*)(src);
            float4 f1 = *(const float4*)(src + 4);
            float4 f2 = *(const float4*)(src + 8);
            float4 f3 = *(const float4*)(src + 12);
            u32 hh[8], ll[8];
            bsplit2(f0.x, f0.y, hh[0], ll[0]);
            bsplit2(f0.z, f0.w, hh[1], ll[1]);
            bsplit2(f1.x, f1.y, hh[2], ll[2]);
            bsplit2(f1.z, f1.w, hh[3], ll[3]);
            bsplit2(f2.x, f2.y, hh[4], ll[4]);
            bsplit2(f2.z, f2.w, hh[5], ll[5]);
            bsplit2(f3.x, f3.y, hh[6], ll[6]);
            bsplit2(f3.z, f3.w, hh[7], ll[7]);
            int ws = row * PJSTRIDE + col0;
            *(uint4*)&Whi[ws]     = make_uint4(hh[0], hh[1], hh[2], hh[3]);
            *(uint4*)&Whi[ws + 8] = make_uint4(hh[4], hh[5], hh[6], hh[7]);
            *(uint4*)&Wlo[ws]     = make_uint4(ll[0], ll[1], ll[2], ll[3]);
            *(uint4*)&Wlo[ws + 8] = make_uint4(ll[4], ll[5], ll[6], ll[7]);
        }
        __syncthreads();

        #pragma unroll
        for (int kc = 0; kc < 4; kc++) {
            u32 ah[4], al[4];
            int cb = k0 + kc * 16 + c2;
            float2 f;
            f = *(const float2*)(arow0 + cb);     bsplit2(f.x, f.y, ah[0], al[0]);
            f = *(const float2*)(arow1 + cb);     bsplit2(f.x, f.y, ah[1], al[1]);
            f = *(const float2*)(arow0 + cb + 8); bsplit2(f.x, f.y, ah[2], al[2]);
            f = *(const float2*)(arow1 + cb + 8); bsplit2(f.x, f.y, ah[3], al[3]);
            #pragma unroll
            for (int nc = 0; nc < 8; nc++) {
                int off = (nc * 8 + r) * PJSTRIDE + kc * 16 + c2;
                u32 bh0 = *(const u32*)&Whi[off];
                u32 bh1 = *(const u32*)&Whi[off + 8];
                u32 bl0 = *(const u32*)&Wlo[off];
                u32 bl1 = *(const u32*)&Wlo[off + 8];
                mma16816(o[nc], ah, bh0, bh1);
                mma16816(o[nc], ah, bl0, bl1);
                mma16816(o[nc], al, bh0, bh1);
            }
        }
    }

    // epilogue: bias (+scale), split, store u32 pairs
    size_t r0off = (size_t)(m0 + w * 16 + r) * CDIM + n0;
    size_t r1off = r0off + 8 * CDIM;
    #pragma unroll
    for (int nc = 0; nc < 8; nc++) {
        float2 bi = *(const float2*)(bias + n0 + nc * 8 + c2);
        u32 hh, ll;
        bsplit2((o[nc][0] + bi.x) * qs, (o[nc][1] + bi.y) * qs, hh, ll);
        *(u32*)&outh[r0off + nc * 8 + c2] = hh;
        *(u32*)&outl[r0off + nc * 8 + c2] = ll;
        bsplit2((o[nc][2] + bi.x) * qs, (o[nc][3] + bi.y) * qs, hh, ll);
        *(u32*)&outh[r1off + nc * 8 + c2] = hh;
        *(u32*)&outl[r1off + nc * 8 + c2] = ll;
    }
}

// ---------------------------------------------------------------------------
// Output projection: fp32 A from g_ao, transposed store.
// ---------------------------------------------------------------------------
__global__ void __launch_bounds__(256) k_proj_out(
    const float* __restrict__ wo, const float* __restrict__ bo,
    float* __restrict__ out)
{
    const float* A = g_ao;
    __shared__ u16 Whi[64 * PJSTRIDE];
    __shared__ u16 Wlo[64 * PJSTRIDE];

    int tid = threadIdx.x;
    int w = tid >> 5, lane = tid & 31;
    int r = lane >> 2, c2 = (lane & 3) * 2;
    int m0 = blockIdx.y * 128;
    int n0 = blockIdx.x * 64;

    float o[8][4];
    #pragma unroll
    for (int i = 0; i < 8; i++)
        #pragma unroll
        for (int j = 0; j < 4; j++) o[i][j] = 0.0f;

    const float* arow0 = A + (size_t)(m0 + w * 16 + r) * CDIM;
    const float* arow1 = arow0 + 8 * CDIM;

    for (int k0 = 0; k0 < CDIM; k0 += 64) {
        __syncthreads();
        {
            int row = tid >> 2, col0 = (tid & 3) * 16;
            const float* src = wo + (size_t)(n0 + row) * CDIM + k0 + col0;
            float4 f0 = *(const float4*)(src);
            float4 f1 = *(const float4*)(src + 4);
            float4 f2 = *(const float4*)(src + 8);
            float4 f3 = *(const float4*)(src + 12);
            u32 hh[8], ll[8];
            bsplit2(f0.x, f0.y, hh[0], ll[0]);
            bsplit2(f0.z, f0.w, hh[1], ll[1]);
            bsplit2(f1.x, f1.y, hh[2], ll[2]);
            bsplit2(f1.z, f1.w, hh[3], ll[3]);
            bsplit2(f2.x, f2.y, hh[4], ll[4]);
            bsplit2(f2.z, f2.w, hh[5], ll[5]);
            bsplit2(f3.x, f3.y, hh[6], ll[6]);
            bsplit2(f3.z, f3.w, hh[7], ll[7]);
            int ws = row * PJSTRIDE + col0;
            *(uint4*)&Whi[ws]     = make_uint4(hh[0], hh[1], hh[2], hh[3]);
            *(uint4*)&Whi[ws + 8] = make_uint4(hh[4], hh[5], hh[6], hh[7]);
            *(uint4*)&Wlo[ws]     = make_uint4(ll[0], ll[1], ll[2], ll[3]);
            *(uint4*)&Wlo[ws + 8] = make_uint4(ll[4], ll[5], ll[6], ll[7]);
        }
        __syncthreads();

        #pragma unroll
        for (int kc = 0; kc < 4; kc++) {
            u32 ah[4], al[4];
            int cb = k0 + kc * 16 + c2;
            float2 f;
            f = *(const float2*)(arow0 + cb);     bsplit2(f.x, f.y, ah[0], al[0]);
            f = *(const float2*)(arow1 + cb);     bsplit2(f.x, f.y, ah[1], al[1]);
            f = *(const float2*)(arow0 + cb + 8); bsplit2(f.x, f.y, ah[2], al[2]);
            f = *(const float2*)(arow1 + cb + 8); bsplit2(f.x, f.y, ah[3], al[3]);
            #pragma unroll
            for (int nc = 0; nc < 8; nc++) {
                int off = (nc * 8 + r) * PJSTRIDE + kc * 16 + c2;
                u32 bh0 = *(const u32*)&Whi[off];
                u32 bh1 = *(const u32*)&Whi[off + 8];
                u32 bl0 = *(const u32*)&Wlo[off];
                u32 bl1 = *(const u32*)&Wlo[off + 8];
                mma16816(o[nc], ah, bh0, bh1);
                mma16816(o[nc], ah, bl0, bl1);
                mma16816(o[nc], al, bh0, bh1);
            }
        }
    }

    int mr0 = m0 + w * 16 + r;
    int mr1 = mr0 + 8;
    int bb0 = mr0 / HW, pp0 = mr0 % HW;
    int bb1 = mr1 / HW, pp1 = mr1 % HW;
    #pragma unroll
    for (int nc = 0; nc < 8; nc++) {
        float2 bi = *(const float2*)(bo + n0 + nc * 8 + c2);
        int nn = n0 + nc * 8 + c2;
        out[((size_t)(bb0 * CDIM + nn)) * HW + pp0]     = o[nc][0] + bi.x;
        out[((size_t)(bb0 * CDIM + nn + 1)) * HW + pp0] = o[nc][1] + bi.y;
        out[((size_t)(bb1 * CDIM + nn)) * HW + pp1]     = o[nc][2] + bi.x;
        out[((size_t)(bb1 * CDIM + nn + 1)) * HW + pp1] = o[nc][3] + bi.y;
    }
}

// ---------------------------------------------------------------------------
// Kernel 3: flash attention, pre-split inputs + cp.async double buffer +
// ldmatrix.trans V. Block = 256 thr = 8 warps (warp = 16 queries).
// smem: [buf][Kh,Kl,Vh,Vl][64 rows x 40 halves]; array = 5120 B, buf = 20480 B
// ---------------------------------------------------------------------------
#define KST 40
#define NT  (HW / 64)

__global__ void __launch_bounds__(256, 2) k_attn_mma()
{
    __shared__ u16 sbuf[2][4][64 * KST];

    int tid = threadIdx.x;
    int w = tid >> 5, lane = tid & 31;
    int r = lane >> 2, c2 = (lane & 3) * 2;
    int b = blockIdx.y >> 3, h = blockIdx.y & 7;
    int q0 = blockIdx.x * 128;
    u32 sb = smem_u32_(&sbuf[0][0][0]);

    // staging coords (per thread: one 16B chunk per array)
    int srow = tid >> 2, sch = (tid & 3) * 8;
    size_t gbase = ((size_t)(b * HW) + srow) * CDIM + h * DHEAD + sch;
    u32 sdst = sb + (u32)(srow * KST + sch) * 2;

    // ---- prologue: stage tile 0 ----
    {
        size_t g0 = gbase;  // kt = 0
        cpa16(sdst,              g_kh + g0);
        cpa16(sdst +  1 * 5120,  g_kl + g0);
        cpa16(sdst +  2 * 5120,  g_vh + g0);
        cpa16(sdst +  3 * 5120,  g_vl + g0);
        CP_COMMIT();
    }

    // ---- Q fragments (pre-scaled, pre-split) straight from gmem ----
    u32 qh[2][4], ql[2][4];
    {
        const u16* qhg = g_qh + ((size_t)(b * HW + q0 + w * 16)) * CDIM + h * DHEAD;
        const u16* qlg = g_ql + ((size_t)(b * HW + q0 + w * 16)) * CDIM + h * DHEAD;
        #pragma unroll
        for (int kc = 0; kc < 2; kc++)
            #pragma unroll
            for (int i = 0; i < 4; i++) {
                int rr = r + (i & 1) * 8;
                int cc = kc * 16 + c2 + (i >> 1) * 8;
                qh[kc][i] = *(const u32*)(qhg + (size_t)rr * CDIM + cc);
                ql[kc][i] = *(const u32*)(qlg + (size_t)rr * CDIM + cc);
            }
    }

    float o[4][4];
    #pragma unroll
    for (int i = 0; i < 4; i++)
        #pragma unroll
        for (int j = 0; j < 4; j++) o[i][j] = 0.0f;
    float lsum0 = 0.0f, lsum1 = 0.0f;

    // ldmatrix lane addressing for V (.x4.trans on 16key x 16dim tiles)
    int vkey = lane & 15;
    int vdim = (lane >> 4) << 3;

    for (int kt = 0; kt < NT; kt++) {
        int buf = kt & 1;
        CP_WAIT0();
        __syncthreads();
        if (kt + 1 < NT) {
            size_t g1 = gbase + (size_t)(kt + 1) * 64 * CDIM;
            u32 d1 = sdst + (u32)((kt + 1) & 1) * 20480;
            cpa16(d1,             g_kh + g1);
            cpa16(d1 + 1 * 5120,  g_kl + g1);
            cpa16(d1 + 2 * 5120,  g_vh + g1);
            cpa16(d1 + 3 * 5120,  g_vl + g1);
            CP_COMMIT();
        }

        const u16* Kh = sbuf[buf][0];
        const u16* Kl = sbuf[buf][1];

        // ---- S = Q K^T ----
        float s[8][4];
        #pragma unroll
        for (int i = 0; i < 8; i++)
            #pragma unroll
            for (int j = 0; j < 4; j++) s[i][j] = 0.0f;

        #pragma unroll
        for (int kc = 0; kc < 2; kc++)
            #pragma unroll
            for (int nc = 0; nc < 8; nc++) {
                int off = (nc * 8 + r) * KST + kc * 16 + c2;
                u32 bh0 = *(const u32*)&Kh[off];
                u32 bh1 = *(const u32*)&Kh[off + 8];
                u32 bl0 = *(const u32*)&Kl[off];
                u32 bl1 = *(const u32*)&Kl[off + 8];
                mma16816(s[nc], qh[kc], bh0, bh1);
                mma16816(s[nc], qh[kc], bl0, bl1);
                mma16816(s[nc], ql[kc], bh0, bh1);
            }

        // ---- softmax (no max-sub; exact fp32 sums) + split P to bf16 ----
        u32 ph[4][4], pl[4][4];
        #pragma unroll
        for (int j = 0; j < 8; j++) {
            float p0 = __expf(s[j][0]);
            float p1 = __expf(s[j][1]);
            float p2 = __expf(s[j][2]);
            float p3 = __expf(s[j][3]);
            lsum0 += p0 + p1;
            lsum1 += p2 + p3;
            int kc2 = j >> 1, hl = j & 1;
            bsplit2(p0, p1, ph[kc2][hl * 2 + 0], pl[kc2][hl * 2 + 0]);
            bsplit2(p2, p3, ph[kc2][hl * 2 + 1], pl[kc2][hl * 2 + 1]);
        }

        // ---- O += P V  (V fragments via ldmatrix.x4.trans) ----
        // FIX (R7 bug): array stride is 5120 B, buffer stride 20480 B.
        u32 vhb = sb + (u32)buf * 20480 + 2 * 5120;
        u32 vlb = sb + (u32)buf * 20480 + 3 * 5120;
        #pragma unroll
        for (int kc2 = 0; kc2 < 4; kc2++) {
            u32 a0 = (u32)(((kc2 * 16 + vkey) * KST) + vdim) * 2;
            u32 a1 = a0 + 32;   // +16 halves (dims 16..31)
            u32 vh0[4], vh1[4], vl0[4], vl1[4];
            ldmat4t(vh0, vhb + a0);
            ldmat4t(vh1, vhb + a1);
            ldmat4t(vl0, vlb + a0);
            ldmat4t(vl1, vlb + a1);
            mma16816(o[0], ph[kc2], vh0[0], vh0[1]);
            mma16816(o[0], ph[kc2], vl0[0], vl0[1]);
            mma16816(o[0], pl[kc2], vh0[0], vh0[1]);
            mma16816(o[1], ph[kc2], vh0[2], vh0[3]);
            mma16816(o[1], ph[kc2], vl0[2], vl0[3]);
            mma16816(o[1], pl[kc2], vh0[2], vh0[3]);
            mma16816(o[2], ph[kc2], vh1[0], vh1[1]);
            mma16816(o[2], ph[kc2], vl1[0], vl1[1]);
            mma16816(o[2], pl[kc2], vh1[0], vh1[1]);
            mma16816(o[3], ph[kc2], vh1[2], vh1[3]);
            mma16816(o[3], ph[kc2], vl1[2], vl1[3]);
            mma16816(o[3], pl[kc2], vh1[2], vh1[3]);
        }
    }

    // ---- epilogue: normalize rows, write g_ao ----
    lsum0 += __shfl_xor_sync(0xffffffffu, lsum0, 1);
    lsum0 += __shfl_xor_sync(0xffffffffu, lsum0, 2);
    lsum1 += __shfl_xor_sync(0xffffffffu, lsum1, 1);
    lsum1 += __shfl_xor_sync(0xffffffffu, lsum1, 2);
    float inv0 = 1.0f / lsum0, inv1 = 1.0f / lsum1;

    int row0 = q0 + w * 16 + r;
    float* og0 = g_ao + ((size_t)(b * HW + row0)) * CDIM + h * DHEAD;
    float* og1 = og0 + 8 * CDIM;
    #pragma unroll
    for (int nc2 = 0; nc2 < 4; nc2++) {
        *(float2*)(og0 + nc2 * 8 + c2) = make_float2(o[nc2][0] * inv0, o[nc2][1] * inv0);
        *(float2*)(og1 + nc2 * 8 + c2) = make_float2(o[nc2][2] * inv1, o[nc2][3] * inv1);
    }
}

// ---------------------------------------------------------------------------
extern "C" void kernel_launch(void* const* d_in, const int* in_sizes, int n_in,
                              void* d_out, int out_size)
{
    const float* x  = (const float*)d_in[0];
    const float* wq = (const float*)d_in[1];
    const float* bq = (const float*)d_in[2];
    const float* wk = (const float*)d_in[3];
    const float* bk = (const float*)d_in[4];
    const float* wv = (const float*)d_in[5];
    const float* bv = (const float*)d_in[6];
    const float* wo = (const float*)d_in[7];
    const float* bo = (const float*)d_in[8];

    {   // 1) transpose + positional encoding
        dim3 blk(32, 8);
        dim3 grd(HW / 32, CDIM / 32, BATCH);
        k_transpose_pe<<<grd, blk>>>(x);
    }
    {   // 2) QKV projections -> pre-split bf16 hi/lo
        dim3 grd(CDIM / 64, MROWS / 128, 3);
        k_proj_qkv<<<grd, 256>>>(wq, bq, wk, bk, wv, bv);
    }
    {   // 3) flash attention (cp.async pipeline + ldmatrix.trans V)
        dim3 grd(HW / 128, BATCH * NHEAD);
        k_attn_mma<<<grd, 256>>>();
    }
    {   // 4) output projection + transpose to [b,c,h,w]
        dim3 grd(CDIM / 64, MROWS / 128);
        k_proj_out<<<grd, 256>>>(wo, bo, (float*)d_out);
    }
}

// round 9
// speedup vs baseline: 4.1310x; 1.0143x over previous
#include <cuda_runtime.h>
#include <cuda_bf16.h>
#include <math.h>
#include <stdint.h>

#define BATCH 4
#define CDIM  256
#define HW    2304          // n = 48*48
#define MROWS (BATCH*HW)    // 9216
#define NHEAD 8
#define DHEAD 32

typedef unsigned long long u64;
typedef unsigned int u32;
typedef unsigned short u16;

// Scratch (static device memory; no runtime allocation allowed).
// Everything between kernels is pre-split bf16 hi/lo.
__device__ __align__(16) u16 g_xsh[MROWS*CDIM];
__device__ __align__(16) u16 g_xsl[MROWS*CDIM];
__device__ __align__(16) u16 g_qh[MROWS*CDIM];
__device__ __align__(16) u16 g_ql[MROWS*CDIM];
__device__ __align__(16) u16 g_kh[MROWS*CDIM];
__device__ __align__(16) u16 g_kl[MROWS*CDIM];
__device__ __align__(16) u16 g_vh[MROWS*CDIM];
__device__ __align__(16) u16 g_vl[MROWS*CDIM];
__device__ __align__(16) u16 g_aoh[MROWS*CDIM];
__device__ __align__(16) u16 g_aol[MROWS*CDIM];
__device__ __align__(16) u16 g_wh[4*CDIM*CDIM];
__device__ __align__(16) u16 g_wl[4*CDIM*CDIM];

// ---------------------------------------------------------------------------
// helpers
// ---------------------------------------------------------------------------
__device__ __forceinline__ u32 bf2(float lo, float hi) {
    u32 r; asm("cvt.rn.bf16x2.f32 %0, %1, %2;" : "=r"(r) : "f"(hi), "f"(lo));
    return r;
}
__device__ __forceinline__ void bsplit2(float x0, float x1, u32& h, u32& l) {
    h = bf2(x0, x1);
    float h0 = __uint_as_float(h << 16);
    float h1 = __uint_as_float(h & 0xFFFF0000u);
    l = bf2(x0 - h0, x1 - h1);
}
__device__ __forceinline__ void bsplit1(float x, u16& h, u16& l) {
    __nv_bfloat16 hb = __float2bfloat16_rn(x);
    float hf = __bfloat162float(hb);
    __nv_bfloat16 lb = __float2bfloat16_rn(x - hf);
    h = *(u16*)&hb; l = *(u16*)&lb;
}
__device__ __forceinline__ void mma16816(float d[4], const u32 a[4], u32 b0, u32 b1) {
    asm volatile("mma.sync.aligned.m16n8k16.row.col.f32.bf16.bf16.f32 "
        "{%0,%1,%2,%3}, {%4,%5,%6,%7}, {%8,%9}, {%0,%1,%2,%3};"
        : "+f"(d[0]), "+f"(d[1]), "+f"(d[2]), "+f"(d[3])
        : "r"(a[0]), "r"(a[1]), "r"(a[2]), "r"(a[3]), "r"(b0), "r"(b1));
}
__device__ __forceinline__ u32 smem_u32_(const void* p) {
    u32 a; asm("{ .reg .u64 t; cvta.to.shared.u64 t, %1; cvt.u32.u64 %0, t; }"
               : "=r"(a) : "l"(p)); return a;
}
__device__ __forceinline__ void cpa16(u32 dst, const void* src) {
    asm volatile("cp.async.cg.shared.global [%0], [%1], 16;"
                 :: "r"(dst), "l"(src) : "memory");
}
#define CP_COMMIT() asm volatile("cp.async.commit_group;" ::: "memory")
#define CP_WAIT0()  asm volatile("cp.async.wait_group 0;" ::: "memory")
__device__ __forceinline__ void ldmat4(u32 r[4], u32 addr) {
    asm volatile("ldmatrix.sync.aligned.m8n8.x4.shared.b16 {%0,%1,%2,%3}, [%4];"
        : "=r"(r[0]), "=r"(r[1]), "=r"(r[2]), "=r"(r[3]) : "r"(addr));
}
__device__ __forceinline__ void ldmat4t(u32 r[4], u32 addr) {
    asm volatile("ldmatrix.sync.aligned.m8n8.x4.trans.shared.b16 {%0,%1,%2,%3}, [%4];"
        : "=r"(r[0]), "=r"(r[1]), "=r"(r[2]), "=r"(r[3]) : "r"(addr));
}

// ---------------------------------------------------------------------------
// Kernel 0: split weight matrices once (4 x 256x256)
// ---------------------------------------------------------------------------
__global__ void k_split_w(const float* __restrict__ wq, const float* __restrict__ wk,
                          const float* __restrict__ wv, const float* __restrict__ wo)
{
    int idx = blockIdx.x * 256 + threadIdx.x;   // 0..65535
    const float* ws[4] = { wq, wk, wv, wo };
    #pragma unroll
    for (int m = 0; m < 4; m++) {
        float v = ws[m][idx];
        u16 h, l; bsplit1(v, h, l);
        g_wh[m * 65536 + idx] = h;
        g_wl[m * 65536 + idx] = l;
    }
}

// ---------------------------------------------------------------------------
// Kernel 1: x [b,c,h,w] -> xs split bf16 [b,n,c] transpose + positional enc
// ---------------------------------------------------------------------------
__global__ void k_transpose_pe(const float* __restrict__ x)
{
    __shared__ float tile[32][33];
    int b  = blockIdx.z;
    int p0 = blockIdx.x * 32;
    int c0 = blockIdx.y * 32;
    int tx = threadIdx.x, ty = threadIdx.y;

    #pragma unroll
    for (int i = 0; i < 4; i++) {
        int cc = c0 + ty + i * 8;
        tile[ty + i * 8][tx] = x[((size_t)(b * CDIM + cc)) * HW + p0 + tx];
    }
    __syncthreads();
    #pragma unroll
    for (int i = 0; i < 4; i++) {
        int p  = p0 + ty + i * 8;
        int cc = c0 + tx;
        float v = tile[tx][ty + i * 8];
        float pe = 0.0f;
        if (p != 0) {
            float ang = (float)p * powf(10000.0f, -2.0f * (float)cc / 256.0f);
            pe = (cc & 1) ? cosf(ang) : sinf(ang);
        }
        float val = v + pe;
        u16 h, l; bsplit1(val, h, l);
        size_t idx = ((size_t)(b * HW + p)) * CDIM + cc;
        g_xsh[idx] = h;
        g_xsl[idx] = l;
    }
}

// ---------------------------------------------------------------------------
// Projection GEMM (pure MMA): out = A @ W^T + bias, all operands pre-split.
// Block = 256 thr = 8 warps; tile 128m x 64n; K chunks of 64 double-buffered
// via cp.async (A hi/lo + W hi/lo). A-frags via ldmatrix, W via LDS.
// ---------------------------------------------------------------------------
#define PST   72              // u16 per smem row (64 + 8 pad)
#define SA_H  0               // u16 offsets within one stage
#define SA_L  9216
#define SW_H  18432
#define SW_L  23040
#define PSTAGE 27648          // u16 per stage (55296 B); x2 stages = 110592 B

__device__ __forceinline__ void proj_stage(
    u32 sbase, int buf, int m0, int n0, int k0, int tid,
    const u16* __restrict__ Agh, const u16* __restrict__ Agl,
    const u16* __restrict__ Wgh, const u16* __restrict__ Wgl)
{
    u32 b0 = sbase + (u32)buf * (PSTAGE * 2);
    #pragma unroll
    for (int it = 0; it < 4; it++) {
        int idx = tid + it * 256;            // 0..1023
        int row = idx >> 3, c8 = (idx & 7) * 8;
        size_t gs = (size_t)(m0 + row) * CDIM + k0 + c8;
        u32 doff = (u32)(row * PST + c8) * 2;
        cpa16(b0 + SA_H * 2 + doff, Agh + gs);
        cpa16(b0 + SA_L * 2 + doff, Agl + gs);
    }
    #pragma unroll
    for (int it = 0; it < 2; it++) {
        int idx = tid + it * 256;            // 0..511
        int row = idx >> 3, c8 = (idx & 7) * 8;
        size_t gs = (size_t)(n0 + row) * CDIM + k0 + c8;
        u32 doff = (u32)(row * PST + c8) * 2;
        cpa16(b0 + SW_H * 2 + doff, Wgh + gs);
        cpa16(b0 + SW_L * 2 + doff, Wgl + gs);
    }
}

template<bool TRANS_OUT>
__device__ __forceinline__ void proj_body(
    const u16* __restrict__ Agh, const u16* __restrict__ Agl,
    int widx, const float* __restrict__ bias,
    u16* __restrict__ outh, u16* __restrict__ outl,
    float* __restrict__ outf, float qs)
{
    extern __shared__ u16 smp[];
    int tid = threadIdx.x;
    int w = tid >> 5, lane = tid & 31;
    int r = lane >> 2, c2 = (lane & 3) * 2;
    int m0 = blockIdx.y * 128, n0 = blockIdx.x * 64;
    u32 sbase = smem_u32_(smp);
    const u16* Wgh = g_wh + widx * 65536;
    const u16* Wgl = g_wl + widx * 65536;

    float o[8][4];
    #pragma unroll
    for (int i = 0; i < 8; i++)
        #pragma unroll
        for (int j = 0; j < 4; j++) o[i][j] = 0.0f;

    proj_stage(sbase, 0, m0, n0, 0, tid, Agh, Agl, Wgh, Wgl);
    CP_COMMIT();

    u32 arow = (u32)(w * 16 + (lane & 15));
    u32 acol = (u32)((lane >> 4) << 3);

    for (int c = 0; c < 4; c++) {
        CP_WAIT0();
        __syncthreads();
        if (c < 3) {
            proj_stage(sbase, (c + 1) & 1, m0, n0, (c + 1) * 64, tid, Agh, Agl, Wgh, Wgl);
            CP_COMMIT();
        }

        int sb = (c & 1) * PSTAGE;
        const u16* sWh = smp + sb + SW_H;
        const u16* sWl = smp + sb + SW_L;
        u32 abase = sbase + (u32)sb * 2 + (arow * PST + acol) * 2;

        #pragma unroll
        for (int kc = 0; kc < 4; kc++) {
            u32 ah[4], al[4];
            u32 aoff = abase + (u32)(kc * 16) * 2;
            ldmat4(ah, aoff + SA_H * 2);
            ldmat4(al, aoff + SA_L * 2);
            #pragma unroll
            for (int nc = 0; nc < 8; nc++) {
                int off = (nc * 8 + r) * PST + kc * 16 + c2;
                u32 bh0 = *(const u32*)&sWh[off];
                u32 bh1 = *(const u32*)&sWh[off + 8];
                u32 bl0 = *(const u32*)&sWl[off];
                u32 bl1 = *(const u32*)&sWl[off + 8];
                mma16816(o[nc], ah, bh0, bh1);
                mma16816(o[nc], ah, bl0, bl1);
                mma16816(o[nc], al, bh0, bh1);
            }
        }
    }

    // ---- epilogue ----
    int mr0 = m0 + w * 16 + r;
    int mr1 = mr0 + 8;
    if (!TRANS_OUT) {
        size_t r0off = (size_t)mr0 * CDIM + n0;
        size_t r1off = (size_t)mr1 * CDIM + n0;
        #pragma unroll
        for (int nc = 0; nc < 8; nc++) {
            float2 bi = *(const float2*)(bias + n0 + nc * 8 + c2);
            u32 hh, ll;
            bsplit2((o[nc][0] + bi.x) * qs, (o[nc][1] + bi.y) * qs, hh, ll);
            *(u32*)&outh[r0off + nc * 8 + c2] = hh;
            *(u32*)&outl[r0off + nc * 8 + c2] = ll;
            bsplit2((o[nc][2] + bi.x) * qs, (o[nc][3] + bi.y) * qs, hh, ll);
            *(u32*)&outh[r1off + nc * 8 + c2] = hh;
            *(u32*)&outl[r1off + nc * 8 + c2] = ll;
        }
    } else {
        int bb0 = mr0 / HW, pp0 = mr0 % HW;
        int bb1 = mr1 / HW, pp1 = mr1 % HW;
        #pragma unroll
        for (int nc = 0; nc < 8; nc++) {
            float2 bi = *(const float2*)(bias + n0 + nc * 8 + c2);
            int nn = n0 + nc * 8 + c2;
            outf[((size_t)(bb0 * CDIM + nn)) * HW + pp0]     = o[nc][0] + bi.x;
            outf[((size_t)(bb0 * CDIM + nn + 1)) * HW + pp0] = o[nc][1] + bi.y;
            outf[((size_t)(bb1 * CDIM + nn)) * HW + pp1]     = o[nc][2] + bi.x;
            outf[((size_t)(bb1 * CDIM + nn + 1)) * HW + pp1] = o[nc][3] + bi.y;
        }
    }
}

__global__ void __launch_bounds__(256) k_proj_qkv(
    const float* __restrict__ bq, const float* __restrict__ bk,
    const float* __restrict__ bv)
{
    const float* bias; u16* outh; u16* outl; float qs;
    if (blockIdx.z == 0)      { bias = bq; outh = g_qh; outl = g_ql; qs = 0.17677669529663687f; }
    else if (blockIdx.z == 1) { bias = bk; outh = g_kh; outl = g_kl; qs = 1.0f; }
    else                      { bias = bv; outh = g_vh; outl = g_vl; qs = 1.0f; }
    proj_body<false>(g_xsh, g_xsl, blockIdx.z, bias, outh, outl, nullptr, qs);
}

__global__ void __launch_bounds__(256) k_proj_out(
    const float* __restrict__ bo, float* __restrict__ out)
{
    proj_body<true>(g_aoh, g_aol, 3, bo, nullptr, nullptr, out, 1.0f);
}

// ---------------------------------------------------------------------------
// Kernel 3: flash attention (unchanged R8 core; epilogue writes split bf16).
// smem: [buf][Kh,Kl,Vh,Vl][64 rows x 40 halves]; array = 5120 B, buf = 20480 B
// ---------------------------------------------------------------------------
#define KST 40
#define NT  (HW / 64)

__global__ void __launch_bounds__(256, 2) k_attn_mma()
{
    __shared__ u16 sbuf[2][4][64 * KST];

    int tid = threadIdx.x;
    int w = tid >> 5, lane = tid & 31;
    int r = lane >> 2, c2 = (lane & 3) * 2;
    int b = blockIdx.y >> 3, h = blockIdx.y & 7;
    int q0 = blockIdx.x * 128;
    u32 sb = smem_u32_(&sbuf[0][0][0]);

    int srow = tid >> 2, sch = (tid & 3) * 8;
    size_t gbase = ((size_t)(b * HW) + srow) * CDIM + h * DHEAD + sch;
    u32 sdst = sb + (u32)(srow * KST + sch) * 2;

    {   // prologue: stage tile 0
        size_t g0 = gbase;
        cpa16(sdst,              g_kh + g0);
        cpa16(sdst +  1 * 5120,  g_kl + g0);
        cpa16(sdst +  2 * 5120,  g_vh + g0);
        cpa16(sdst +  3 * 5120,  g_vl + g0);
        CP_COMMIT();
    }

    u32 qh[2][4], ql[2][4];
    {
        const u16* qhg = g_qh + ((size_t)(b * HW + q0 + w * 16)) * CDIM + h * DHEAD;
        const u16* qlg = g_ql + ((size_t)(b * HW + q0 + w * 16)) * CDIM + h * DHEAD;
        #pragma unroll
        for (int kc = 0; kc < 2; kc++)
            #pragma unroll
            for (int i = 0; i < 4; i++) {
                int rr = r + (i & 1) * 8;
                int cc = kc * 16 + c2 + (i >> 1) * 8;
                qh[kc][i] = *(const u32*)(qhg + (size_t)rr * CDIM + cc);
                ql[kc][i] = *(const u32*)(qlg + (size_t)rr * CDIM + cc);
            }
    }

    float o[4][4];
    #pragma unroll
    for (int i = 0; i < 4; i++)
        #pragma unroll
        for (int j = 0; j < 4; j++) o[i][j] = 0.0f;
    float lsum0 = 0.0f, lsum1 = 0.0f;

    int vkey = lane & 15;
    int vdim = (lane >> 4) << 3;

    for (int kt = 0; kt < NT; kt++) {
        int buf = kt & 1;
        CP_WAIT0();
        __syncthreads();
        if (kt + 1 < NT) {
            size_t g1 = gbase + (size_t)(kt + 1) * 64 * CDIM;
            u32 d1 = sdst + (u32)((kt + 1) & 1) * 20480;
            cpa16(d1,             g_kh + g1);
            cpa16(d1 + 1 * 5120,  g_kl + g1);
            cpa16(d1 + 2 * 5120,  g_vh + g1);
            cpa16(d1 + 3 * 5120,  g_vl + g1);
            CP_COMMIT();
        }

        const u16* Kh = sbuf[buf][0];
        const u16* Kl = sbuf[buf][1];

        float s[8][4];
        #pragma unroll
        for (int i = 0; i < 8; i++)
            #pragma unroll
            for (int j = 0; j < 4; j++) s[i][j] = 0.0f;

        #pragma unroll
        for (int kc = 0; kc < 2; kc++)
            #pragma unroll
            for (int nc = 0; nc < 8; nc++) {
                int off = (nc * 8 + r) * KST + kc * 16 + c2;
                u32 bh0 = *(const u32*)&Kh[off];
                u32 bh1 = *(const u32*)&Kh[off + 8];
                u32 bl0 = *(const u32*)&Kl[off];
                u32 bl1 = *(const u32*)&Kl[off + 8];
                mma16816(s[nc], qh[kc], bh0, bh1);
                mma16816(s[nc], qh[kc], bl0, bl1);
                mma16816(s[nc], ql[kc], bh0, bh1);
            }

        u32 ph[4][4], pl[4][4];
        #pragma unroll
        for (int j = 0; j < 8; j++) {
            float p0 = __expf(s[j][0]);
            float p1 = __expf(s[j][1]);
            float p2 = __expf(s[j][2]);
            float p3 = __expf(s[j][3]);
            lsum0 += p0 + p1;
            lsum1 += p2 + p3;
            int kc2 = j >> 1, hl = j & 1;
            bsplit2(p0, p1, ph[kc2][hl * 2 + 0], pl[kc2][hl * 2 + 0]);
            bsplit2(p2, p3, ph[kc2][hl * 2 + 1], pl[kc2][hl * 2 + 1]);
        }

        u32 vhb = sb + (u32)buf * 20480 + 2 * 5120;
        u32 vlb = sb + (u32)buf * 20480 + 3 * 5120;
        #pragma unroll
        for (int kc2 = 0; kc2 < 4; kc2++) {
            u32 a0 = (u32)(((kc2 * 16 + vkey) * KST) + vdim) * 2;
            u32 a1 = a0 + 32;
            u32 vh0[4], vh1[4], vl0[4], vl1[4];
            ldmat4t(vh0, vhb + a0);
            ldmat4t(vh1, vhb + a1);
            ldmat4t(vl0, vlb + a0);
            ldmat4t(vl1, vlb + a1);
            mma16816(o[0], ph[kc2], vh0[0], vh0[1]);
            mma16816(o[0], ph[kc2], vl0[0], vl0[1]);
            mma16816(o[0], pl[kc2], vh0[0], vh0[1]);
            mma16816(o[1], ph[kc2], vh0[2], vh0[3]);
            mma16816(o[1], ph[kc2], vl0[2], vl0[3]);
            mma16816(o[1], pl[kc2], vh0[2], vh0[3]);
            mma16816(o[2], ph[kc2], vh1[0], vh1[1]);
            mma16816(o[2], ph[kc2], vl1[0], vl1[1]);
            mma16816(o[2], pl[kc2], vh1[0], vh1[1]);
            mma16816(o[3], ph[kc2], vh1[2], vh1[3]);
            mma16816(o[3], ph[kc2], vl1[2], vl1[3]);
            mma16816(o[3], pl[kc2], vh1[2], vh1[3]);
        }
    }

    lsum0 += __shfl_xor_sync(0xffffffffu, lsum0, 1);
    lsum0 += __shfl_xor_sync(0xffffffffu, lsum0, 2);
    lsum1 += __shfl_xor_sync(0xffffffffu, lsum1, 1);
    lsum1 += __shfl_xor_sync(0xffffffffu, lsum1, 2);
    float inv0 = 1.0f / lsum0, inv1 = 1.0f / lsum1;

    int row0 = q0 + w * 16 + r;
    size_t o0 = ((size_t)(b * HW + row0)) * CDIM + h * DHEAD;
    size_t o1 = o0 + 8 * CDIM;
    #pragma unroll
    for (int nc2 = 0; nc2 < 4; nc2++) {
        u32 hh, ll;
        bsplit2(o[nc2][0] * inv0, o[nc2][1] * inv0, hh, ll);
        *(u32*)&g_aoh[o0 + nc2 * 8 + c2] = hh;
        *(u32*)&g_aol[o0 + nc2 * 8 + c2] = ll;
        bsplit2(o[nc2][2] * inv1, o[nc2][3] * inv1, hh, ll);
        *(u32*)&g_aoh[o1 + nc2 * 8 + c2] = hh;
        *(u32*)&g_aol[o1 + nc2 * 8 + c2] = ll;
    }
}

// ---------------------------------------------------------------------------
extern "C" void kernel_launch(void* const* d_in, const int* in_sizes, int n_in,
                              void* d_out, int out_size)
{
    const float* x  = (const float*)d_in[0];
    const float* wq = (const float*)d_in[1];
    const float* bq = (const float*)d_in[2];
    const float* wk = (const float*)d_in[3];
    const float* bk = (const float*)d_in[4];
    const float* wv = (const float*)d_in[5];
    const float* bv = (const float*)d_in[6];
    const float* wo = (const float*)d_in[7];
    const float* bo = (const float*)d_in[8];

    const int PROJ_SMEM = PSTAGE * 2 * 2;   // 110592 bytes
    cudaFuncSetAttribute(k_proj_qkv, cudaFuncAttributeMaxDynamicSharedMemorySize, PROJ_SMEM);
    cudaFuncSetAttribute(k_proj_out, cudaFuncAttributeMaxDynamicSharedMemorySize, PROJ_SMEM);

    {   // 0) split weights once
        k_split_w<<<256, 256>>>(wq, wk, wv, wo);
    }
    {   // 1) transpose + positional encoding -> split bf16 xs
        dim3 blk(32, 8);
        dim3 grd(HW / 32, CDIM / 32, BATCH);
        k_transpose_pe<<<grd, blk>>>(x);
    }
    {   // 2) QKV projections (pure tensor-core)
        dim3 grd(CDIM / 64, MROWS / 128, 3);
        k_proj_qkv<<<grd, 256, PROJ_SMEM>>>(bq, bk, bv);
    }
    {   // 3) flash attention
        dim3 grd(HW / 128, BATCH * NHEAD);
        k_attn_mma<<<grd, 256>>>();
    }
    {   // 4) output projection + transpose to [b,c,h,w]
        dim3 grd(CDIM / 64, MROWS / 128);
        k_proj_out<<<grd, 256, PROJ_SMEM>>>(bo, (float*)d_out);
    }
}

// round 10
// speedup vs baseline: 5.1028x; 1.2353x over previous
#include <cuda_runtime.h>
#include <cuda_bf16.h>
#include <cuda_fp16.h>
#include <math.h>
#include <stdint.h>

#define BATCH 4
#define CDIM  256
#define HW    2304          // n = 48*48
#define MROWS (BATCH*HW)    // 9216
#define NHEAD 8
#define DHEAD 32

typedef unsigned long long u64;
typedef unsigned int u32;
typedef unsigned short u16;

// Scratch (static device memory; no runtime allocation allowed).
__device__ __align__(16) u16 g_xsh[MROWS*CDIM];   // xs bf16 hi
__device__ __align__(16) u16 g_xsl[MROWS*CDIM];   // xs bf16 lo
__device__ __align__(16) u16 g_qh[MROWS*CDIM];    // Q fp16 (scaled), single
__device__ __align__(16) u16 g_kh[MROWS*CDIM];    // K fp16 hi
__device__ __align__(16) u16 g_kl[MROWS*CDIM];    // K fp16 lo
__device__ __align__(16) u16 g_vh[MROWS*CDIM];    // V fp16 hi
__device__ __align__(16) u16 g_vl[MROWS*CDIM];    // V fp16 lo
__device__ __align__(16) u16 g_aoh[MROWS*CDIM];   // attn out bf16 hi
__device__ __align__(16) u16 g_aol[MROWS*CDIM];   // attn out bf16 lo
__device__ __align__(16) u16 g_wh[4*CDIM*CDIM];   // weights bf16 hi
__device__ __align__(16) u16 g_wl[4*CDIM*CDIM];   // weights bf16 lo

// ---------------------------------------------------------------------------
// helpers
// ---------------------------------------------------------------------------
__device__ __forceinline__ u32 bf2(float lo, float hi) {
    u32 r; asm("cvt.rn.bf16x2.f32 %0, %1, %2;" : "=r"(r) : "f"(hi), "f"(lo));
    return r;
}
__device__ __forceinline__ void bsplit2(float x0, float x1, u32& h, u32& l) {
    h = bf2(x0, x1);
    float h0 = __uint_as_float(h << 16);
    float h1 = __uint_as_float(h & 0xFFFF0000u);
    l = bf2(x0 - h0, x1 - h1);
}
__device__ __forceinline__ void bsplit1(float x, u16& h, u16& l) {
    __nv_bfloat16 hb = __float2bfloat16_rn(x);
    float hf = __bfloat162float(hb);
    __nv_bfloat16 lb = __float2bfloat16_rn(x - hf);
    h = *(u16*)&hb; l = *(u16*)&lb;
}
// fp16 pack (lo -> low half, hi -> high half)
__device__ __forceinline__ u32 hf2(float lo, float hi) {
    u32 r; asm("cvt.rn.f16x2.f32 %0, %1, %2;" : "=r"(r) : "f"(hi), "f"(lo));
    return r;
}
// fp16 split pair into hi + residual lo (packed)
__device__ __forceinline__ void hsplit2(float x0, float x1, u32& h, u32& l) {
    __half h0 = __float2half_rn(x0), h1 = __float2half_rn(x1);
    float f0 = __half2float(h0), f1 = __half2float(h1);
    __half l0 = __float2half_rn(x0 - f0), l1 = __float2half_rn(x1 - f1);
    h = ((u32)(*(u16*)&h1) << 16) | (u32)(*(u16*)&h0);
    l = ((u32)(*(u16*)&l1) << 16) | (u32)(*(u16*)&l0);
}
__device__ __forceinline__ void mma16816(float d[4], const u32 a[4], u32 b0, u32 b1) {
    asm volatile("mma.sync.aligned.m16n8k16.row.col.f32.bf16.bf16.f32 "
        "{%0,%1,%2,%3}, {%4,%5,%6,%7}, {%8,%9}, {%0,%1,%2,%3};"
        : "+f"(d[0]), "+f"(d[1]), "+f"(d[2]), "+f"(d[3])
        : "r"(a[0]), "r"(a[1]), "r"(a[2]), "r"(a[3]), "r"(b0), "r"(b1));
}
__device__ __forceinline__ void mma16816h(float d[4], const u32 a[4], u32 b0, u32 b1) {
    asm volatile("mma.sync.aligned.m16n8k16.row.col.f32.f16.f16.f32 "
        "{%0,%1,%2,%3}, {%4,%5,%6,%7}, {%8,%9}, {%0,%1,%2,%3};"
        : "+f"(d[0]), "+f"(d[1]), "+f"(d[2]), "+f"(d[3])
        : "r"(a[0]), "r"(a[1]), "r"(a[2]), "r"(a[3]), "r"(b0), "r"(b1));
}
__device__ __forceinline__ u32 smem_u32_(const void* p) {
    u32 a; asm("{ .reg .u64 t; cvta.to.shared.u64 t, %1; cvt.u32.u64 %0, t; }"
               : "=r"(a) : "l"(p)); return a;
}
__device__ __forceinline__ void cpa16(u32 dst, const void* src) {
    asm volatile("cp.async.cg.shared.global [%0], [%1], 16;"
                 :: "r"(dst), "l"(src) : "memory");
}
#define CP_COMMIT() asm volatile("cp.async.commit_group;" ::: "memory")
#define CP_WAIT0()  asm volatile("cp.async.wait_group 0;" ::: "memory")
__device__ __forceinline__ void ldmat4(u32 r[4], u32 addr) {
    asm volatile("ldmatrix.sync.aligned.m8n8.x4.shared.b16 {%0,%1,%2,%3}, [%4];"
        : "=r"(r[0]), "=r"(r[1]), "=r"(r[2]), "=r"(r[3]) : "r"(addr));
}
__device__ __forceinline__ void ldmat4t(u32 r[4], u32 addr) {
    asm volatile("ldmatrix.sync.aligned.m8n8.x4.trans.shared.b16 {%0,%1,%2,%3}, [%4];"
        : "=r"(r[0]), "=r"(r[1]), "=r"(r[2]), "=r"(r[3]) : "r"(addr));
}

// ---------------------------------------------------------------------------
// Kernel 0: split weight matrices once (4 x 256x256, bf16 hi/lo)
// ---------------------------------------------------------------------------
__global__ void k_split_w(const float* __restrict__ wq, const float* __restrict__ wk,
                          const float* __restrict__ wv, const float* __restrict__ wo)
{
    int idx = blockIdx.x * 256 + threadIdx.x;
    const float* ws[4] = { wq, wk, wv, wo };
    #pragma unroll
    for (int m = 0; m < 4; m++) {
        float v = ws[m][idx];
        u16 h, l; bsplit1(v, h, l);
        g_wh[m * 65536 + idx] = h;
        g_wl[m * 65536 + idx] = l;
    }
}

// ---------------------------------------------------------------------------
// Kernel 1: x [b,c,h,w] -> xs split bf16 [b,n,c] transpose + positional enc
// ---------------------------------------------------------------------------
__global__ void k_transpose_pe(const float* __restrict__ x)
{
    __shared__ float tile[32][33];
    int b  = blockIdx.z;
    int p0 = blockIdx.x * 32;
    int c0 = blockIdx.y * 32;
    int tx = threadIdx.x, ty = threadIdx.y;

    #pragma unroll
    for (int i = 0; i < 4; i++) {
        int cc = c0 + ty + i * 8;
        tile[ty + i * 8][tx] = x[((size_t)(b * CDIM + cc)) * HW + p0 + tx];
    }
    __syncthreads();
    #pragma unroll
    for (int i = 0; i < 4; i++) {
        int p  = p0 + ty + i * 8;
        int cc = c0 + tx;
        float v = tile[tx][ty + i * 8];
        float pe = 0.0f;
        if (p != 0) {
            float ang = (float)p * powf(10000.0f, -2.0f * (float)cc / 256.0f);
            pe = (cc & 1) ? cosf(ang) : sinf(ang);
        }
        float val = v + pe;
        u16 h, l; bsplit1(val, h, l);
        size_t idx = ((size_t)(b * HW + p)) * CDIM + cc;
        g_xsh[idx] = h;
        g_xsl[idx] = l;
    }
}

// ---------------------------------------------------------------------------
// Projection GEMM (pure MMA, bf16 3-pass): out = A @ W^T + bias.
// ---------------------------------------------------------------------------
#define PST   72
#define SA_H  0
#define SA_L  9216
#define SW_H  18432
#define SW_L  23040
#define PSTAGE 27648

__device__ __forceinline__ void proj_stage(
    u32 sbase, int buf, int m0, int n0, int k0, int tid,
    const u16* __restrict__ Agh, const u16* __restrict__ Agl,
    const u16* __restrict__ Wgh, const u16* __restrict__ Wgl)
{
    u32 b0 = sbase + (u32)buf * (PSTAGE * 2);
    #pragma unroll
    for (int it = 0; it < 4; it++) {
        int idx = tid + it * 256;
        int row = idx >> 3, c8 = (idx & 7) * 8;
        size_t gs = (size_t)(m0 + row) * CDIM + k0 + c8;
        u32 doff = (u32)(row * PST + c8) * 2;
        cpa16(b0 + SA_H * 2 + doff, Agh + gs);
        cpa16(b0 + SA_L * 2 + doff, Agl + gs);
    }
    #pragma unroll
    for (int it = 0; it < 2; it++) {
        int idx = tid + it * 256;
        int row = idx >> 3, c8 = (idx & 7) * 8;
        size_t gs = (size_t)(n0 + row) * CDIM + k0 + c8;
        u32 doff = (u32)(row * PST + c8) * 2;
        cpa16(b0 + SW_H * 2 + doff, Wgh + gs);
        cpa16(b0 + SW_L * 2 + doff, Wgl + gs);
    }
}

// OUT_MODE: 0 = fp16 split (QKV), 1 = fp32 transposed (final out)
template<int OUT_MODE>
__device__ __forceinline__ void proj_body(
    const u16* __restrict__ Agh, const u16* __restrict__ Agl,
    int widx, const float* __restrict__ bias,
    u16* __restrict__ outh, u16* __restrict__ outl,
    float* __restrict__ outf, float qs, bool want_lo)
{
    extern __shared__ u16 smp[];
    int tid = threadIdx.x;
    int w = tid >> 5, lane = tid & 31;
    int r = lane >> 2, c2 = (lane & 3) * 2;
    int m0 = blockIdx.y * 128, n0 = blockIdx.x * 64;
    u32 sbase = smem_u32_(smp);
    const u16* Wgh = g_wh + widx * 65536;
    const u16* Wgl = g_wl + widx * 65536;

    float o[8][4];
    #pragma unroll
    for (int i = 0; i < 8; i++)
        #pragma unroll
        for (int j = 0; j < 4; j++) o[i][j] = 0.0f;

    proj_stage(sbase, 0, m0, n0, 0, tid, Agh, Agl, Wgh, Wgl);
    CP_COMMIT();

    u32 arow = (u32)(w * 16 + (lane & 15));
    u32 acol = (u32)((lane >> 4) << 3);

    for (int c = 0; c < 4; c++) {
        CP_WAIT0();
        __syncthreads();
        if (c < 3) {
            proj_stage(sbase, (c + 1) & 1, m0, n0, (c + 1) * 64, tid, Agh, Agl, Wgh, Wgl);
            CP_COMMIT();
        }

        int sb = (c & 1) * PSTAGE;
        const u16* sWh = smp + sb + SW_H;
        const u16* sWl = smp + sb + SW_L;
        u32 abase = sbase + (u32)sb * 2 + (arow * PST + acol) * 2;

        #pragma unroll
        for (int kc = 0; kc < 4; kc++) {
            u32 ah[4], al[4];
            u32 aoff = abase + (u32)(kc * 16) * 2;
            ldmat4(ah, aoff + SA_H * 2);
            ldmat4(al, aoff + SA_L * 2);
            #pragma unroll
            for (int nc = 0; nc < 8; nc++) {
                int off = (nc * 8 + r) * PST + kc * 16 + c2;
                u32 bh0 = *(const u32*)&sWh[off];
                u32 bh1 = *(const u32*)&sWh[off + 8];
                u32 bl0 = *(const u32*)&sWl[off];
                u32 bl1 = *(const u32*)&sWl[off + 8];
                mma16816(o[nc], ah, bh0, bh1);
                mma16816(o[nc], ah, bl0, bl1);
                mma16816(o[nc], al, bh0, bh1);
            }
        }
    }

    int mr0 = m0 + w * 16 + r;
    int mr1 = mr0 + 8;
    if (OUT_MODE == 0) {
        size_t r0off = (size_t)mr0 * CDIM + n0;
        size_t r1off = (size_t)mr1 * CDIM + n0;
        #pragma unroll
        for (int nc = 0; nc < 8; nc++) {
            float2 bi = *(const float2*)(bias + n0 + nc * 8 + c2);
            u32 hh, ll;
            hsplit2((o[nc][0] + bi.x) * qs, (o[nc][1] + bi.y) * qs, hh, ll);
            *(u32*)&outh[r0off + nc * 8 + c2] = hh;
            if (want_lo) *(u32*)&outl[r0off + nc * 8 + c2] = ll;
            hsplit2((o[nc][2] + bi.x) * qs, (o[nc][3] + bi.y) * qs, hh, ll);
            *(u32*)&outh[r1off + nc * 8 + c2] = hh;
            if (want_lo) *(u32*)&outl[r1off + nc * 8 + c2] = ll;
        }
    } else {
        int bb0 = mr0 / HW, pp0 = mr0 % HW;
        int bb1 = mr1 / HW, pp1 = mr1 % HW;
        #pragma unroll
        for (int nc = 0; nc < 8; nc++) {
            float2 bi = *(const float2*)(bias + n0 + nc * 8 + c2);
            int nn = n0 + nc * 8 + c2;
            outf[((size_t)(bb0 * CDIM + nn)) * HW + pp0]     = o[nc][0] + bi.x;
            outf[((size_t)(bb0 * CDIM + nn + 1)) * HW + pp0] = o[nc][1] + bi.y;
            outf[((size_t)(bb1 * CDIM + nn)) * HW + pp1]     = o[nc][2] + bi.x;
            outf[((size_t)(bb1 * CDIM + nn + 1)) * HW + pp1] = o[nc][3] + bi.y;
        }
    }
}

__global__ void __launch_bounds__(256) k_proj_qkv(
    const float* __restrict__ bq, const float* __restrict__ bk,
    const float* __restrict__ bv)
{
    const float* bias; u16* outh; u16* outl; float qs; bool want_lo;
    if (blockIdx.z == 0)      { bias = bq; outh = g_qh; outl = nullptr; qs = 0.17677669529663687f; want_lo = false; }
    else if (blockIdx.z == 1) { bias = bk; outh = g_kh; outl = g_kl; qs = 1.0f; want_lo = true; }
    else                      { bias = bv; outh = g_vh; outl = g_vl; qs = 1.0f; want_lo = true; }
    proj_body<0>(g_xsh, g_xsl, blockIdx.z, bias, outh, outl, nullptr, qs, want_lo);
}

__global__ void __launch_bounds__(256) k_proj_out(
    const float* __restrict__ bo, float* __restrict__ out)
{
    proj_body<1>(g_aoh, g_aol, 3, bo, nullptr, nullptr, out, 1.0f, false);
}

// ---------------------------------------------------------------------------
// Kernel 3: flash attention, fp16 2-pass (Q single fp16, K/V fp16 hi+lo).
// smem: [buf][Kh,Kl,Vh,Vl][64 rows x 40 halves]; array = 5120 B, buf = 20480 B
// ---------------------------------------------------------------------------
#define KST 40
#define NT  (HW / 64)

__global__ void __launch_bounds__(256, 2) k_attn_mma()
{
    __shared__ u16 sbuf[2][4][64 * KST];

    int tid = threadIdx.x;
    int w = tid >> 5, lane = tid & 31;
    int r = lane >> 2, c2 = (lane & 3) * 2;
    int b = blockIdx.y >> 3, h = blockIdx.y & 7;
    int q0 = blockIdx.x * 128;
    u32 sb = smem_u32_(&sbuf[0][0][0]);

    int srow = tid >> 2, sch = (tid & 3) * 8;
    size_t gbase = ((size_t)(b * HW) + srow) * CDIM + h * DHEAD + sch;
    u32 sdst = sb + (u32)(srow * KST + sch) * 2;

    {   // prologue: stage tile 0
        size_t g0 = gbase;
        cpa16(sdst,              g_kh + g0);
        cpa16(sdst +  1 * 5120,  g_kl + g0);
        cpa16(sdst +  2 * 5120,  g_vh + g0);
        cpa16(sdst +  3 * 5120,  g_vl + g0);
        CP_COMMIT();
    }

    // Q fragments (fp16, pre-scaled) straight from gmem
    u32 qh[2][4];
    {
        const u16* qhg = g_qh + ((size_t)(b * HW + q0 + w * 16)) * CDIM + h * DHEAD;
        #pragma unroll
        for (int kc = 0; kc < 2; kc++)
            #pragma unroll
            for (int i = 0; i < 4; i++) {
                int rr = r + (i & 1) * 8;
                int cc = kc * 16 + c2 + (i >> 1) * 8;
                qh[kc][i] = *(const u32*)(qhg + (size_t)rr * CDIM + cc);
            }
    }

    float o[4][4];
    #pragma unroll
    for (int i = 0; i < 4; i++)
        #pragma unroll
        for (int j = 0; j < 4; j++) o[i][j] = 0.0f;
    float lsum0 = 0.0f, lsum1 = 0.0f;

    int vkey = lane & 15;
    int vdim = (lane >> 4) << 3;

    for (int kt = 0; kt < NT; kt++) {
        int buf = kt & 1;
        CP_WAIT0();
        __syncthreads();
        if (kt + 1 < NT) {
            size_t g1 = gbase + (size_t)(kt + 1) * 64 * CDIM;
            u32 d1 = sdst + (u32)((kt + 1) & 1) * 20480;
            cpa16(d1,             g_kh + g1);
            cpa16(d1 + 1 * 5120,  g_kl + g1);
            cpa16(d1 + 2 * 5120,  g_vh + g1);
            cpa16(d1 + 3 * 5120,  g_vl + g1);
            CP_COMMIT();
        }

        const u16* Kh = sbuf[buf][0];
        const u16* Kl = sbuf[buf][1];

        // ---- S = Qh (Kh + Kl) : 2 passes ----
        float s[8][4];
        #pragma unroll
        for (int i = 0; i < 8; i++)
            #pragma unroll
            for (int j = 0; j < 4; j++) s[i][j] = 0.0f;

        #pragma unroll
        for (int kc = 0; kc < 2; kc++)
            #pragma unroll
            for (int nc = 0; nc < 8; nc++) {
                int off = (nc * 8 + r) * KST + kc * 16 + c2;
                u32 bh0 = *(const u32*)&Kh[off];
                u32 bh1 = *(const u32*)&Kh[off + 8];
                u32 bl0 = *(const u32*)&Kl[off];
                u32 bl1 = *(const u32*)&Kl[off + 8];
                mma16816h(s[nc], qh[kc], bh0, bh1);
                mma16816h(s[nc], qh[kc], bl0, bl1);
            }

        // ---- softmax (fp32 sums); P -> fp16 (single) ----
        u32 ph[4][4];
        #pragma unroll
        for (int j = 0; j < 8; j++) {
            float p0 = __expf(s[j][0]);
            float p1 = __expf(s[j][1]);
            float p2 = __expf(s[j][2]);
            float p3 = __expf(s[j][3]);
            lsum0 += p0 + p1;
            lsum1 += p2 + p3;
            int kc2 = j >> 1, hl = j & 1;
            ph[kc2][hl * 2 + 0] = hf2(p0, p1);
            ph[kc2][hl * 2 + 1] = hf2(p2, p3);
        }

        // ---- O += Ph (Vh + Vl) : 2 passes ----
        u32 vhb = sb + (u32)buf * 20480 + 2 * 5120;
        u32 vlb = sb + (u32)buf * 20480 + 3 * 5120;
        #pragma unroll
        for (int kc2 = 0; kc2 < 4; kc2++) {
            u32 a0 = (u32)(((kc2 * 16 + vkey) * KST) + vdim) * 2;
            u32 a1 = a0 + 32;
            u32 vh0[4], vh1[4], vl0[4], vl1[4];
            ldmat4t(vh0, vhb + a0);
            ldmat4t(vh1, vhb + a1);
            ldmat4t(vl0, vlb + a0);
            ldmat4t(vl1, vlb + a1);
            mma16816h(o[0], ph[kc2], vh0[0], vh0[1]);
            mma16816h(o[0], ph[kc2], vl0[0], vl0[1]);
            mma16816h(o[1], ph[kc2], vh0[2], vh0[3]);
            mma16816h(o[1], ph[kc2], vl0[2], vl0[3]);
            mma16816h(o[2], ph[kc2], vh1[0], vh1[1]);
            mma16816h(o[2], ph[kc2], vl1[0], vl1[1]);
            mma16816h(o[3], ph[kc2], vh1[2], vh1[3]);
            mma16816h(o[3], ph[kc2], vl1[2], vl1[3]);
        }
    }

    lsum0 += __shfl_xor_sync(0xffffffffu, lsum0, 1);
    lsum0 += __shfl_xor_sync(0xffffffffu, lsum0, 2);
    lsum1 += __shfl_xor_sync(0xffffffffu, lsum1, 1);
    lsum1 += __shfl_xor_sync(0xffffffffu, lsum1, 2);
    float inv0 = 1.0f / lsum0, inv1 = 1.0f / lsum1;

    int row0 = q0 + w * 16 + r;
    size_t o0 = ((size_t)(b * HW + row0)) * CDIM + h * DHEAD;
    size_t o1 = o0 + 8 * CDIM;
    #pragma unroll
    for (int nc2 = 0; nc2 < 4; nc2++) {
        u32 hh, ll;
        bsplit2(o[nc2][0] * inv0, o[nc2][1] * inv0, hh, ll);
        *(u32*)&g_aoh[o0 + nc2 * 8 + c2] = hh;
        *(u32*)&g_aol[o0 + nc2 * 8 + c2] = ll;
        bsplit2(o[nc2][2] * inv1, o[nc2][3] * inv1, hh, ll);
        *(u32*)&g_aoh[o1 + nc2 * 8 + c2] = hh;
        *(u32*)&g_aol[o1 + nc2 * 8 + c2] = ll;
    }
}

// ---------------------------------------------------------------------------
extern "C" void kernel_launch(void* const* d_in, const int* in_sizes, int n_in,
                              void* d_out, int out_size)
{
    const float* x  = (const float*)d_in[0];
    const float* wq = (const float*)d_in[1];
    const float* bq = (const float*)d_in[2];
    const float* wk = (const float*)d_in[3];
    const float* bk = (const float*)d_in[4];
    const float* wv = (const float*)d_in[5];
    const float* bv = (const float*)d_in[6];
    const float* wo = (const float*)d_in[7];
    const float* bo = (const float*)d_in[8];

    const int PROJ_SMEM = PSTAGE * 2 * 2;   // 110592 bytes
    cudaFuncSetAttribute(k_proj_qkv, cudaFuncAttributeMaxDynamicSharedMemorySize, PROJ_SMEM);
    cudaFuncSetAttribute(k_proj_out, cudaFuncAttributeMaxDynamicSharedMemorySize, PROJ_SMEM);

    {   // 0) split weights once
        k_split_w<<<256, 256>>>(wq, wk, wv, wo);
    }
    {   // 1) transpose + positional encoding -> split bf16 xs
        dim3 blk(32, 8);
        dim3 grd(HW / 32, CDIM / 32, BATCH);
        k_transpose_pe<<<grd, blk>>>(x);
    }
    {   // 2) QKV projections -> fp16 (Q single, K/V hi+lo)
        dim3 grd(CDIM / 64, MROWS / 128, 3);
        k_proj_qkv<<<grd, 256, PROJ_SMEM>>>(bq, bk, bv);
    }
    {   // 3) flash attention (fp16 2-pass)
        dim3 grd(HW / 128, BATCH * NHEAD);
        k_attn_mma<<<grd, 256>>>();
    }
    {   // 4) output projection + transpose to [b,c,h,w]
        dim3 grd(CDIM / 64, MROWS / 128);
        k_proj_out<<<grd, 256, PROJ_SMEM>>>(bo, (float*)d_out);
    }
}

// round 11
// speedup vs baseline: 7.0000x; 1.3718x over previous
#include <cuda_runtime.h>
#include <cuda_bf16.h>
#include <cuda_fp16.h>
#include <math.h>
#include <stdint.h>

#define BATCH 4
#define CDIM  256
#define HW    2304          // n = 48*48
#define MROWS (BATCH*HW)    // 9216
#define NHEAD 8
#define DHEAD 32

typedef unsigned long long u64;
typedef unsigned int u32;
typedef unsigned short u16;

// Scratch (static device memory; no runtime allocation allowed).
__device__ __align__(16) u16 g_xsh[MROWS*CDIM];   // xs bf16 hi
__device__ __align__(16) u16 g_xsl[MROWS*CDIM];   // xs bf16 lo
__device__ __align__(16) u16 g_qh[MROWS*CDIM];    // Q fp16 (scaled by log2e/sqrt(32))
__device__ __align__(16) u16 g_kh[MROWS*CDIM];    // K fp16
__device__ __align__(16) u16 g_vh[MROWS*CDIM];    // V fp16
__device__ __align__(16) u16 g_aoh[MROWS*CDIM];   // attn out bf16 hi
__device__ __align__(16) u16 g_aol[MROWS*CDIM];   // attn out bf16 lo
__device__ __align__(16) u16 g_wh[4*CDIM*CDIM];   // weights bf16 hi
__device__ __align__(16) u16 g_wl[4*CDIM*CDIM];   // weights bf16 lo

// ---------------------------------------------------------------------------
// helpers
// ---------------------------------------------------------------------------
__device__ __forceinline__ u32 bf2(float lo, float hi) {
    u32 r; asm("cvt.rn.bf16x2.f32 %0, %1, %2;" : "=r"(r) : "f"(hi), "f"(lo));
    return r;
}
__device__ __forceinline__ void bsplit2(float x0, float x1, u32& h, u32& l) {
    h = bf2(x0, x1);
    float h0 = __uint_as_float(h << 16);
    float h1 = __uint_as_float(h & 0xFFFF0000u);
    l = bf2(x0 - h0, x1 - h1);
}
__device__ __forceinline__ void bsplit1(float x, u16& h, u16& l) {
    __nv_bfloat16 hb = __float2bfloat16_rn(x);
    float hf = __bfloat162float(hb);
    __nv_bfloat16 lb = __float2bfloat16_rn(x - hf);
    h = *(u16*)&hb; l = *(u16*)&lb;
}
// fp16 pack (x0 -> low half, x1 -> high half)
__device__ __forceinline__ u32 hf2(float x0, float x1) {
    u32 r; asm("cvt.rn.f16x2.f32 %0, %1, %2;" : "=r"(r) : "f"(x1), "f"(x0));
    return r;
}
__device__ __forceinline__ float ex2f(float x) {
    float r; asm("ex2.approx.ftz.f32 %0, %1;" : "=f"(r) : "f"(x));
    return r;
}
__device__ __forceinline__ void mma16816(float d[4], const u32 a[4], u32 b0, u32 b1) {
    asm volatile("mma.sync.aligned.m16n8k16.row.col.f32.bf16.bf16.f32 "
        "{%0,%1,%2,%3}, {%4,%5,%6,%7}, {%8,%9}, {%0,%1,%2,%3};"
        : "+f"(d[0]), "+f"(d[1]), "+f"(d[2]), "+f"(d[3])
        : "r"(a[0]), "r"(a[1]), "r"(a[2]), "r"(a[3]), "r"(b0), "r"(b1));
}
__device__ __forceinline__ void mma16816h(float d[4], const u32 a[4], u32 b0, u32 b1) {
    asm volatile("mma.sync.aligned.m16n8k16.row.col.f32.f16.f16.f32 "
        "{%0,%1,%2,%3}, {%4,%5,%6,%7}, {%8,%9}, {%0,%1,%2,%3};"
        : "+f"(d[0]), "+f"(d[1]), "+f"(d[2]), "+f"(d[3])
        : "r"(a[0]), "r"(a[1]), "r"(a[2]), "r"(a[3]), "r"(b0), "r"(b1));
}
__device__ __forceinline__ u32 smem_u32_(const void* p) {
    u32 a; asm("{ .reg .u64 t; cvta.to.shared.u64 t, %1; cvt.u32.u64 %0, t; }"
               : "=r"(a) : "l"(p)); return a;
}
__device__ __forceinline__ void cpa16(u32 dst, const void* src) {
    asm volatile("cp.async.cg.shared.global [%0], [%1], 16;"
                 :: "r"(dst), "l"(src) : "memory");
}
#define CP_COMMIT() asm volatile("cp.async.commit_group;" ::: "memory")
#define CP_WAIT0()  asm volatile("cp.async.wait_group 0;" ::: "memory")
__device__ __forceinline__ void ldmat4(u32 r[4], u32 addr) {
    asm volatile("ldmatrix.sync.aligned.m8n8.x4.shared.b16 {%0,%1,%2,%3}, [%4];"
        : "=r"(r[0]), "=r"(r[1]), "=r"(r[2]), "=r"(r[3]) : "r"(addr));
}
__device__ __forceinline__ void ldmat4t(u32 r[4], u32 addr) {
    asm volatile("ldmatrix.sync.aligned.m8n8.x4.trans.shared.b16 {%0,%1,%2,%3}, [%4];"
        : "=r"(r[0]), "=r"(r[1]), "=r"(r[2]), "=r"(r[3]) : "r"(addr));
}

// ---------------------------------------------------------------------------
// Kernel 0: split weight matrices once (4 x 256x256, bf16 hi/lo)
// ---------------------------------------------------------------------------
__global__ void k_split_w(const float* __restrict__ wq, const float* __restrict__ wk,
                          const float* __restrict__ wv, const float* __restrict__ wo)
{
    int idx = blockIdx.x * 256 + threadIdx.x;
    const float* ws[4] = { wq, wk, wv, wo };
    #pragma unroll
    for (int m = 0; m < 4; m++) {
        float v = ws[m][idx];
        u16 h, l; bsplit1(v, h, l);
        g_wh[m * 65536 + idx] = h;
        g_wl[m * 65536 + idx] = l;
    }
}

// ---------------------------------------------------------------------------
// Kernel 1: x [b,c,h,w] -> xs split bf16 [b,n,c] transpose + positional enc
// ---------------------------------------------------------------------------
__global__ void k_transpose_pe(const float* __restrict__ x)
{
    __shared__ float tile[32][33];
    int b  = blockIdx.z;
    int p0 = blockIdx.x * 32;
    int c0 = blockIdx.y * 32;
    int tx = threadIdx.x, ty = threadIdx.y;

    #pragma unroll
    for (int i = 0; i < 4; i++) {
        int cc = c0 + ty + i * 8;
        tile[ty + i * 8][tx] = x[((size_t)(b * CDIM + cc)) * HW + p0 + tx];
    }
    __syncthreads();
    #pragma unroll
    for (int i = 0; i < 4; i++) {
        int p  = p0 + ty + i * 8;
        int cc = c0 + tx;
        float v = tile[tx][ty + i * 8];
        float pe = 0.0f;
        if (p != 0) {
            float ang = (float)p * powf(10000.0f, -2.0f * (float)cc / 256.0f);
            pe = (cc & 1) ? cosf(ang) : sinf(ang);
        }
        float val = v + pe;
        u16 h, l; bsplit1(val, h, l);
        size_t idx = ((size_t)(b * HW + p)) * CDIM + cc;
        g_xsh[idx] = h;
        g_xsl[idx] = l;
    }
}

// ---------------------------------------------------------------------------
// Projection GEMM (pure MMA, bf16 3-pass): out = A @ W^T + bias.
// ---------------------------------------------------------------------------
#define PST   72
#define SA_H  0
#define SA_L  9216
#define SW_H  18432
#define SW_L  23040
#define PSTAGE 27648

__device__ __forceinline__ void proj_stage(
    u32 sbase, int buf, int m0, int n0, int k0, int tid,
    const u16* __restrict__ Agh, const u16* __restrict__ Agl,
    const u16* __restrict__ Wgh, const u16* __restrict__ Wgl)
{
    u32 b0 = sbase + (u32)buf * (PSTAGE * 2);
    #pragma unroll
    for (int it = 0; it < 4; it++) {
        int idx = tid + it * 256;
        int row = idx >> 3, c8 = (idx & 7) * 8;
        size_t gs = (size_t)(m0 + row) * CDIM + k0 + c8;
        u32 doff = (u32)(row * PST + c8) * 2;
        cpa16(b0 + SA_H * 2 + doff, Agh + gs);
        cpa16(b0 + SA_L * 2 + doff, Agl + gs);
    }
    #pragma unroll
    for (int it = 0; it < 2; it++) {
        int idx = tid + it * 256;
        int row = idx >> 3, c8 = (idx & 7) * 8;
        size_t gs = (size_t)(n0 + row) * CDIM + k0 + c8;
        u32 doff = (u32)(row * PST + c8) * 2;
        cpa16(b0 + SW_H * 2 + doff, Wgh + gs);
        cpa16(b0 + SW_L * 2 + doff, Wgl + gs);
    }
}

// OUT_MODE: 0 = fp16 single (QKV), 1 = fp32 transposed (final out)
template<int OUT_MODE>
__device__ __forceinline__ void proj_body(
    const u16* __restrict__ Agh, const u16* __restrict__ Agl,
    int widx, const float* __restrict__ bias,
    u16* __restrict__ outh, float* __restrict__ outf, float qs)
{
    extern __shared__ u16 smp[];
    int tid = threadIdx.x;
    int w = tid >> 5, lane = tid & 31;
    int r = lane >> 2, c2 = (lane & 3) * 2;
    int m0 = blockIdx.y * 128, n0 = blockIdx.x * 64;
    u32 sbase = smem_u32_(smp);
    const u16* Wgh = g_wh + widx * 65536;
    const u16* Wgl = g_wl + widx * 65536;

    float o[8][4];
    #pragma unroll
    for (int i = 0; i < 8; i++)
        #pragma unroll
        for (int j = 0; j < 4; j++) o[i][j] = 0.0f;

    proj_stage(sbase, 0, m0, n0, 0, tid, Agh, Agl, Wgh, Wgl);
    CP_COMMIT();

    u32 arow = (u32)(w * 16 + (lane & 15));
    u32 acol = (u32)((lane >> 4) << 3);

    for (int c = 0; c < 4; c++) {
        CP_WAIT0();
        __syncthreads();
        if (c < 3) {
            proj_stage(sbase, (c + 1) & 1, m0, n0, (c + 1) * 64, tid, Agh, Agl, Wgh, Wgl);
            CP_COMMIT();
        }

        int sb = (c & 1) * PSTAGE;
        const u16* sWh = smp + sb + SW_H;
        const u16* sWl = smp + sb + SW_L;
        u32 abase = sbase + (u32)sb * 2 + (arow * PST + acol) * 2;

        #pragma unroll
        for (int kc = 0; kc < 4; kc++) {
            u32 ah[4], al[4];
            u32 aoff = abase + (u32)(kc * 16) * 2;
            ldmat4(ah, aoff + SA_H * 2);
            ldmat4(al, aoff + SA_L * 2);
            #pragma unroll
            for (int nc = 0; nc < 8; nc++) {
                int off = (nc * 8 + r) * PST + kc * 16 + c2;
                u32 bh0 = *(const u32*)&sWh[off];
                u32 bh1 = *(const u32*)&sWh[off + 8];
                u32 bl0 = *(const u32*)&sWl[off];
                u32 bl1 = *(const u32*)&sWl[off + 8];
                mma16816(o[nc], ah, bh0, bh1);
                mma16816(o[nc], ah, bl0, bl1);
                mma16816(o[nc], al, bh0, bh1);
            }
        }
    }

    int mr0 = m0 + w * 16 + r;
    int mr1 = mr0 + 8;
    if (OUT_MODE == 0) {
        size_t r0off = (size_t)mr0 * CDIM + n0;
        size_t r1off = (size_t)mr1 * CDIM + n0;
        #pragma unroll
        for (int nc = 0; nc < 8; nc++) {
            float2 bi = *(const float2*)(bias + n0 + nc * 8 + c2);
            *(u32*)&outh[r0off + nc * 8 + c2] =
                hf2((o[nc][0] + bi.x) * qs, (o[nc][1] + bi.y) * qs);
            *(u32*)&outh[r1off + nc * 8 + c2] =
                hf2((o[nc][2] + bi.x) * qs, (o[nc][3] + bi.y) * qs);
        }
    } else {
        int bb0 = mr0 / HW, pp0 = mr0 % HW;
        int bb1 = mr1 / HW, pp1 = mr1 % HW;
        #pragma unroll
        for (int nc = 0; nc < 8; nc++) {
            float2 bi = *(const float2*)(bias + n0 + nc * 8 + c2);
            int nn = n0 + nc * 8 + c2;
            outf[((size_t)(bb0 * CDIM + nn)) * HW + pp0]     = o[nc][0] + bi.x;
            outf[((size_t)(bb0 * CDIM + nn + 1)) * HW + pp0] = o[nc][1] + bi.y;
            outf[((size_t)(bb1 * CDIM + nn)) * HW + pp1]     = o[nc][2] + bi.x;
            outf[((size_t)(bb1 * CDIM + nn + 1)) * HW + pp1] = o[nc][3] + bi.y;
        }
    }
}

// Q scale folds softmax's log2(e): (1/sqrt(32)) * log2(e)
#define QSCALE 0.25503472316688193f

__global__ void __launch_bounds__(256) k_proj_qkv(
    const float* __restrict__ bq, const float* __restrict__ bk,
    const float* __restrict__ bv)
{
    const float* bias; u16* outh; float qs;
    if (blockIdx.z == 0)      { bias = bq; outh = g_qh; qs = QSCALE; }
    else if (blockIdx.z == 1) { bias = bk; outh = g_kh; qs = 1.0f; }
    else                      { bias = bv; outh = g_vh; qs = 1.0f; }
    proj_body<0>(g_xsh, g_xsl, blockIdx.z, bias, outh, nullptr, qs);
}

__global__ void __launch_bounds__(256) k_proj_out(
    const float* __restrict__ bo, float* __restrict__ out)
{
    proj_body<1>(g_aoh, g_aol, 3, bo, nullptr, out, 1.0f);
}

// ---------------------------------------------------------------------------
// Kernel 3: flash attention, pure fp16 single-pass.
// smem: [buf][K,V][64 rows x 40 halves]; array = 5120 B, buffer = 10240 B.
// exp via ex2 (log2e pre-folded into Q scale).
// ---------------------------------------------------------------------------
#define KST 40
#define NT  (HW / 64)

__global__ void __launch_bounds__(256, 2) k_attn_mma()
{
    __shared__ u16 sbuf[2][2][64 * KST];

    int tid = threadIdx.x;
    int w = tid >> 5, lane = tid & 31;
    int r = lane >> 2, c2 = (lane & 3) * 2;
    int b = blockIdx.y >> 3, h = blockIdx.y & 7;
    int q0 = blockIdx.x * 128;
    u32 sb = smem_u32_(&sbuf[0][0][0]);

    int srow = tid >> 2, sch = (tid & 3) * 8;
    size_t gbase = ((size_t)(b * HW) + srow) * CDIM + h * DHEAD + sch;
    u32 sdst = sb + (u32)(srow * KST + sch) * 2;

    {   // prologue: stage tile 0
        cpa16(sdst,         g_kh + gbase);
        cpa16(sdst + 5120,  g_vh + gbase);
        CP_COMMIT();
    }

    // Q fragments (fp16, pre-scaled by log2e/sqrt(32)) straight from gmem
    u32 qh[2][4];
    {
        const u16* qhg = g_qh + ((size_t)(b * HW + q0 + w * 16)) * CDIM + h * DHEAD;
        #pragma unroll
        for (int kc = 0; kc < 2; kc++)
            #pragma unroll
            for (int i = 0; i < 4; i++) {
                int rr = r + (i & 1) * 8;
                int cc = kc * 16 + c2 + (i >> 1) * 8;
                qh[kc][i] = *(const u32*)(qhg + (size_t)rr * CDIM + cc);
            }
    }

    float o[4][4];
    #pragma unroll
    for (int i = 0; i < 4; i++)
        #pragma unroll
        for (int j = 0; j < 4; j++) o[i][j] = 0.0f;
    float lsum0 = 0.0f, lsum1 = 0.0f;

    int vkey = lane & 15;
    int vdim = (lane >> 4) << 3;

    for (int kt = 0; kt < NT; kt++) {
        int buf = kt & 1;
        CP_WAIT0();
        __syncthreads();
        if (kt + 1 < NT) {
            size_t g1 = gbase + (size_t)(kt + 1) * 64 * CDIM;
            u32 d1 = sdst + (u32)((kt + 1) & 1) * 10240;
            cpa16(d1,         g_kh + g1);
            cpa16(d1 + 5120,  g_vh + g1);
            CP_COMMIT();
        }

        const u16* Kh = sbuf[buf][0];

        // ---- S' = Q K^T (in log2 domain) : single pass ----
        float s[8][4];
        #pragma unroll
        for (int i = 0; i < 8; i++)
            #pragma unroll
            for (int j = 0; j < 4; j++) s[i][j] = 0.0f;

        #pragma unroll
        for (int kc = 0; kc < 2; kc++)
            #pragma unroll
            for (int nc = 0; nc < 8; nc++) {
                int off = (nc * 8 + r) * KST + kc * 16 + c2;
                u32 bh0 = *(const u32*)&Kh[off];
                u32 bh1 = *(const u32*)&Kh[off + 8];
                mma16816h(s[nc], qh[kc], bh0, bh1);
            }

        // ---- softmax: p = 2^s' (ex2), fp32 row sums; P -> fp16 ----
        u32 ph[4][4];
        #pragma unroll
        for (int j = 0; j < 8; j++) {
            float p0 = ex2f(s[j][0]);
            float p1 = ex2f(s[j][1]);
            float p2 = ex2f(s[j][2]);
            float p3 = ex2f(s[j][3]);
            lsum0 += p0 + p1;
            lsum1 += p2 + p3;
            int kc2 = j >> 1, hl = j & 1;
            ph[kc2][hl * 2 + 0] = hf2(p0, p1);
            ph[kc2][hl * 2 + 1] = hf2(p2, p3);
        }

        // ---- O += P V : single pass ----
        u32 vhb = sb + (u32)buf * 10240 + 5120;
        #pragma unroll
        for (int kc2 = 0; kc2 < 4; kc2++) {
            u32 a0 = (u32)(((kc2 * 16 + vkey) * KST) + vdim) * 2;
            u32 a1 = a0 + 32;
            u32 vh0[4], vh1[4];
            ldmat4t(vh0, vhb + a0);
            ldmat4t(vh1, vhb + a1);
            mma16816h(o[0], ph[kc2], vh0[0], vh0[1]);
            mma16816h(o[1], ph[kc2], vh0[2], vh0[3]);
            mma16816h(o[2], ph[kc2], vh1[0], vh1[1]);
            mma16816h(o[3], ph[kc2], vh1[2], vh1[3]);
        }
    }

    lsum0 += __shfl_xor_sync(0xffffffffu, lsum0, 1);
    lsum0 += __shfl_xor_sync(0xffffffffu, lsum0, 2);
    lsum1 += __shfl_xor_sync(0xffffffffu, lsum1, 1);
    lsum1 += __shfl_xor_sync(0xffffffffu, lsum1, 2);
    float inv0 = 1.0f / lsum0, inv1 = 1.0f / lsum1;

    int row0 = q0 + w * 16 + r;
    size_t o0 = ((size_t)(b * HW + row0)) * CDIM + h * DHEAD;
    size_t o1 = o0 + 8 * CDIM;
    #pragma unroll
    for (int nc2 = 0; nc2 < 4; nc2++) {
        u32 hh, ll;
        bsplit2(o[nc2][0] * inv0, o[nc2][1] * inv0, hh, ll);
        *(u32*)&g_aoh[o0 + nc2 * 8 + c2] = hh;
        *(u32*)&g_aol[o0 + nc2 * 8 + c2] = ll;
        bsplit2(o[nc2][2] * inv1, o[nc2][3] * inv1, hh, ll);
        *(u32*)&g_aoh[o1 + nc2 * 8 + c2] = hh;
        *(u32*)&g_aol[o1 + nc2 * 8 + c2] = ll;
    }
}

// ---------------------------------------------------------------------------
extern "C" void kernel_launch(void* const* d_in, const int* in_sizes, int n_in,
                              void* d_out, int out_size)
{
    const float* x  = (const float*)d_in[0];
    const float* wq = (const float*)d_in[1];
    const float* bq = (const float*)d_in[2];
    const float* wk = (const float*)d_in[3];
    const float* bk = (const float*)d_in[4];
    const float* wv = (const float*)d_in[5];
    const float* bv = (const float*)d_in[6];
    const float* wo = (const float*)d_in[7];
    const float* bo = (const float*)d_in[8];

    const int PROJ_SMEM = PSTAGE * 2 * 2;   // 110592 bytes
    cudaFuncSetAttribute(k_proj_qkv, cudaFuncAttributeMaxDynamicSharedMemorySize, PROJ_SMEM);
    cudaFuncSetAttribute(k_proj_out, cudaFuncAttributeMaxDynamicSharedMemorySize, PROJ_SMEM);

    {   // 0) split weights once
        k_split_w<<<256, 256>>>(wq, wk, wv, wo);
    }
    {   // 1) transpose + positional encoding -> split bf16 xs
        dim3 blk(32, 8);
        dim3 grd(HW / 32, CDIM / 32, BATCH);
        k_transpose_pe<<<grd, blk>>>(x);
    }
    {   // 2) QKV projections -> single fp16 (Q pre-scaled with log2e)
        dim3 grd(CDIM / 64, MROWS / 128, 3);
        k_proj_qkv<<<grd, 256, PROJ_SMEM>>>(bq, bk, bv);
    }
    {   // 3) flash attention (fp16 single-pass, ex2 softmax)
        dim3 grd(HW / 128, BATCH * NHEAD);
        k_attn_mma<<<grd, 256>>>();
    }
    {   // 4) output projection + transpose to [b,c,h,w]
        dim3 grd(CDIM / 64, MROWS / 128);
        k_proj_out<<<grd, 256, PROJ_SMEM>>>(bo, (float*)d_out);
    }
}

// round 12
// speedup vs baseline: 8.2727x; 1.1818x over previous
#include <cuda_runtime.h>
#include <cuda_bf16.h>
#include <cuda_fp16.h>
#include <math.h>
#include <stdint.h>

#define BATCH 4
#define CDIM  256
#define HW    2304          // n = 48*48
#define MROWS (BATCH*HW)    // 9216
#define NHEAD 8
#define DHEAD 32

typedef unsigned long long u64;
typedef unsigned int u32;
typedef unsigned short u16;

// Scratch (static device memory). All inter-kernel tensors fp16.
__device__ __align__(16) u16 g_xsh[MROWS*CDIM];   // xs fp16 hi
__device__ __align__(16) u16 g_xsl[MROWS*CDIM];   // xs fp16 lo (residual)
__device__ __align__(16) u16 g_qh[MROWS*CDIM];    // Q fp16 (scaled by log2e/sqrt(32))
__device__ __align__(16) u16 g_kh[MROWS*CDIM];    // K fp16
__device__ __align__(16) u16 g_vh[MROWS*CDIM];    // V fp16
__device__ __align__(16) u16 g_aoh[MROWS*CDIM];   // attn out fp16 hi
__device__ __align__(16) u16 g_aol[MROWS*CDIM];   // attn out fp16 lo
__device__ __align__(16) u16 g_wh[4*CDIM*CDIM];   // weights fp16 (single)

// ---------------------------------------------------------------------------
// helpers
// ---------------------------------------------------------------------------
// fp16 pack (x0 -> low half, x1 -> high half)
__device__ __forceinline__ u32 hf2(float x0, float x1) {
    u32 r; asm("cvt.rn.f16x2.f32 %0, %1, %2;" : "=r"(r) : "f"(x1), "f"(x0));
    return r;
}
// fp16 split pair into hi + residual lo (packed)
__device__ __forceinline__ void hsplit2(float x0, float x1, u32& h, u32& l) {
    __half h0 = __float2half_rn(x0), h1 = __float2half_rn(x1);
    float f0 = __half2float(h0), f1 = __half2float(h1);
    __half l0 = __float2half_rn(x0 - f0), l1 = __float2half_rn(x1 - f1);
    h = ((u32)(*(u16*)&h1) << 16) | (u32)(*(u16*)&h0);
    l = ((u32)(*(u16*)&l1) << 16) | (u32)(*(u16*)&l0);
}
__device__ __forceinline__ void hsplit1(float x, u16& h, u16& l) {
    __half hb = __float2half_rn(x);
    float hf = __half2float(hb);
    __half lb = __float2half_rn(x - hf);
    h = *(u16*)&hb; l = *(u16*)&lb;
}
__device__ __forceinline__ u32 ex2h2(u32 v) {
    u32 r; asm("ex2.approx.f16x2 %0, %1;" : "=r"(r) : "r"(v));
    return r;
}
__device__ __forceinline__ u32 hadd2(u32 a, u32 b) {
    u32 r; asm("add.rn.f16x2 %0, %1, %2;" : "=r"(r) : "r"(a), "r"(b));
    return r;
}
__device__ __forceinline__ float2 h22f2(u32 v) {
    __half2 h = *(__half2*)&v;
    return __half22float2(h);
}
__device__ __forceinline__ void mma16816h(float d[4], const u32 a[4], u32 b0, u32 b1) {
    asm volatile("mma.sync.aligned.m16n8k16.row.col.f32.f16.f16.f32 "
        "{%0,%1,%2,%3}, {%4,%5,%6,%7}, {%8,%9}, {%0,%1,%2,%3};"
        : "+f"(d[0]), "+f"(d[1]), "+f"(d[2]), "+f"(d[3])
        : "r"(a[0]), "r"(a[1]), "r"(a[2]), "r"(a[3]), "r"(b0), "r"(b1));
}
__device__ __forceinline__ u32 smem_u32_(const void* p) {
    u32 a; asm("{ .reg .u64 t; cvta.to.shared.u64 t, %1; cvt.u32.u64 %0, t; }"
               : "=r"(a) : "l"(p)); return a;
}
__device__ __forceinline__ void cpa16(u32 dst, const void* src) {
    asm volatile("cp.async.cg.shared.global [%0], [%1], 16;"
                 :: "r"(dst), "l"(src) : "memory");
}
#define CP_COMMIT() asm volatile("cp.async.commit_group;" ::: "memory")
#define CP_WAIT0()  asm volatile("cp.async.wait_group 0;" ::: "memory")
__device__ __forceinline__ void ldmat4(u32 r[4], u32 addr) {
    asm volatile("ldmatrix.sync.aligned.m8n8.x4.shared.b16 {%0,%1,%2,%3}, [%4];"
        : "=r"(r[0]), "=r"(r[1]), "=r"(r[2]), "=r"(r[3]) : "r"(addr));
}
__device__ __forceinline__ void ldmat4t(u32 r[4], u32 addr) {
    asm volatile("ldmatrix.sync.aligned.m8n8.x4.trans.shared.b16 {%0,%1,%2,%3}, [%4];"
        : "=r"(r[0]), "=r"(r[1]), "=r"(r[2]), "=r"(r[3]) : "r"(addr));
}

// ---------------------------------------------------------------------------
// Kernel 0: convert weight matrices to fp16 once (4 x 256x256)
// ---------------------------------------------------------------------------
__global__ void k_split_w(const float* __restrict__ wq, const float* __restrict__ wk,
                          const float* __restrict__ wv, const float* __restrict__ wo)
{
    int idx = blockIdx.x * 256 + threadIdx.x;
    const float* ws[4] = { wq, wk, wv, wo };
    #pragma unroll
    for (int m = 0; m < 4; m++) {
        __half h = __float2half_rn(ws[m][idx]);
        g_wh[m * 65536 + idx] = *(u16*)&h;
    }
}

// ---------------------------------------------------------------------------
// Kernel 1: x [b,c,h,w] -> xs fp16 hi/lo [b,n,c] transpose + positional enc
// ---------------------------------------------------------------------------
__global__ void k_transpose_pe(const float* __restrict__ x)
{
    __shared__ float tile[32][33];
    int b  = blockIdx.z;
    int p0 = blockIdx.x * 32;
    int c0 = blockIdx.y * 32;
    int tx = threadIdx.x, ty = threadIdx.y;

    #pragma unroll
    for (int i = 0; i < 4; i++) {
        int cc = c0 + ty + i * 8;
        tile[ty + i * 8][tx] = x[((size_t)(b * CDIM + cc)) * HW + p0 + tx];
    }
    __syncthreads();
    #pragma unroll
    for (int i = 0; i < 4; i++) {
        int p  = p0 + ty + i * 8;
        int cc = c0 + tx;
        float v = tile[tx][ty + i * 8];
        float pe = 0.0f;
        if (p != 0) {
            float ang = (float)p * powf(10000.0f, -2.0f * (float)cc / 256.0f);
            pe = (cc & 1) ? cosf(ang) : sinf(ang);
        }
        float val = v + pe;
        u16 h, l; hsplit1(val, h, l);
        size_t idx = ((size_t)(b * HW + p)) * CDIM + cc;
        g_xsh[idx] = h;
        g_xsl[idx] = l;
    }
}

// ---------------------------------------------------------------------------
// Projection GEMM (fp16 2-pass: A hi/lo exact, W single): out = A @ W^T + bias
// Block = 256 thr = 8 warps; tile 128m x 64n; K chunks of 64 double-buffered.
// ---------------------------------------------------------------------------
#define PST   72
#define SA_H  0
#define SA_L  9216
#define SW    18432
#define PSTAGE 23040          // u16 per stage (46080 B); x2 = 92160 B

__device__ __forceinline__ void proj_stage(
    u32 sbase, int buf, int m0, int n0, int k0, int tid,
    const u16* __restrict__ Agh, const u16* __restrict__ Agl,
    const u16* __restrict__ Wg)
{
    u32 b0 = sbase + (u32)buf * (PSTAGE * 2);
    #pragma unroll
    for (int it = 0; it < 4; it++) {
        int idx = tid + it * 256;
        int row = idx >> 3, c8 = (idx & 7) * 8;
        size_t gs = (size_t)(m0 + row) * CDIM + k0 + c8;
        u32 doff = (u32)(row * PST + c8) * 2;
        cpa16(b0 + SA_H * 2 + doff, Agh + gs);
        cpa16(b0 + SA_L * 2 + doff, Agl + gs);
    }
    #pragma unroll
    for (int it = 0; it < 2; it++) {
        int idx = tid + it * 256;
        int row = idx >> 3, c8 = (idx & 7) * 8;
        size_t gs = (size_t)(n0 + row) * CDIM + k0 + c8;
        u32 doff = (u32)(row * PST + c8) * 2;
        cpa16(b0 + SW * 2 + doff, Wg + gs);
    }
}

// OUT_MODE: 0 = fp16 single (QKV), 1 = fp32 transposed (final out)
template<int OUT_MODE>
__device__ __forceinline__ void proj_body(
    const u16* __restrict__ Agh, const u16* __restrict__ Agl,
    int widx, const float* __restrict__ bias,
    u16* __restrict__ outh, float* __restrict__ outf, float qs)
{
    extern __shared__ u16 smp[];
    int tid = threadIdx.x;
    int w = tid >> 5, lane = tid & 31;
    int r = lane >> 2, c2 = (lane & 3) * 2;
    int m0 = blockIdx.y * 128, n0 = blockIdx.x * 64;
    u32 sbase = smem_u32_(smp);
    const u16* Wg = g_wh + widx * 65536;

    float o[8][4];
    #pragma unroll
    for (int i = 0; i < 8; i++)
        #pragma unroll
        for (int j = 0; j < 4; j++) o[i][j] = 0.0f;

    proj_stage(sbase, 0, m0, n0, 0, tid, Agh, Agl, Wg);
    CP_COMMIT();

    u32 arow = (u32)(w * 16 + (lane & 15));
    u32 acol = (u32)((lane >> 4) << 3);

    for (int c = 0; c < 4; c++) {
        CP_WAIT0();
        __syncthreads();
        if (c < 3) {
            proj_stage(sbase, (c + 1) & 1, m0, n0, (c + 1) * 64, tid, Agh, Agl, Wg);
            CP_COMMIT();
        }

        int sb = (c & 1) * PSTAGE;
        const u16* sW = smp + sb + SW;
        u32 abase = sbase + (u32)sb * 2 + (arow * PST + acol) * 2;

        #pragma unroll
        for (int kc = 0; kc < 4; kc++) {
            u32 ah[4], al[4];
            u32 aoff = abase + (u32)(kc * 16) * 2;
            ldmat4(ah, aoff + SA_H * 2);
            ldmat4(al, aoff + SA_L * 2);
            #pragma unroll
            for (int nc = 0; nc < 8; nc++) {
                int off = (nc * 8 + r) * PST + kc * 16 + c2;
                u32 b0 = *(const u32*)&sW[off];
                u32 b1 = *(const u32*)&sW[off + 8];
                mma16816h(o[nc], ah, b0, b1);
                mma16816h(o[nc], al, b0, b1);
            }
        }
    }

    int mr0 = m0 + w * 16 + r;
    int mr1 = mr0 + 8;
    if (OUT_MODE == 0) {
        size_t r0off = (size_t)mr0 * CDIM + n0;
        size_t r1off = (size_t)mr1 * CDIM + n0;
        #pragma unroll
        for (int nc = 0; nc < 8; nc++) {
            float2 bi = *(const float2*)(bias + n0 + nc * 8 + c2);
            *(u32*)&outh[r0off + nc * 8 + c2] =
                hf2((o[nc][0] + bi.x) * qs, (o[nc][1] + bi.y) * qs);
            *(u32*)&outh[r1off + nc * 8 + c2] =
                hf2((o[nc][2] + bi.x) * qs, (o[nc][3] + bi.y) * qs);
        }
    } else {
        int bb0 = mr0 / HW, pp0 = mr0 % HW;
        int bb1 = mr1 / HW, pp1 = mr1 % HW;
        #pragma unroll
        for (int nc = 0; nc < 8; nc++) {
            float2 bi = *(const float2*)(bias + n0 + nc * 8 + c2);
            int nn = n0 + nc * 8 + c2;
            outf[((size_t)(bb0 * CDIM + nn)) * HW + pp0]     = o[nc][0] + bi.x;
            outf[((size_t)(bb0 * CDIM + nn + 1)) * HW + pp0] = o[nc][1] + bi.y;
            outf[((size_t)(bb1 * CDIM + nn)) * HW + pp1]     = o[nc][2] + bi.x;
            outf[((size_t)(bb1 * CDIM + nn + 1)) * HW + pp1] = o[nc][3] + bi.y;
        }
    }
}

// Q scale folds softmax's log2(e): (1/sqrt(32)) * log2(e)
#define QSCALE 0.25503472316688193f

__global__ void __launch_bounds__(256) k_proj_qkv(
    const float* __restrict__ bq, const float* __restrict__ bk,
    const float* __restrict__ bv)
{
    const float* bias; u16* outh; float qs;
    if (blockIdx.z == 0)      { bias = bq; outh = g_qh; qs = QSCALE; }
    else if (blockIdx.z == 1) { bias = bk; outh = g_kh; qs = 1.0f; }
    else                      { bias = bv; outh = g_vh; qs = 1.0f; }
    proj_body<0>(g_xsh, g_xsl, blockIdx.z, bias, outh, nullptr, qs);
}

__global__ void __launch_bounds__(256) k_proj_out(
    const float* __restrict__ bo, float* __restrict__ out)
{
    proj_body<1>(g_aoh, g_aol, 3, bo, nullptr, out, 1.0f);
}

// ---------------------------------------------------------------------------
// Kernel 3: flash attention, fp16 single-pass; ex2.approx.f16x2 softmax;
// K-fragments via ldmatrix.x4. smem: [buf][K,V][64 x 40 halves].
// ---------------------------------------------------------------------------
#define KST 40
#define NT  (HW / 64)

__global__ void __launch_bounds__(256, 2) k_attn_mma()
{
    __shared__ u16 sbuf[2][2][64 * KST];

    int tid = threadIdx.x;
    int w = tid >> 5, lane = tid & 31;
    int r = lane >> 2, c2 = (lane & 3) * 2;
    int b = blockIdx.y >> 3, h = blockIdx.y & 7;
    int q0 = blockIdx.x * 128;
    u32 sb = smem_u32_(&sbuf[0][0][0]);

    int srow = tid >> 2, sch = (tid & 3) * 8;
    size_t gbase = ((size_t)(b * HW) + srow) * CDIM + h * DHEAD + sch;
    u32 sdst = sb + (u32)(srow * KST + sch) * 2;

    {   // prologue: stage tile 0
        cpa16(sdst,         g_kh + gbase);
        cpa16(sdst + 5120,  g_vh + gbase);
        CP_COMMIT();
    }

    // Q fragments (fp16, pre-scaled by log2e/sqrt(32)) straight from gmem
    u32 qh[2][4];
    {
        const u16* qhg = g_qh + ((size_t)(b * HW + q0 + w * 16)) * CDIM + h * DHEAD;
        #pragma unroll
        for (int kc = 0; kc < 2; kc++)
            #pragma unroll
            for (int i = 0; i < 4; i++) {
                int rr = r + (i & 1) * 8;
                int cc = kc * 16 + c2 + (i >> 1) * 8;
                qh[kc][i] = *(const u32*)(qhg + (size_t)rr * CDIM + cc);
            }
    }

    float o[4][4];
    #pragma unroll
    for (int i = 0; i < 4; i++)
        #pragma unroll
        for (int j = 0; j < 4; j++) o[i][j] = 0.0f;
    float lsum0 = 0.0f, lsum1 = 0.0f;

    // ldmatrix lane addressing
    int vkey = lane & 15;
    int vdim = (lane >> 4) << 3;
    int klrow = ((lane >> 4) << 3) + (lane & 7);   // key within 16-key group
    int kdoff = ((lane >> 3) & 1) * 8;             // dim offset 0/8

    for (int kt = 0; kt < NT; kt++) {
        int buf = kt & 1;
        CP_WAIT0();
        __syncthreads();
        if (kt + 1 < NT) {
            size_t g1 = gbase + (size_t)(kt + 1) * 64 * CDIM;
            u32 d1 = sdst + (u32)((kt + 1) & 1) * 10240;
            cpa16(d1,         g_kh + g1);
            cpa16(d1 + 5120,  g_vh + g1);
            CP_COMMIT();
        }

        u32 kbase = sb + (u32)buf * 10240;

        // ---- S' = Q K^T (log2 domain), K-fragments via ldmatrix ----
        float s[8][4];
        #pragma unroll
        for (int i = 0; i < 8; i++)
            #pragma unroll
            for (int j = 0; j < 4; j++) s[i][j] = 0.0f;

        #pragma unroll
        for (int kc = 0; kc < 2; kc++)
            #pragma unroll
            for (int np = 0; np < 4; np++) {
                u32 kb[4];
                u32 addr = kbase +
                    (u32)(((np * 16 + klrow) * KST) + kc * 16 + kdoff) * 2;
                ldmat4(kb, addr);
                mma16816h(s[np * 2],     qh[kc], kb[0], kb[1]);
                mma16816h(s[np * 2 + 1], qh[kc], kb[2], kb[3]);
            }

        // ---- softmax: pack -> ex2.f16x2; lsum via HADD2 tile partials ----
        u32 ph[4][4];
        u32 acc0 = 0, acc1 = 0;
        #pragma unroll
        for (int j = 0; j < 8; j++) {
            int kc2 = j >> 1, hl = j & 1;
            u32 pr0 = ex2h2(hf2(s[j][0], s[j][1]));   // row r
            u32 pr1 = ex2h2(hf2(s[j][2], s[j][3]));   // row r+8
            ph[kc2][hl * 2 + 0] = pr0;
            ph[kc2][hl * 2 + 1] = pr1;
            acc0 = hadd2(acc0, pr0);
            acc1 = hadd2(acc1, pr1);
        }
        {
            float2 a0 = h22f2(acc0), a1 = h22f2(acc1);
            lsum0 += a0.x + a0.y;
            lsum1 += a1.x + a1.y;
        }

        // ---- O += P V : single pass ----
        u32 vhb = kbase + 5120;
        #pragma unroll
        for (int kc2 = 0; kc2 < 4; kc2++) {
            u32 a0 = (u32)(((kc2 * 16 + vkey) * KST) + vdim) * 2;
            u32 a1 = a0 + 32;
            u32 vh0[4], vh1[4];
            ldmat4t(vh0, vhb + a0);
            ldmat4t(vh1, vhb + a1);
            mma16816h(o[0], ph[kc2], vh0[0], vh0[1]);
            mma16816h(o[1], ph[kc2], vh0[2], vh0[3]);
            mma16816h(o[2], ph[kc2], vh1[0], vh1[1]);
            mma16816h(o[3], ph[kc2], vh1[2], vh1[3]);
        }
    }

    lsum0 += __shfl_xor_sync(0xffffffffu, lsum0, 1);
    lsum0 += __shfl_xor_sync(0xffffffffu, lsum0, 2);
    lsum1 += __shfl_xor_sync(0xffffffffu, lsum1, 1);
    lsum1 += __shfl_xor_sync(0xffffffffu, lsum1, 2);
    float inv0 = 1.0f / lsum0, inv1 = 1.0f / lsum1;

    int row0 = q0 + w * 16 + r;
    size_t o0 = ((size_t)(b * HW + row0)) * CDIM + h * DHEAD;
    size_t o1 = o0 + 8 * CDIM;
    #pragma unroll
    for (int nc2 = 0; nc2 < 4; nc2++) {
        u32 hh, ll;
        hsplit2(o[nc2][0] * inv0, o[nc2][1] * inv0, hh, ll);
        *(u32*)&g_aoh[o0 + nc2 * 8 + c2] = hh;
        *(u32*)&g_aol[o0 + nc2 * 8 + c2] = ll;
        hsplit2(o[nc2][2] * inv1, o[nc2][3] * inv1, hh, ll);
        *(u32*)&g_aoh[o1 + nc2 * 8 + c2] = hh;
        *(u32*)&g_aol[o1 + nc2 * 8 + c2] = ll;
    }
}

// ---------------------------------------------------------------------------
extern "C" void kernel_launch(void* const* d_in, const int* in_sizes, int n_in,
                              void* d_out, int out_size)
{
    const float* x  = (const float*)d_in[0];
    const float* wq = (const float*)d_in[1];
    const float* bq = (const float*)d_in[2];
    const float* wk = (const float*)d_in[3];
    const float* bk = (const float*)d_in[4];
    const float* wv = (const float*)d_in[5];
    const float* bv = (const float*)d_in[6];
    const float* wo = (const float*)d_in[7];
    const float* bo = (const float*)d_in[8];

    const int PROJ_SMEM = PSTAGE * 2 * 2;   // 92160 bytes
    cudaFuncSetAttribute(k_proj_qkv, cudaFuncAttributeMaxDynamicSharedMemorySize, PROJ_SMEM);
    cudaFuncSetAttribute(k_proj_out, cudaFuncAttributeMaxDynamicSharedMemorySize, PROJ_SMEM);

    {   // 0) weights -> fp16 once
        k_split_w<<<256, 256>>>(wq, wk, wv, wo);
    }
    {   // 1) transpose + positional encoding -> fp16 hi/lo xs
        dim3 blk(32, 8);
        dim3 grd(HW / 32, CDIM / 32, BATCH);
        k_transpose_pe<<<grd, blk>>>(x);
    }
    {   // 2) QKV projections (fp16 2-pass)
        dim3 grd(CDIM / 64, MROWS / 128, 3);
        k_proj_qkv<<<grd, 256, PROJ_SMEM>>>(bq, bk, bv);
    }
    {   // 3) flash attention (fp16, ex2.f16x2 softmax, ldmatrix K)
        dim3 grd(HW / 128, BATCH * NHEAD);
        k_attn_mma<<<grd, 256>>>();
    }
    {   // 4) output projection (fp16 2-pass) + transpose to [b,c,h,w]
        dim3 grd(CDIM / 64, MROWS / 128);
        k_proj_out<<<grd, 256, PROJ_SMEM>>>(bo, (float*)d_out);
    }
}

// round 13
// speedup vs baseline: 8.5292x; 1.0310x over previous
#include <cuda_runtime.h>
#include <cuda_bf16.h>
#include <cuda_fp16.h>
#include <math.h>
#include <stdint.h>

#define BATCH 4
#define CDIM  256
#define HW    2304          // n = 48*48
#define MROWS (BATCH*HW)    // 9216
#define NHEAD 8
#define DHEAD 32

typedef unsigned long long u64;
typedef unsigned int u32;
typedef unsigned short u16;

// Scratch (static device memory). All inter-kernel tensors fp16.
__device__ __align__(16) u16 g_xsh[MROWS*CDIM];   // xs fp16 hi
__device__ __align__(16) u16 g_xsl[MROWS*CDIM];   // xs fp16 lo (residual)
__device__ __align__(16) u16 g_qh[MROWS*CDIM];    // Q fp16 (scaled by log2e/sqrt(32))
__device__ __align__(16) u16 g_kh[MROWS*CDIM];    // K fp16
__device__ __align__(16) u16 g_vh[MROWS*CDIM];    // V fp16
__device__ __align__(16) u16 g_aoh[MROWS*CDIM];   // attn out fp16 hi
__device__ __align__(16) u16 g_aol[MROWS*CDIM];   // attn out fp16 lo
__device__ __align__(16) u16 g_wh[4*CDIM*CDIM];   // weights fp16 (single)

// ---------------------------------------------------------------------------
// helpers
// ---------------------------------------------------------------------------
__device__ __forceinline__ u32 hf2(float x0, float x1) {
    u32 r; asm("cvt.rn.f16x2.f32 %0, %1, %2;" : "=r"(r) : "f"(x1), "f"(x0));
    return r;
}
__device__ __forceinline__ void hsplit2(float x0, float x1, u32& h, u32& l) {
    __half h0 = __float2half_rn(x0), h1 = __float2half_rn(x1);
    float f0 = __half2float(h0), f1 = __half2float(h1);
    __half l0 = __float2half_rn(x0 - f0), l1 = __float2half_rn(x1 - f1);
    h = ((u32)(*(u16*)&h1) << 16) | (u32)(*(u16*)&h0);
    l = ((u32)(*(u16*)&l1) << 16) | (u32)(*(u16*)&l0);
}
__device__ __forceinline__ void hsplit1(float x, u16& h, u16& l) {
    __half hb = __float2half_rn(x);
    float hf = __half2float(hb);
    __half lb = __float2half_rn(x - hf);
    h = *(u16*)&hb; l = *(u16*)&lb;
}
__device__ __forceinline__ u32 ex2h2(u32 v) {
    u32 r; asm("ex2.approx.f16x2 %0, %1;" : "=r"(r) : "r"(v));
    return r;
}
__device__ __forceinline__ u32 hadd2(u32 a, u32 b) {
    u32 r; asm("add.rn.f16x2 %0, %1, %2;" : "=r"(r) : "r"(a), "r"(b));
    return r;
}
__device__ __forceinline__ float2 h22f2(u32 v) {
    __half2 h = *(__half2*)&v;
    return __half22float2(h);
}
__device__ __forceinline__ void mma16816h(float d[4], const u32 a[4], u32 b0, u32 b1) {
    asm volatile("mma.sync.aligned.m16n8k16.row.col.f32.f16.f16.f32 "
        "{%0,%1,%2,%3}, {%4,%5,%6,%7}, {%8,%9}, {%0,%1,%2,%3};"
        : "+f"(d[0]), "+f"(d[1]), "+f"(d[2]), "+f"(d[3])
        : "r"(a[0]), "r"(a[1]), "r"(a[2]), "r"(a[3]), "r"(b0), "r"(b1));
}
__device__ __forceinline__ u32 smem_u32_(const void* p) {
    u32 a; asm("{ .reg .u64 t; cvta.to.shared.u64 t, %1; cvt.u32.u64 %0, t; }"
               : "=r"(a) : "l"(p)); return a;
}
__device__ __forceinline__ void cpa16(u32 dst, const void* src) {
    asm volatile("cp.async.cg.shared.global [%0], [%1], 16;"
                 :: "r"(dst), "l"(src) : "memory");
}
#define CP_COMMIT() asm volatile("cp.async.commit_group;" ::: "memory")
#define CP_WAIT0()  asm volatile("cp.async.wait_group 0;" ::: "memory")
__device__ __forceinline__ void ldmat4(u32 r[4], u32 addr) {
    asm volatile("ldmatrix.sync.aligned.m8n8.x4.shared.b16 {%0,%1,%2,%3}, [%4];"
        : "=r"(r[0]), "=r"(r[1]), "=r"(r[2]), "=r"(r[3]) : "r"(addr));
}
__device__ __forceinline__ void ldmat4t(u32 r[4], u32 addr) {
    asm volatile("ldmatrix.sync.aligned.m8n8.x4.trans.shared.b16 {%0,%1,%2,%3}, [%4];"
        : "=r"(r[0]), "=r"(r[1]), "=r"(r[2]), "=r"(r[3]) : "r"(addr));
}

// ---------------------------------------------------------------------------
// Kernel 0: convert weight matrices to fp16 once (4 x 256x256)
// ---------------------------------------------------------------------------
__global__ void k_split_w(const float* __restrict__ wq, const float* __restrict__ wk,
                          const float* __restrict__ wv, const float* __restrict__ wo)
{
    int idx = blockIdx.x * 256 + threadIdx.x;
    const float* ws[4] = { wq, wk, wv, wo };
    #pragma unroll
    for (int m = 0; m < 4; m++) {
        __half h = __float2half_rn(ws[m][idx]);
        g_wh[m * 65536 + idx] = *(u16*)&h;
    }
}

// ---------------------------------------------------------------------------
// Kernel 1: x [b,c,h,w] -> xs fp16 hi/lo [b,n,c] transpose + positional enc
// ---------------------------------------------------------------------------
__global__ void k_transpose_pe(const float* __restrict__ x)
{
    __shared__ float tile[32][33];
    int b  = blockIdx.z;
    int p0 = blockIdx.x * 32;
    int c0 = blockIdx.y * 32;
    int tx = threadIdx.x, ty = threadIdx.y;

    #pragma unroll
    for (int i = 0; i < 4; i++) {
        int cc = c0 + ty + i * 8;
        tile[ty + i * 8][tx] = x[((size_t)(b * CDIM + cc)) * HW + p0 + tx];
    }
    __syncthreads();
    #pragma unroll
    for (int i = 0; i < 4; i++) {
        int p  = p0 + ty + i * 8;
        int cc = c0 + tx;
        float v = tile[tx][ty + i * 8];
        float pe = 0.0f;
        if (p != 0) {
            float ang = (float)p * powf(10000.0f, -2.0f * (float)cc / 256.0f);
            pe = (cc & 1) ? cosf(ang) : sinf(ang);
        }
        float val = v + pe;
        u16 h, l; hsplit1(val, h, l);
        size_t idx = ((size_t)(b * HW + p)) * CDIM + cc;
        g_xsh[idx] = h;
        g_xsl[idx] = l;
    }
}

// ---------------------------------------------------------------------------
// Projection GEMM (fp16 2-pass: A hi/lo exact, W single): out = A @ W^T + bias
// ---------------------------------------------------------------------------
#define PST   72
#define SA_H  0
#define SA_L  9216
#define SW    18432
#define PSTAGE 23040          // u16 per stage (46080 B); x2 = 92160 B

__device__ __forceinline__ void proj_stage(
    u32 sbase, int buf, int m0, int n0, int k0, int tid,
    const u16* __restrict__ Agh, const u16* __restrict__ Agl,
    const u16* __restrict__ Wg)
{
    u32 b0 = sbase + (u32)buf * (PSTAGE * 2);
    #pragma unroll
    for (int it = 0; it < 4; it++) {
        int idx = tid + it * 256;
        int row = idx >> 3, c8 = (idx & 7) * 8;
        size_t gs = (size_t)(m0 + row) * CDIM + k0 + c8;
        u32 doff = (u32)(row * PST + c8) * 2;
        cpa16(b0 + SA_H * 2 + doff, Agh + gs);
        cpa16(b0 + SA_L * 2 + doff, Agl + gs);
    }
    #pragma unroll
    for (int it = 0; it < 2; it++) {
        int idx = tid + it * 256;
        int row = idx >> 3, c8 = (idx & 7) * 8;
        size_t gs = (size_t)(n0 + row) * CDIM + k0 + c8;
        u32 doff = (u32)(row * PST + c8) * 2;
        cpa16(b0 + SW * 2 + doff, Wg + gs);
    }
}

// OUT_MODE: 0 = fp16 single (QKV), 1 = fp32 transposed (final out)
template<int OUT_MODE>
__device__ __forceinline__ void proj_body(
    const u16* __restrict__ Agh, const u16* __restrict__ Agl,
    int widx, const float* __restrict__ bias,
    u16* __restrict__ outh, float* __restrict__ outf, float qs)
{
    extern __shared__ u16 smp[];
    int tid = threadIdx.x;
    int w = tid >> 5, lane = tid & 31;
    int r = lane >> 2, c2 = (lane & 3) * 2;
    int m0 = blockIdx.y * 128, n0 = blockIdx.x * 64;
    u32 sbase = smem_u32_(smp);
    const u16* Wg = g_wh + widx * 65536;

    float o[8][4];
    #pragma unroll
    for (int i = 0; i < 8; i++)
        #pragma unroll
        for (int j = 0; j < 4; j++) o[i][j] = 0.0f;

    proj_stage(sbase, 0, m0, n0, 0, tid, Agh, Agl, Wg);
    CP_COMMIT();

    u32 arow = (u32)(w * 16 + (lane & 15));
    u32 acol = (u32)((lane >> 4) << 3);

    for (int c = 0; c < 4; c++) {
        CP_WAIT0();
        __syncthreads();
        if (c < 3) {
            proj_stage(sbase, (c + 1) & 1, m0, n0, (c + 1) * 64, tid, Agh, Agl, Wg);
            CP_COMMIT();
        }

        int sb = (c & 1) * PSTAGE;
        const u16* sW = smp + sb + SW;
        u32 abase = sbase + (u32)sb * 2 + (arow * PST + acol) * 2;

        #pragma unroll
        for (int kc = 0; kc < 4; kc++) {
            u32 ah[4], al[4];
            u32 aoff = abase + (u32)(kc * 16) * 2;
            ldmat4(ah, aoff + SA_H * 2);
            ldmat4(al, aoff + SA_L * 2);
            #pragma unroll
            for (int nc = 0; nc < 8; nc++) {
                int off = (nc * 8 + r) * PST + kc * 16 + c2;
                u32 b0 = *(const u32*)&sW[off];
                u32 b1 = *(const u32*)&sW[off + 8];
                mma16816h(o[nc], ah, b0, b1);
                mma16816h(o[nc], al, b0, b1);
            }
        }
    }

    int mr0 = m0 + w * 16 + r;
    int mr1 = mr0 + 8;
    if (OUT_MODE == 0) {
        size_t r0off = (size_t)mr0 * CDIM + n0;
        size_t r1off = (size_t)mr1 * CDIM + n0;
        #pragma unroll
        for (int nc = 0; nc < 8; nc++) {
            float2 bi = *(const float2*)(bias + n0 + nc * 8 + c2);
            *(u32*)&outh[r0off + nc * 8 + c2] =
                hf2((o[nc][0] + bi.x) * qs, (o[nc][1] + bi.y) * qs);
            *(u32*)&outh[r1off + nc * 8 + c2] =
                hf2((o[nc][2] + bi.x) * qs, (o[nc][3] + bi.y) * qs);
        }
    } else {
        int bb0 = mr0 / HW, pp0 = mr0 % HW;
        int bb1 = mr1 / HW, pp1 = mr1 % HW;
        #pragma unroll
        for (int nc = 0; nc < 8; nc++) {
            float2 bi = *(const float2*)(bias + n0 + nc * 8 + c2);
            int nn = n0 + nc * 8 + c2;
            outf[((size_t)(bb0 * CDIM + nn)) * HW + pp0]     = o[nc][0] + bi.x;
            outf[((size_t)(bb0 * CDIM + nn + 1)) * HW + pp0] = o[nc][1] + bi.y;
            outf[((size_t)(bb1 * CDIM + nn)) * HW + pp1]     = o[nc][2] + bi.x;
            outf[((size_t)(bb1 * CDIM + nn + 1)) * HW + pp1] = o[nc][3] + bi.y;
        }
    }
}

// Q scale folds softmax's log2(e): (1/sqrt(32)) * log2(e)
#define QSCALE 0.25503472316688193f

__global__ void __launch_bounds__(256) k_proj_qkv(
    const float* __restrict__ bq, const float* __restrict__ bk,
    const float* __restrict__ bv)
{
    const float* bias; u16* outh; float qs;
    if (blockIdx.z == 0)      { bias = bq; outh = g_qh; qs = QSCALE; }
    else if (blockIdx.z == 1) { bias = bk; outh = g_kh; qs = 1.0f; }
    else                      { bias = bv; outh = g_vh; qs = 1.0f; }
    proj_body<0>(g_xsh, g_xsl, blockIdx.z, bias, outh, nullptr, qs);
}

__global__ void __launch_bounds__(256) k_proj_out(
    const float* __restrict__ bo, float* __restrict__ out)
{
    proj_body<1>(g_aoh, g_aol, 3, bo, nullptr, out, 1.0f);
}

// ---------------------------------------------------------------------------
// Kernel 3: flash attention. Block = 128 thr = 4 warps; warp owns 32 queries
// (two 16-row A-fragments) so each K/V B-fragment feeds 4 MMAs (2x reuse).
// 4 CTAs/SM; smem [buf][K,V][64 x 40 halves]; buffer = 10240 B.
// ---------------------------------------------------------------------------
#define KST 40
#define NT  (HW / 64)

__global__ void __launch_bounds__(128, 4) k_attn_mma()
{
    __shared__ u16 sbuf[2][2][64 * KST];

    int tid = threadIdx.x;
    int w = tid >> 5, lane = tid & 31;
    int r = lane >> 2, c2 = (lane & 3) * 2;
    int b = blockIdx.y >> 3, h = blockIdx.y & 7;
    int q0 = blockIdx.x * 128;
    u32 sb = smem_u32_(&sbuf[0][0][0]);

    // staging: 128 threads x 2 chunks per array (rows row0 and row0+32)
    int srow = tid >> 2, sch = (tid & 3) * 8;
    size_t gb0 = ((size_t)(b * HW) + srow) * CDIM + h * DHEAD + sch;
    size_t gb1 = gb0 + (size_t)32 * CDIM;
    u32 sd0 = sb + (u32)(srow * KST + sch) * 2;
    u32 sd1 = sd0 + 32 * KST * 2;

    {   // prologue: stage tile 0
        cpa16(sd0,         g_kh + gb0);
        cpa16(sd0 + 5120,  g_vh + gb0);
        cpa16(sd1,         g_kh + gb1);
        cpa16(sd1 + 5120,  g_vh + gb1);
        CP_COMMIT();
    }

    // Q fragments: two 16-row blocks per warp
    u32 qh[2][2][4];
    #pragma unroll
    for (int qb = 0; qb < 2; qb++) {
        const u16* qhg = g_qh
            + ((size_t)(b * HW + q0 + w * 32 + qb * 16)) * CDIM + h * DHEAD;
        #pragma unroll
        for (int kc = 0; kc < 2; kc++)
            #pragma unroll
            for (int i = 0; i < 4; i++) {
                int rr = r + (i & 1) * 8;
                int cc = kc * 16 + c2 + (i >> 1) * 8;
                qh[qb][kc][i] = *(const u32*)(qhg + (size_t)rr * CDIM + cc);
            }
    }

    float o[2][4][4];
    #pragma unroll
    for (int qb = 0; qb < 2; qb++)
        #pragma unroll
        for (int i = 0; i < 4; i++)
            #pragma unroll
            for (int j = 0; j < 4; j++) o[qb][i][j] = 0.0f;
    float lsum[2][2] = {{0.0f, 0.0f}, {0.0f, 0.0f}};

    // ldmatrix lane addressing
    int vkey = lane & 15;
    int vdim = (lane >> 4) << 3;
    int klrow = ((lane >> 4) << 3) + (lane & 7);
    int kdoff = ((lane >> 3) & 1) * 8;

    for (int kt = 0; kt < NT; kt++) {
        int buf = kt & 1;
        CP_WAIT0();
        __syncthreads();
        if (kt + 1 < NT) {
            size_t off = (size_t)(kt + 1) * 64 * CDIM;
            u32 d0 = sd0 + (u32)((kt + 1) & 1) * 10240;
            u32 d1 = sd1 + (u32)((kt + 1) & 1) * 10240;
            cpa16(d0,         g_kh + gb0 + off);
            cpa16(d0 + 5120,  g_vh + gb0 + off);
            cpa16(d1,         g_kh + gb1 + off);
            cpa16(d1 + 5120,  g_vh + gb1 + off);
            CP_COMMIT();
        }

        u32 kbase = sb + (u32)buf * 10240;
        u32 ph[2][4][4];

        // ---- S + softmax, processed in two 32-key halves (reg pressure) ----
        #pragma unroll
        for (int ha = 0; ha < 2; ha++) {
            float s[2][4][4];
            #pragma unroll
            for (int qb = 0; qb < 2; qb++)
                #pragma unroll
                for (int i = 0; i < 4; i++)
                    #pragma unroll
                    for (int j = 0; j < 4; j++) s[qb][i][j] = 0.0f;

            #pragma unroll
            for (int kc = 0; kc < 2; kc++)
                #pragma unroll
                for (int npl = 0; npl < 2; npl++) {
                    int np = ha * 2 + npl;
                    u32 kb[4];
                    u32 addr = kbase +
                        (u32)(((np * 16 + klrow) * KST) + kc * 16 + kdoff) * 2;
                    ldmat4(kb, addr);
                    mma16816h(s[0][npl * 2],     qh[0][kc], kb[0], kb[1]);
                    mma16816h(s[0][npl * 2 + 1], qh[0][kc], kb[2], kb[3]);
                    mma16816h(s[1][npl * 2],     qh[1][kc], kb[0], kb[1]);
                    mma16816h(s[1][npl * 2 + 1], qh[1][kc], kb[2], kb[3]);
                }

            #pragma unroll
            for (int qb = 0; qb < 2; qb++) {
                u32 acc0 = 0, acc1 = 0;
                #pragma unroll
                for (int j = 0; j < 4; j++) {
                    int kc2 = ha * 2 + (j >> 1);
                    int hl = j & 1;
                    u32 pr0 = ex2h2(hf2(s[qb][j][0], s[qb][j][1]));
                    u32 pr1 = ex2h2(hf2(s[qb][j][2], s[qb][j][3]));
                    ph[qb][kc2][hl * 2 + 0] = pr0;
                    ph[qb][kc2][hl * 2 + 1] = pr1;
                    acc0 = hadd2(acc0, pr0);
                    acc1 = hadd2(acc1, pr1);
                }
                float2 a0 = h22f2(acc0), a1 = h22f2(acc1);
                lsum[qb][0] += a0.x + a0.y;
                lsum[qb][1] += a1.x + a1.y;
            }
        }

        // ---- O += P V : V fragments shared across both q-blocks ----
        u32 vhb = kbase + 5120;
        #pragma unroll
        for (int kc2 = 0; kc2 < 4; kc2++) {
            u32 a0 = (u32)(((kc2 * 16 + vkey) * KST) + vdim) * 2;
            u32 a1 = a0 + 32;
            u32 vh0[4], vh1[4];
            ldmat4t(vh0, vhb + a0);
            ldmat4t(vh1, vhb + a1);
            mma16816h(o[0][0], ph[0][kc2], vh0[0], vh0[1]);
            mma16816h(o[0][1], ph[0][kc2], vh0[2], vh0[3]);
            mma16816h(o[0][2], ph[0][kc2], vh1[0], vh1[1]);
            mma16816h(o[0][3], ph[0][kc2], vh1[2], vh1[3]);
            mma16816h(o[1][0], ph[1][kc2], vh0[0], vh0[1]);
            mma16816h(o[1][1], ph[1][kc2], vh0[2], vh0[3]);
            mma16816h(o[1][2], ph[1][kc2], vh1[0], vh1[1]);
            mma16816h(o[1][3], ph[1][kc2], vh1[2], vh1[3]);
        }
    }

    // ---- epilogue ----
    #pragma unroll
    for (int qb = 0; qb < 2; qb++) {
        float l0 = lsum[qb][0], l1 = lsum[qb][1];
        l0 += __shfl_xor_sync(0xffffffffu, l0, 1);
        l0 += __shfl_xor_sync(0xffffffffu, l0, 2);
        l1 += __shfl_xor_sync(0xffffffffu, l1, 1);
        l1 += __shfl_xor_sync(0xffffffffu, l1, 2);
        float inv0 = 1.0f / l0, inv1 = 1.0f / l1;

        int row0 = q0 + w * 32 + qb * 16 + r;
        size_t o0 = ((size_t)(b * HW + row0)) * CDIM + h * DHEAD;
        size_t o1 = o0 + 8 * CDIM;
        #pragma unroll
        for (int nc2 = 0; nc2 < 4; nc2++) {
            u32 hh, ll;
            hsplit2(o[qb][nc2][0] * inv0, o[qb][nc2][1] * inv0, hh, ll);
            *(u32*)&g_aoh[o0 + nc2 * 8 + c2] = hh;
            *(u32*)&g_aol[o0 + nc2 * 8 + c2] = ll;
            hsplit2(o[qb][nc2][2] * inv1, o[qb][nc2][3] * inv1, hh, ll);
            *(u32*)&g_aoh[o1 + nc2 * 8 + c2] = hh;
            *(u32*)&g_aol[o1 + nc2 * 8 + c2] = ll;
        }
    }
}

// ---------------------------------------------------------------------------
extern "C" void kernel_launch(void* const* d_in, const int* in_sizes, int n_in,
                              void* d_out, int out_size)
{
    const float* x  = (const float*)d_in[0];
    const float* wq = (const float*)d_in[1];
    const float* bq = (const float*)d_in[2];
    const float* wk = (const float*)d_in[3];
    const float* bk = (const float*)d_in[4];
    const float* wv = (const float*)d_in[5];
    const float* bv = (const float*)d_in[6];
    const float* wo = (const float*)d_in[7];
    const float* bo = (const float*)d_in[8];

    const int PROJ_SMEM = PSTAGE * 2 * 2;   // 92160 bytes
    cudaFuncSetAttribute(k_proj_qkv, cudaFuncAttributeMaxDynamicSharedMemorySize, PROJ_SMEM);
    cudaFuncSetAttribute(k_proj_out, cudaFuncAttributeMaxDynamicSharedMemorySize, PROJ_SMEM);

    {   // 0) weights -> fp16 once
        k_split_w<<<256, 256>>>(wq, wk, wv, wo);
    }
    {   // 1) transpose + positional encoding -> fp16 hi/lo xs
        dim3 blk(32, 8);
        dim3 grd(HW / 32, CDIM / 32, BATCH);
        k_transpose_pe<<<grd, blk>>>(x);
    }
    {   // 2) QKV projections (fp16 2-pass)
        dim3 grd(CDIM / 64, MROWS / 128, 3);
        k_proj_qkv<<<grd, 256, PROJ_SMEM>>>(bq, bk, bv);
    }
    {   // 3) flash attention (4 warps, 32q/warp, 2x B-frag reuse)
        dim3 grd(HW / 128, BATCH * NHEAD);
        k_attn_mma<<<grd, 128>>>();
    }
    {   // 4) output projection (fp16 2-pass) + transpose to [b,c,h,w]
        dim3 grd(CDIM / 64, MROWS / 128);
        k_proj_out<<<grd, 256, PROJ_SMEM>>>(bo, (float*)d_out);
    }
}

// round 14
// speedup vs baseline: 8.8042x; 1.0322x over previous
#include <cuda_runtime.h>
#include <cuda_bf16.h>
#include <cuda_fp16.h>
#include <math.h>
#include <stdint.h>

#define BATCH 4
#define CDIM  256
#define HW    2304          // n = 48*48
#define MROWS (BATCH*HW)    // 9216
#define NHEAD 8
#define DHEAD 32

typedef unsigned long long u64;
typedef unsigned int u32;
typedef unsigned short u16;

// Scratch (static device memory). All inter-kernel tensors fp16.
__device__ __align__(16) u16 g_xsh[MROWS*CDIM];   // xs fp16 hi
__device__ __align__(16) u16 g_xsl[MROWS*CDIM];   // xs fp16 lo (residual)
__device__ __align__(16) u16 g_qh[MROWS*CDIM];    // Q fp16 (scaled by log2e/sqrt(32))
__device__ __align__(16) u16 g_kh[MROWS*CDIM];    // K fp16
__device__ __align__(16) u16 g_vh[MROWS*CDIM];    // V fp16
__device__ __align__(16) u16 g_aoh[MROWS*CDIM];   // attn out fp16 hi
__device__ __align__(16) u16 g_aol[MROWS*CDIM];   // attn out fp16 lo
__device__ __align__(16) u16 g_wh[4*CDIM*CDIM];   // weights fp16 (single)

// ---------------------------------------------------------------------------
// helpers
// ---------------------------------------------------------------------------
__device__ __forceinline__ u32 hf2(float x0, float x1) {
    u32 r; asm("cvt.rn.f16x2.f32 %0, %1, %2;" : "=r"(r) : "f"(x1), "f"(x0));
    return r;
}
__device__ __forceinline__ void hsplit2(float x0, float x1, u32& h, u32& l) {
    __half h0 = __float2half_rn(x0), h1 = __float2half_rn(x1);
    float f0 = __half2float(h0), f1 = __half2float(h1);
    __half l0 = __float2half_rn(x0 - f0), l1 = __float2half_rn(x1 - f1);
    h = ((u32)(*(u16*)&h1) << 16) | (u32)(*(u16*)&h0);
    l = ((u32)(*(u16*)&l1) << 16) | (u32)(*(u16*)&l0);
}
__device__ __forceinline__ void hsplit1(float x, u16& h, u16& l) {
    __half hb = __float2half_rn(x);
    float hf = __half2float(hb);
    __half lb = __float2half_rn(x - hf);
    h = *(u16*)&hb; l = *(u16*)&lb;
}
__device__ __forceinline__ u32 ex2h2(u32 v) {
    u32 r; asm("ex2.approx.f16x2 %0, %1;" : "=r"(r) : "r"(v));
    return r;
}
__device__ __forceinline__ u32 hadd2(u32 a, u32 b) {
    u32 r; asm("add.rn.f16x2 %0, %1, %2;" : "=r"(r) : "r"(a), "r"(b));
    return r;
}
__device__ __forceinline__ float2 h22f2(u32 v) {
    __half2 h = *(__half2*)&v;
    return __half22float2(h);
}
__device__ __forceinline__ void mma16816h(float d[4], const u32 a[4], u32 b0, u32 b1) {
    asm volatile("mma.sync.aligned.m16n8k16.row.col.f32.f16.f16.f32 "
        "{%0,%1,%2,%3}, {%4,%5,%6,%7}, {%8,%9}, {%0,%1,%2,%3};"
        : "+f"(d[0]), "+f"(d[1]), "+f"(d[2]), "+f"(d[3])
        : "r"(a[0]), "r"(a[1]), "r"(a[2]), "r"(a[3]), "r"(b0), "r"(b1));
}
// fp16-accumulator MMA: D (2x u32 = 4 halves) += A*B
__device__ __forceinline__ void mma16816hh(u32* d, const u32 a[4], u32 b0, u32 b1) {
    asm volatile("mma.sync.aligned.m16n8k16.row.col.f16.f16.f16.f16 "
        "{%0,%1}, {%2,%3,%4,%5}, {%6,%7}, {%0,%1};"
        : "+r"(d[0]), "+r"(d[1])
        : "r"(a[0]), "r"(a[1]), "r"(a[2]), "r"(a[3]), "r"(b0), "r"(b1));
}
__device__ __forceinline__ u32 smem_u32_(const void* p) {
    u32 a; asm("{ .reg .u64 t; cvta.to.shared.u64 t, %1; cvt.u32.u64 %0, t; }"
               : "=r"(a) : "l"(p)); return a;
}
__device__ __forceinline__ void cpa16(u32 dst, const void* src) {
    asm volatile("cp.async.cg.shared.global [%0], [%1], 16;"
                 :: "r"(dst), "l"(src) : "memory");
}
#define CP_COMMIT() asm volatile("cp.async.commit_group;" ::: "memory")
#define CP_WAIT0()  asm volatile("cp.async.wait_group 0;" ::: "memory")
__device__ __forceinline__ void ldmat4(u32 r[4], u32 addr) {
    asm volatile("ldmatrix.sync.aligned.m8n8.x4.shared.b16 {%0,%1,%2,%3}, [%4];"
        : "=r"(r[0]), "=r"(r[1]), "=r"(r[2]), "=r"(r[3]) : "r"(addr));
}
__device__ __forceinline__ void ldmat4t(u32 r[4], u32 addr) {
    asm volatile("ldmatrix.sync.aligned.m8n8.x4.trans.shared.b16 {%0,%1,%2,%3}, [%4];"
        : "=r"(r[0]), "=r"(r[1]), "=r"(r[2]), "=r"(r[3]) : "r"(addr));
}

// ---------------------------------------------------------------------------
// Kernel 0: convert weight matrices to fp16 once (4 x 256x256)
// ---------------------------------------------------------------------------
__global__ void k_split_w(const float* __restrict__ wq, const float* __restrict__ wk,
                          const float* __restrict__ wv, const float* __restrict__ wo)
{
    int idx = blockIdx.x * 256 + threadIdx.x;
    const float* ws[4] = { wq, wk, wv, wo };
    #pragma unroll
    for (int m = 0; m < 4; m++) {
        __half h = __float2half_rn(ws[m][idx]);
        g_wh[m * 65536 + idx] = *(u16*)&h;
    }
}

// ---------------------------------------------------------------------------
// Kernel 1: x [b,c,h,w] -> xs fp16 hi/lo [b,n,c] transpose + positional enc
// ---------------------------------------------------------------------------
__global__ void k_transpose_pe(const float* __restrict__ x)
{
    __shared__ float tile[32][33];
    int b  = blockIdx.z;
    int p0 = blockIdx.x * 32;
    int c0 = blockIdx.y * 32;
    int tx = threadIdx.x, ty = threadIdx.y;

    #pragma unroll
    for (int i = 0; i < 4; i++) {
        int cc = c0 + ty + i * 8;
        tile[ty + i * 8][tx] = x[((size_t)(b * CDIM + cc)) * HW + p0 + tx];
    }
    __syncthreads();
    #pragma unroll
    for (int i = 0; i < 4; i++) {
        int p  = p0 + ty + i * 8;
        int cc = c0 + tx;
        float v = tile[tx][ty + i * 8];
        float pe = 0.0f;
        if (p != 0) {
            float ang = (float)p * powf(10000.0f, -2.0f * (float)cc / 256.0f);
            pe = (cc & 1) ? cosf(ang) : sinf(ang);
        }
        float val = v + pe;
        u16 h, l; hsplit1(val, h, l);
        size_t idx = ((size_t)(b * HW + p)) * CDIM + cc;
        g_xsh[idx] = h;
        g_xsl[idx] = l;
    }
}

// ---------------------------------------------------------------------------
// Projection GEMM (fp16 2-pass: A hi/lo exact, W single): out = A @ W^T + bias
// ---------------------------------------------------------------------------
#define PST   72
#define SA_H  0
#define SA_L  9216
#define SW    18432
#define PSTAGE 23040          // u16 per stage (46080 B); x2 = 92160 B

__device__ __forceinline__ void proj_stage(
    u32 sbase, int buf, int m0, int n0, int k0, int tid,
    const u16* __restrict__ Agh, const u16* __restrict__ Agl,
    const u16* __restrict__ Wg)
{
    u32 b0 = sbase + (u32)buf * (PSTAGE * 2);
    #pragma unroll
    for (int it = 0; it < 4; it++) {
        int idx = tid + it * 256;
        int row = idx >> 3, c8 = (idx & 7) * 8;
        size_t gs = (size_t)(m0 + row) * CDIM + k0 + c8;
        u32 doff = (u32)(row * PST + c8) * 2;
        cpa16(b0 + SA_H * 2 + doff, Agh + gs);
        cpa16(b0 + SA_L * 2 + doff, Agl + gs);
    }
    #pragma unroll
    for (int it = 0; it < 2; it++) {
        int idx = tid + it * 256;
        int row = idx >> 3, c8 = (idx & 7) * 8;
        size_t gs = (size_t)(n0 + row) * CDIM + k0 + c8;
        u32 doff = (u32)(row * PST + c8) * 2;
        cpa16(b0 + SW * 2 + doff, Wg + gs);
    }
}

// OUT_MODE: 0 = fp16 single (QKV), 1 = fp32 transposed (final out)
template<int OUT_MODE>
__device__ __forceinline__ void proj_body(
    const u16* __restrict__ Agh, const u16* __restrict__ Agl,
    int widx, const float* __restrict__ bias,
    u16* __restrict__ outh, float* __restrict__ outf, float qs)
{
    extern __shared__ u16 smp[];
    int tid = threadIdx.x;
    int w = tid >> 5, lane = tid & 31;
    int r = lane >> 2, c2 = (lane & 3) * 2;
    int m0 = blockIdx.y * 128, n0 = blockIdx.x * 64;
    u32 sbase = smem_u32_(smp);
    const u16* Wg = g_wh + widx * 65536;

    float o[8][4];
    #pragma unroll
    for (int i = 0; i < 8; i++)
        #pragma unroll
        for (int j = 0; j < 4; j++) o[i][j] = 0.0f;

    proj_stage(sbase, 0, m0, n0, 0, tid, Agh, Agl, Wg);
    CP_COMMIT();

    u32 arow = (u32)(w * 16 + (lane & 15));
    u32 acol = (u32)((lane >> 4) << 3);

    for (int c = 0; c < 4; c++) {
        CP_WAIT0();
        __syncthreads();
        if (c < 3) {
            proj_stage(sbase, (c + 1) & 1, m0, n0, (c + 1) * 64, tid, Agh, Agl, Wg);
            CP_COMMIT();
        }

        int sb = (c & 1) * PSTAGE;
        const u16* sW = smp + sb + SW;
        u32 abase = sbase + (u32)sb * 2 + (arow * PST + acol) * 2;

        #pragma unroll
        for (int kc = 0; kc < 4; kc++) {
            u32 ah[4], al[4];
            u32 aoff = abase + (u32)(kc * 16) * 2;
            ldmat4(ah, aoff + SA_H * 2);
            ldmat4(al, aoff + SA_L * 2);
            #pragma unroll
            for (int nc = 0; nc < 8; nc++) {
                int off = (nc * 8 + r) * PST + kc * 16 + c2;
                u32 b0 = *(const u32*)&sW[off];
                u32 b1 = *(const u32*)&sW[off + 8];
                mma16816h(o[nc], ah, b0, b1);
                mma16816h(o[nc], al, b0, b1);
            }
        }
    }

    int mr0 = m0 + w * 16 + r;
    int mr1 = mr0 + 8;
    if (OUT_MODE == 0) {
        size_t r0off = (size_t)mr0 * CDIM + n0;
        size_t r1off = (size_t)mr1 * CDIM + n0;
        #pragma unroll
        for (int nc = 0; nc < 8; nc++) {
            float2 bi = *(const float2*)(bias + n0 + nc * 8 + c2);
            *(u32*)&outh[r0off + nc * 8 + c2] =
                hf2((o[nc][0] + bi.x) * qs, (o[nc][1] + bi.y) * qs);
            *(u32*)&outh[r1off + nc * 8 + c2] =
                hf2((o[nc][2] + bi.x) * qs, (o[nc][3] + bi.y) * qs);
        }
    } else {
        int bb0 = mr0 / HW, pp0 = mr0 % HW;
        int bb1 = mr1 / HW, pp1 = mr1 % HW;
        #pragma unroll
        for (int nc = 0; nc < 8; nc++) {
            float2 bi = *(const float2*)(bias + n0 + nc * 8 + c2);
            int nn = n0 + nc * 8 + c2;
            outf[((size_t)(bb0 * CDIM + nn)) * HW + pp0]     = o[nc][0] + bi.x;
            outf[((size_t)(bb0 * CDIM + nn + 1)) * HW + pp0] = o[nc][1] + bi.y;
            outf[((size_t)(bb1 * CDIM + nn)) * HW + pp1]     = o[nc][2] + bi.x;
            outf[((size_t)(bb1 * CDIM + nn + 1)) * HW + pp1] = o[nc][3] + bi.y;
        }
    }
}

// Q scale folds softmax's log2(e): (1/sqrt(32)) * log2(e)
#define QSCALE 0.25503472316688193f

__global__ void __launch_bounds__(256) k_proj_qkv(
    const float* __restrict__ bq, const float* __restrict__ bk,
    const float* __restrict__ bv)
{
    const float* bias; u16* outh; float qs;
    if (blockIdx.z == 0)      { bias = bq; outh = g_qh; qs = QSCALE; }
    else if (blockIdx.z == 1) { bias = bk; outh = g_kh; qs = 1.0f; }
    else                      { bias = bv; outh = g_vh; qs = 1.0f; }
    proj_body<0>(g_xsh, g_xsl, blockIdx.z, bias, outh, nullptr, qs);
}

__global__ void __launch_bounds__(256) k_proj_out(
    const float* __restrict__ bo, float* __restrict__ out)
{
    proj_body<1>(g_aoh, g_aol, 3, bo, nullptr, out, 1.0f);
}

// ---------------------------------------------------------------------------
// Kernel 3: flash attention. Block = 128 thr = 4 warps; warp owns 32 queries.
// S-GEMM uses fp16 accumulators: MMA output IS the packed P fragment (ex2 in
// place, no cvt, no fp32 s regs). PV keeps fp32 accumulators.
// ---------------------------------------------------------------------------
#define KST 40
#define NT  (HW / 64)

__global__ void __launch_bounds__(128, 4) k_attn_mma()
{
    __shared__ u16 sbuf[2][2][64 * KST];

    int tid = threadIdx.x;
    int w = tid >> 5, lane = tid & 31;
    int r = lane >> 2, c2 = (lane & 3) * 2;
    int b = blockIdx.y >> 3, h = blockIdx.y & 7;
    int q0 = blockIdx.x * 128;
    u32 sb = smem_u32_(&sbuf[0][0][0]);

    // staging: 128 threads x 2 chunks per array (rows row0 and row0+32)
    int srow = tid >> 2, sch = (tid & 3) * 8;
    size_t gb0 = ((size_t)(b * HW) + srow) * CDIM + h * DHEAD + sch;
    size_t gb1 = gb0 + (size_t)32 * CDIM;
    u32 sd0 = sb + (u32)(srow * KST + sch) * 2;
    u32 sd1 = sd0 + 32 * KST * 2;

    {   // prologue: stage tile 0
        cpa16(sd0,         g_kh + gb0);
        cpa16(sd0 + 5120,  g_vh + gb0);
        cpa16(sd1,         g_kh + gb1);
        cpa16(sd1 + 5120,  g_vh + gb1);
        CP_COMMIT();
    }

    // Q fragments: two 16-row blocks per warp
    u32 qh[2][2][4];
    #pragma unroll
    for (int qb = 0; qb < 2; qb++) {
        const u16* qhg = g_qh
            + ((size_t)(b * HW + q0 + w * 32 + qb * 16)) * CDIM + h * DHEAD;
        #pragma unroll
        for (int kc = 0; kc < 2; kc++)
            #pragma unroll
            for (int i = 0; i < 4; i++) {
                int rr = r + (i & 1) * 8;
                int cc = kc * 16 + c2 + (i >> 1) * 8;
                qh[qb][kc][i] = *(const u32*)(qhg + (size_t)rr * CDIM + cc);
            }
    }

    float o[2][4][4];
    #pragma unroll
    for (int qb = 0; qb < 2; qb++)
        #pragma unroll
        for (int i = 0; i < 4; i++)
            #pragma unroll
            for (int j = 0; j < 4; j++) o[qb][i][j] = 0.0f;
    float lsum[2][2] = {{0.0f, 0.0f}, {0.0f, 0.0f}};

    // ldmatrix lane addressing
    int vkey = lane & 15;
    int vdim = (lane >> 4) << 3;
    int klrow = ((lane >> 4) << 3) + (lane & 7);
    int kdoff = ((lane >> 3) & 1) * 8;

    for (int kt = 0; kt < NT; kt++) {
        int buf = kt & 1;
        CP_WAIT0();
        __syncthreads();
        if (kt + 1 < NT) {
            size_t off = (size_t)(kt + 1) * 64 * CDIM;
            u32 d0 = sd0 + (u32)((kt + 1) & 1) * 10240;
            u32 d1 = sd1 + (u32)((kt + 1) & 1) * 10240;
            cpa16(d0,         g_kh + gb0 + off);
            cpa16(d0 + 5120,  g_vh + gb0 + off);
            cpa16(d1,         g_kh + gb1 + off);
            cpa16(d1 + 5120,  g_vh + gb1 + off);
            CP_COMMIT();
        }

        u32 kbase = sb + (u32)buf * 10240;

        // ---- S in fp16 accumulators: ph[qb][np] = P fragment directly ----
        // ph[qb][np][0,1] = keys np*16+c2(+1), rows r / r+8
        // ph[qb][np][2,3] = keys np*16+8+c2(+1), rows r / r+8
        u32 ph[2][4][4];
        #pragma unroll
        for (int qb = 0; qb < 2; qb++)
            #pragma unroll
            for (int np = 0; np < 4; np++)
                #pragma unroll
                for (int j = 0; j < 4; j++) ph[qb][np][j] = 0;

        #pragma unroll
        for (int kc = 0; kc < 2; kc++)
            #pragma unroll
            for (int np = 0; np < 4; np++) {
                u32 kb[4];
                u32 addr = kbase +
                    (u32)(((np * 16 + klrow) * KST) + kc * 16 + kdoff) * 2;
                ldmat4(kb, addr);
                mma16816hh(&ph[0][np][0], qh[0][kc], kb[0], kb[1]);
                mma16816hh(&ph[0][np][2], qh[0][kc], kb[2], kb[3]);
                mma16816hh(&ph[1][np][0], qh[1][kc], kb[0], kb[1]);
                mma16816hh(&ph[1][np][2], qh[1][kc], kb[2], kb[3]);
            }

        // ---- softmax: ex2.f16x2 in place; row sums via HADD2 ----
        #pragma unroll
        for (int qb = 0; qb < 2; qb++) {
            u32 acc0 = 0, acc1 = 0;     // rows r / r+8
            #pragma unroll
            for (int np = 0; np < 4; np++) {
                ph[qb][np][0] = ex2h2(ph[qb][np][0]);
                ph[qb][np][1] = ex2h2(ph[qb][np][1]);
                ph[qb][np][2] = ex2h2(ph[qb][np][2]);
                ph[qb][np][3] = ex2h2(ph[qb][np][3]);
                acc0 = hadd2(acc0, ph[qb][np][0]);
                acc0 = hadd2(acc0, ph[qb][np][2]);
                acc1 = hadd2(acc1, ph[qb][np][1]);
                acc1 = hadd2(acc1, ph[qb][np][3]);
            }
            float2 a0 = h22f2(acc0), a1 = h22f2(acc1);
            lsum[qb][0] += a0.x + a0.y;
            lsum[qb][1] += a1.x + a1.y;
        }

        // ---- O += P V : V fragments shared across both q-blocks ----
        u32 vhb = kbase + 5120;
        #pragma unroll
        for (int kc2 = 0; kc2 < 4; kc2++) {
            u32 a0 = (u32)(((kc2 * 16 + vkey) * KST) + vdim) * 2;
            u32 a1 = a0 + 32;
            u32 vh0[4], vh1[4];
            ldmat4t(vh0, vhb + a0);
            ldmat4t(vh1, vhb + a1);
            mma16816h(o[0][0], ph[0][kc2], vh0[0], vh0[1]);
            mma16816h(o[0][1], ph[0][kc2], vh0[2], vh0[3]);
            mma16816h(o[0][2], ph[0][kc2], vh1[0], vh1[1]);
            mma16816h(o[0][3], ph[0][kc2], vh1[2], vh1[3]);
            mma16816h(o[1][0], ph[1][kc2], vh0[0], vh0[1]);
            mma16816h(o[1][1], ph[1][kc2], vh0[2], vh0[3]);
            mma16816h(o[1][2], ph[1][kc2], vh1[0], vh1[1]);
            mma16816h(o[1][3], ph[1][kc2], vh1[2], vh1[3]);
        }
    }

    // ---- epilogue ----
    #pragma unroll
    for (int qb = 0; qb < 2; qb++) {
        float l0 = lsum[qb][0], l1 = lsum[qb][1];
        l0 += __shfl_xor_sync(0xffffffffu, l0, 1);
        l0 += __shfl_xor_sync(0xffffffffu, l0, 2);
        l1 += __shfl_xor_sync(0xffffffffu, l1, 1);
        l1 += __shfl_xor_sync(0xffffffffu, l1, 2);
        float inv0 = 1.0f / l0, inv1 = 1.0f / l1;

        int row0 = q0 + w * 32 + qb * 16 + r;
        size_t o0 = ((size_t)(b * HW + row0)) * CDIM + h * DHEAD;
        size_t o1 = o0 + 8 * CDIM;
        #pragma unroll
        for (int nc2 = 0; nc2 < 4; nc2++) {
            u32 hh, ll;
            hsplit2(o[qb][nc2][0] * inv0, o[qb][nc2][1] * inv0, hh, ll);
            *(u32*)&g_aoh[o0 + nc2 * 8 + c2] = hh;
            *(u32*)&g_aol[o0 + nc2 * 8 + c2] = ll;
            hsplit2(o[qb][nc2][2] * inv1, o[qb][nc2][3] * inv1, hh, ll);
            *(u32*)&g_aoh[o1 + nc2 * 8 + c2] = hh;
            *(u32*)&g_aol[o1 + nc2 * 8 + c2] = ll;
        }
    }
}

// ---------------------------------------------------------------------------
extern "C" void kernel_launch(void* const* d_in, const int* in_sizes, int n_in,
                              void* d_out, int out_size)
{
    const float* x  = (const float*)d_in[0];
    const float* wq = (const float*)d_in[1];
    const float* bq = (const float*)d_in[2];
    const float* wk = (const float*)d_in[3];
    const float* bk = (const float*)d_in[4];
    const float* wv = (const float*)d_in[5];
    const float* bv = (const float*)d_in[6];
    const float* wo = (const float*)d_in[7];
    const float* bo = (const float*)d_in[8];

    const int PROJ_SMEM = PSTAGE * 2 * 2;   // 92160 bytes
    cudaFuncSetAttribute(k_proj_qkv, cudaFuncAttributeMaxDynamicSharedMemorySize, PROJ_SMEM);
    cudaFuncSetAttribute(k_proj_out, cudaFuncAttributeMaxDynamicSharedMemorySize, PROJ_SMEM);

    {   // 0) weights -> fp16 once
        k_split_w<<<256, 256>>>(wq, wk, wv, wo);
    }
    {   // 1) transpose + positional encoding -> fp16 hi/lo xs
        dim3 blk(32, 8);
        dim3 grd(HW / 32, CDIM / 32, BATCH);
        k_transpose_pe<<<grd, blk>>>(x);
    }
    {   // 2) QKV projections (fp16 2-pass)
        dim3 grd(CDIM / 64, MROWS / 128, 3);
        k_proj_qkv<<<grd, 256, PROJ_SMEM>>>(bq, bk, bv);
    }
    {   // 3) flash attention (fp16-acc S, in-place ex2 softmax)
        dim3 grd(HW / 128, BATCH * NHEAD);
        k_attn_mma<<<grd, 128>>>();
    }
    {   // 4) output projection (fp16 2-pass) + transpose to [b,c,h,w]
        dim3 grd(CDIM / 64, MROWS / 128);
        k_proj_out<<<grd, 256, PROJ_SMEM>>>(bo, (float*)d_out);
    }
}

// round 15
// speedup vs baseline: 8.9485x; 1.0164x over previous
#include <cuda_runtime.h>
#include <cuda_bf16.h>
#include <cuda_fp16.h>
#include <math.h>
#include <stdint.h>

#define BATCH 4
#define CDIM  256
#define HW    2304          // n = 48*48
#define MROWS (BATCH*HW)    // 9216
#define NHEAD 8
#define DHEAD 32

typedef unsigned long long u64;
typedef unsigned int u32;
typedef unsigned short u16;

// Scratch (static device memory). All inter-kernel tensors fp16.
__device__ __align__(16) u16 g_xsh[MROWS*CDIM];   // xs fp16 hi
__device__ __align__(16) u16 g_xsl[MROWS*CDIM];   // xs fp16 lo (residual)
__device__ __align__(16) u16 g_qh[MROWS*CDIM];    // Q fp16 (scaled by log2e/sqrt(32))
__device__ __align__(16) u16 g_kh[MROWS*CDIM];    // K fp16
__device__ __align__(16) u16 g_vh[MROWS*CDIM];    // V fp16
__device__ __align__(16) u16 g_aoh[MROWS*CDIM];   // attn out fp16 (single)
__device__ __align__(16) u16 g_wh[4*CDIM*CDIM];   // weights fp16 (single)

// ---------------------------------------------------------------------------
// helpers
// ---------------------------------------------------------------------------
__device__ __forceinline__ u32 hf2(float x0, float x1) {
    u32 r; asm("cvt.rn.f16x2.f32 %0, %1, %2;" : "=r"(r) : "f"(x1), "f"(x0));
    return r;
}
__device__ __forceinline__ void hsplit1(float x, u16& h, u16& l) {
    __half hb = __float2half_rn(x);
    float hf = __half2float(hb);
    __half lb = __float2half_rn(x - hf);
    h = *(u16*)&hb; l = *(u16*)&lb;
}
__device__ __forceinline__ u32 ex2h2(u32 v) {
    u32 r; asm("ex2.approx.f16x2 %0, %1;" : "=r"(r) : "r"(v));
    return r;
}
__device__ __forceinline__ u32 hadd2(u32 a, u32 b) {
    u32 r; asm("add.rn.f16x2 %0, %1, %2;" : "=r"(r) : "r"(a), "r"(b));
    return r;
}
__device__ __forceinline__ float2 h22f2(u32 v) {
    __half2 h = *(__half2*)&v;
    return __half22float2(h);
}
__device__ __forceinline__ void mma16816h(float d[4], const u32 a[4], u32 b0, u32 b1) {
    asm volatile("mma.sync.aligned.m16n8k16.row.col.f32.f16.f16.f32 "
        "{%0,%1,%2,%3}, {%4,%5,%6,%7}, {%8,%9}, {%0,%1,%2,%3};"
        : "+f"(d[0]), "+f"(d[1]), "+f"(d[2]), "+f"(d[3])
        : "r"(a[0]), "r"(a[1]), "r"(a[2]), "r"(a[3]), "r"(b0), "r"(b1));
}
// fp16-accumulator MMA: D (2x u32 = 4 halves) += A*B
__device__ __forceinline__ void mma16816hh(u32* d, const u32 a[4], u32 b0, u32 b1) {
    asm volatile("mma.sync.aligned.m16n8k16.row.col.f16.f16.f16.f16 "
        "{%0,%1}, {%2,%3,%4,%5}, {%6,%7}, {%0,%1};"
        : "+r"(d[0]), "+r"(d[1])
        : "r"(a[0]), "r"(a[1]), "r"(a[2]), "r"(a[3]), "r"(b0), "r"(b1));
}
__device__ __forceinline__ u32 smem_u32_(const void* p) {
    u32 a; asm("{ .reg .u64 t; cvta.to.shared.u64 t, %1; cvt.u32.u64 %0, t; }"
               : "=r"(a) : "l"(p)); return a;
}
__device__ __forceinline__ void cpa16(u32 dst, const void* src) {
    asm volatile("cp.async.cg.shared.global [%0], [%1], 16;"
                 :: "r"(dst), "l"(src) : "memory");
}
#define CP_COMMIT() asm volatile("cp.async.commit_group;" ::: "memory")
#define CP_WAIT0()  asm volatile("cp.async.wait_group 0;" ::: "memory")
__device__ __forceinline__ void ldmat4(u32 r[4], u32 addr) {
    asm volatile("ldmatrix.sync.aligned.m8n8.x4.shared.b16 {%0,%1,%2,%3}, [%4];"
        : "=r"(r[0]), "=r"(r[1]), "=r"(r[2]), "=r"(r[3]) : "r"(addr));
}
__device__ __forceinline__ void ldmat4t(u32 r[4], u32 addr) {
    asm volatile("ldmatrix.sync.aligned.m8n8.x4.trans.shared.b16 {%0,%1,%2,%3}, [%4];"
        : "=r"(r[0]), "=r"(r[1]), "=r"(r[2]), "=r"(r[3]) : "r"(addr));
}

// ---------------------------------------------------------------------------
// Kernel 0: convert weight matrices to fp16 once (4 x 256x256)
// ---------------------------------------------------------------------------
__global__ void k_split_w(const float* __restrict__ wq, const float* __restrict__ wk,
                          const float* __restrict__ wv, const float* __restrict__ wo)
{
    int idx = blockIdx.x * 256 + threadIdx.x;
    const float* ws[4] = { wq, wk, wv, wo };
    #pragma unroll
    for (int m = 0; m < 4; m++) {
        __half h = __float2half_rn(ws[m][idx]);
        g_wh[m * 65536 + idx] = *(u16*)&h;
    }
}

// ---------------------------------------------------------------------------
// Kernel 1: x [b,c,h,w] -> xs fp16 hi/lo [b,n,c] transpose + positional enc
// ---------------------------------------------------------------------------
__global__ void k_transpose_pe(const float* __restrict__ x)
{
    __shared__ float tile[32][33];
    int b  = blockIdx.z;
    int p0 = blockIdx.x * 32;
    int c0 = blockIdx.y * 32;
    int tx = threadIdx.x, ty = threadIdx.y;

    #pragma unroll
    for (int i = 0; i < 4; i++) {
        int cc = c0 + ty + i * 8;
        tile[ty + i * 8][tx] = x[((size_t)(b * CDIM + cc)) * HW + p0 + tx];
    }
    __syncthreads();
    #pragma unroll
    for (int i = 0; i < 4; i++) {
        int p  = p0 + ty + i * 8;
        int cc = c0 + tx;
        float v = tile[tx][ty + i * 8];
        float pe = 0.0f;
        if (p != 0) {
            float ang = (float)p * powf(10000.0f, -2.0f * (float)cc / 256.0f);
            pe = (cc & 1) ? cosf(ang) : sinf(ang);
        }
        float val = v + pe;
        u16 h, l; hsplit1(val, h, l);
        size_t idx = ((size_t)(b * HW + p)) * CDIM + cc;
        g_xsh[idx] = h;
        g_xsl[idx] = l;
    }
}

// ---------------------------------------------------------------------------
// Projection GEMM: out = A @ W^T + bias. ALO: A 2-pass (hi+lo) vs 1-pass.
// ---------------------------------------------------------------------------
#define PST   72
#define SA_H  0
#define SA_L  9216
#define SW    18432
#define PSTAGE 23040          // u16 per stage (46080 B); x2 = 92160 B

template<bool ALO>
__device__ __forceinline__ void proj_stage(
    u32 sbase, int buf, int m0, int n0, int k0, int tid,
    const u16* __restrict__ Agh, const u16* __restrict__ Agl,
    const u16* __restrict__ Wg)
{
    u32 b0 = sbase + (u32)buf * (PSTAGE * 2);
    #pragma unroll
    for (int it = 0; it < 4; it++) {
        int idx = tid + it * 256;
        int row = idx >> 3, c8 = (idx & 7) * 8;
        size_t gs = (size_t)(m0 + row) * CDIM + k0 + c8;
        u32 doff = (u32)(row * PST + c8) * 2;
        cpa16(b0 + SA_H * 2 + doff, Agh + gs);
        if (ALO) cpa16(b0 + SA_L * 2 + doff, Agl + gs);
    }
    #pragma unroll
    for (int it = 0; it < 2; it++) {
        int idx = tid + it * 256;
        int row = idx >> 3, c8 = (idx & 7) * 8;
        size_t gs = (size_t)(n0 + row) * CDIM + k0 + c8;
        u32 doff = (u32)(row * PST + c8) * 2;
        cpa16(b0 + SW * 2 + doff, Wg + gs);
    }
}

// OUT_MODE: 0 = fp16 single (QKV), 1 = fp32 transposed (final out)
template<int OUT_MODE, bool ALO>
__device__ __forceinline__ void proj_body(
    const u16* __restrict__ Agh, const u16* __restrict__ Agl,
    int widx, const float* __restrict__ bias,
    u16* __restrict__ outh, float* __restrict__ outf, float qs)
{
    extern __shared__ u16 smp[];
    int tid = threadIdx.x;
    int w = tid >> 5, lane = tid & 31;
    int r = lane >> 2, c2 = (lane & 3) * 2;
    int m0 = blockIdx.y * 128, n0 = blockIdx.x * 64;
    u32 sbase = smem_u32_(smp);
    const u16* Wg = g_wh + widx * 65536;

    float o[8][4];
    #pragma unroll
    for (int i = 0; i < 8; i++)
        #pragma unroll
        for (int j = 0; j < 4; j++) o[i][j] = 0.0f;

    proj_stage<ALO>(sbase, 0, m0, n0, 0, tid, Agh, Agl, Wg);
    CP_COMMIT();

    u32 arow = (u32)(w * 16 + (lane & 15));
    u32 acol = (u32)((lane >> 4) << 3);

    for (int c = 0; c < 4; c++) {
        CP_WAIT0();
        __syncthreads();
        if (c < 3) {
            proj_stage<ALO>(sbase, (c + 1) & 1, m0, n0, (c + 1) * 64, tid, Agh, Agl, Wg);
            CP_COMMIT();
        }

        int sb = (c & 1) * PSTAGE;
        const u16* sW = smp + sb + SW;
        u32 abase = sbase + (u32)sb * 2 + (arow * PST + acol) * 2;

        #pragma unroll
        for (int kc = 0; kc < 4; kc++) {
            u32 ah[4], al[4];
            u32 aoff = abase + (u32)(kc * 16) * 2;
            ldmat4(ah, aoff + SA_H * 2);
            if (ALO) ldmat4(al, aoff + SA_L * 2);
            #pragma unroll
            for (int nc = 0; nc < 8; nc++) {
                int off = (nc * 8 + r) * PST + kc * 16 + c2;
                u32 b0 = *(const u32*)&sW[off];
                u32 b1 = *(const u32*)&sW[off + 8];
                mma16816h(o[nc], ah, b0, b1);
                if (ALO) mma16816h(o[nc], al, b0, b1);
            }
        }
    }

    int mr0 = m0 + w * 16 + r;
    int mr1 = mr0 + 8;
    if (OUT_MODE == 0) {
        size_t r0off = (size_t)mr0 * CDIM + n0;
        size_t r1off = (size_t)mr1 * CDIM + n0;
        #pragma unroll
        for (int nc = 0; nc < 8; nc++) {
            float2 bi = *(const float2*)(bias + n0 + nc * 8 + c2);
            *(u32*)&outh[r0off + nc * 8 + c2] =
                hf2((o[nc][0] + bi.x) * qs, (o[nc][1] + bi.y) * qs);
            *(u32*)&outh[r1off + nc * 8 + c2] =
                hf2((o[nc][2] + bi.x) * qs, (o[nc][3] + bi.y) * qs);
        }
    } else {
        int bb0 = mr0 / HW, pp0 = mr0 % HW;
        int bb1 = mr1 / HW, pp1 = mr1 % HW;
        #pragma unroll
        for (int nc = 0; nc < 8; nc++) {
            float2 bi = *(const float2*)(bias + n0 + nc * 8 + c2);
            int nn = n0 + nc * 8 + c2;
            outf[((size_t)(bb0 * CDIM + nn)) * HW + pp0]     = o[nc][0] + bi.x;
            outf[((size_t)(bb0 * CDIM + nn + 1)) * HW + pp0] = o[nc][1] + bi.y;
            outf[((size_t)(bb1 * CDIM + nn)) * HW + pp1]     = o[nc][2] + bi.x;
            outf[((size_t)(bb1 * CDIM + nn + 1)) * HW + pp1] = o[nc][3] + bi.y;
        }
    }
}

// Q scale folds softmax's log2(e): (1/sqrt(32)) * log2(e)
#define QSCALE 0.25503472316688193f

__global__ void __launch_bounds__(256) k_proj_qkv(
    const float* __restrict__ bq, const float* __restrict__ bk,
    const float* __restrict__ bv)
{
    const float* bias; u16* outh; float qs;
    if (blockIdx.z == 0)      { bias = bq; outh = g_qh; qs = QSCALE; }
    else if (blockIdx.z == 1) { bias = bk; outh = g_kh; qs = 1.0f; }
    else                      { bias = bv; outh = g_vh; qs = 1.0f; }
    proj_body<0, true>(g_xsh, g_xsl, blockIdx.z, bias, outh, nullptr, qs);
}

__global__ void __launch_bounds__(256) k_proj_out(
    const float* __restrict__ bo, float* __restrict__ out)
{
    proj_body<1, false>(g_aoh, nullptr, 3, bo, nullptr, out, 1.0f);
}

// ---------------------------------------------------------------------------
// Kernel 3: flash attention. Block = 128 thr = 4 warps; warp owns 32 queries.
// Per 16-key chunk: S (fp16-acc) -> ex2 in place -> PV, interleaved so chunks
// pipeline on the tensor unit. PV keeps fp32 accumulators.
// ---------------------------------------------------------------------------
#define KST 40
#define NT  (HW / 64)

__global__ void __launch_bounds__(128, 4) k_attn_mma()
{
    __shared__ u16 sbuf[2][2][64 * KST];

    int tid = threadIdx.x;
    int w = tid >> 5, lane = tid & 31;
    int r = lane >> 2, c2 = (lane & 3) * 2;
    int b = blockIdx.y >> 3, h = blockIdx.y & 7;
    int q0 = blockIdx.x * 128;
    u32 sb = smem_u32_(&sbuf[0][0][0]);

    // staging: 128 threads x 2 chunks per array (rows row0 and row0+32)
    int srow = tid >> 2, sch = (tid & 3) * 8;
    size_t gb0 = ((size_t)(b * HW) + srow) * CDIM + h * DHEAD + sch;
    size_t gb1 = gb0 + (size_t)32 * CDIM;
    u32 sd0 = sb + (u32)(srow * KST + sch) * 2;
    u32 sd1 = sd0 + 32 * KST * 2;

    {   // prologue: stage tile 0
        cpa16(sd0,         g_kh + gb0);
        cpa16(sd0 + 5120,  g_vh + gb0);
        cpa16(sd1,         g_kh + gb1);
        cpa16(sd1 + 5120,  g_vh + gb1);
        CP_COMMIT();
    }

    // Q fragments: two 16-row blocks per warp
    u32 qh[2][2][4];
    #pragma unroll
    for (int qb = 0; qb < 2; qb++) {
        const u16* qhg = g_qh
            + ((size_t)(b * HW + q0 + w * 32 + qb * 16)) * CDIM + h * DHEAD;
        #pragma unroll
        for (int kc = 0; kc < 2; kc++)
            #pragma unroll
            for (int i = 0; i < 4; i++) {
                int rr = r + (i & 1) * 8;
                int cc = kc * 16 + c2 + (i >> 1) * 8;
                qh[qb][kc][i] = *(const u32*)(qhg + (size_t)rr * CDIM + cc);
            }
    }

    float o[2][4][4];
    #pragma unroll
    for (int qb = 0; qb < 2; qb++)
        #pragma unroll
        for (int i = 0; i < 4; i++)
            #pragma unroll
            for (int j = 0; j < 4; j++) o[qb][i][j] = 0.0f;
    float lsum[2][2] = {{0.0f, 0.0f}, {0.0f, 0.0f}};

    // ldmatrix lane addressing
    int vkey = lane & 15;
    int vdim = (lane >> 4) << 3;
    int klrow = ((lane >> 4) << 3) + (lane & 7);
    int kdoff = ((lane >> 3) & 1) * 8;

    for (int kt = 0; kt < NT; kt++) {
        int buf = kt & 1;
        CP_WAIT0();
        __syncthreads();
        if (kt + 1 < NT) {
            size_t off = (size_t)(kt + 1) * 64 * CDIM;
            u32 d0 = sd0 + (u32)((kt + 1) & 1) * 10240;
            u32 d1 = sd1 + (u32)((kt + 1) & 1) * 10240;
            cpa16(d0,         g_kh + gb0 + off);
            cpa16(d0 + 5120,  g_vh + gb0 + off);
            cpa16(d1,         g_kh + gb1 + off);
            cpa16(d1 + 5120,  g_vh + gb1 + off);
            CP_COMMIT();
        }

        u32 kbase = sb + (u32)buf * 10240;
        u32 vhb = kbase + 5120;
        u32 acc0q0 = 0, acc1q0 = 0, acc0q1 = 0, acc1q1 = 0;

        // ---- per 16-key chunk: S -> ex2 -> PV (chunks pipeline) ----
        #pragma unroll
        for (int np = 0; np < 4; np++) {
            u32 p0[4] = {0, 0, 0, 0};    // P fragment, q-block 0
            u32 p1[4] = {0, 0, 0, 0};    // P fragment, q-block 1
            #pragma unroll
            for (int kc = 0; kc < 2; kc++) {
                u32 kb[4];
                u32 addr = kbase +
                    (u32)(((np * 16 + klrow) * KST) + kc * 16 + kdoff) * 2;
                ldmat4(kb, addr);
                mma16816hh(&p0[0], qh[0][kc], kb[0], kb[1]);
                mma16816hh(&p0[2], qh[0][kc], kb[2], kb[3]);
                mma16816hh(&p1[0], qh[1][kc], kb[0], kb[1]);
                mma16816hh(&p1[2], qh[1][kc], kb[2], kb[3]);
            }
            // softmax in place
            p0[0] = ex2h2(p0[0]); p0[1] = ex2h2(p0[1]);
            p0[2] = ex2h2(p0[2]); p0[3] = ex2h2(p0[3]);
            p1[0] = ex2h2(p1[0]); p1[1] = ex2h2(p1[1]);
            p1[2] = ex2h2(p1[2]); p1[3] = ex2h2(p1[3]);
            acc0q0 = hadd2(acc0q0, hadd2(p0[0], p0[2]));
            acc1q0 = hadd2(acc1q0, hadd2(p0[1], p0[3]));
            acc0q1 = hadd2(acc0q1, hadd2(p1[0], p1[2]));
            acc1q1 = hadd2(acc1q1, hadd2(p1[1], p1[3]));

            // PV for this key chunk
            u32 a0 = (u32)(((np * 16 + vkey) * KST) + vdim) * 2;
            u32 vh0[4], vh1[4];
            ldmat4t(vh0, vhb + a0);
            ldmat4t(vh1, vhb + a0 + 32);
            mma16816h(o[0][0], p0, vh0[0], vh0[1]);
            mma16816h(o[0][1], p0, vh0[2], vh0[3]);
            mma16816h(o[0][2], p0, vh1[0], vh1[1]);
            mma16816h(o[0][3], p0, vh1[2], vh1[3]);
            mma16816h(o[1][0], p1, vh0[0], vh0[1]);
            mma16816h(o[1][1], p1, vh0[2], vh0[3]);
            mma16816h(o[1][2], p1, vh1[0], vh1[1]);
            mma16816h(o[1][3], p1, vh1[2], vh1[3]);
        }

        float2 a;
        a = h22f2(acc0q0); lsum[0][0] += a.x + a.y;
        a = h22f2(acc1q0); lsum[0][1] += a.x + a.y;
        a = h22f2(acc0q1); lsum[1][0] += a.x + a.y;
        a = h22f2(acc1q1); lsum[1][1] += a.x + a.y;
    }

    // ---- epilogue: single fp16 output ----
    #pragma unroll
    for (int qb = 0; qb < 2; qb++) {
        float l0 = lsum[qb][0], l1 = lsum[qb][1];
        l0 += __shfl_xor_sync(0xffffffffu, l0, 1);
        l0 += __shfl_xor_sync(0xffffffffu, l0, 2);
        l1 += __shfl_xor_sync(0xffffffffu, l1, 1);
        l1 += __shfl_xor_sync(0xffffffffu, l1, 2);
        float inv0 = 1.0f / l0, inv1 = 1.0f / l1;

        int row0 = q0 + w * 32 + qb * 16 + r;
        size_t o0 = ((size_t)(b * HW + row0)) * CDIM + h * DHEAD;
        size_t o1 = o0 + 8 * CDIM;
        #pragma unroll
        for (int nc2 = 0; nc2 < 4; nc2++) {
            *(u32*)&g_aoh[o0 + nc2 * 8 + c2] =
                hf2(o[qb][nc2][0] * inv0, o[qb][nc2][1] * inv0);
            *(u32*)&g_aoh[o1 + nc2 * 8 + c2] =
                hf2(o[qb][nc2][2] * inv1, o[qb][nc2][3] * inv1);
        }
    }
}

// ---------------------------------------------------------------------------
extern "C" void kernel_launch(void* const* d_in, const int* in_sizes, int n_in,
                              void* d_out, int out_size)
{
    const float* x  = (const float*)d_in[0];
    const float* wq = (const float*)d_in[1];
    const float* bq = (const float*)d_in[2];
    const float* wk = (const float*)d_in[3];
    const float* bk = (const float*)d_in[4];
    const float* wv = (const float*)d_in[5];
    const float* bv = (const float*)d_in[6];
    const float* wo = (const float*)d_in[7];
    const float* bo = (const float*)d_in[8];

    const int PROJ_SMEM = PSTAGE * 2 * 2;   // 92160 bytes
    cudaFuncSetAttribute(k_proj_qkv, cudaFuncAttributeMaxDynamicSharedMemorySize, PROJ_SMEM);
    cudaFuncSetAttribute(k_proj_out, cudaFuncAttributeMaxDynamicSharedMemorySize, PROJ_SMEM);

    {   // 0) weights -> fp16 once
        k_split_w<<<256, 256>>>(wq, wk, wv, wo);
    }
    {   // 1) transpose + positional encoding -> fp16 hi/lo xs
        dim3 blk(32, 8);
        dim3 grd(HW / 32, CDIM / 32, BATCH);
        k_transpose_pe<<<grd, blk>>>(x);
    }
    {   // 2) QKV projections (fp16 2-pass)
        dim3 grd(CDIM / 64, MROWS / 128, 3);
        k_proj_qkv<<<grd, 256, PROJ_SMEM>>>(bq, bk, bv);
    }
    {   // 3) flash attention (chunk-interleaved S/softmax/PV)
        dim3 grd(HW / 128, BATCH * NHEAD);
        k_attn_mma<<<grd, 128>>>();
    }
    {   // 4) output projection (fp16 1-pass) + transpose to [b,c,h,w]
        dim3 grd(CDIM / 64, MROWS / 128);
        k_proj_out<<<grd, 256, PROJ_SMEM>>>(bo, (float*)d_out);
    }
}

// round 16
// speedup vs baseline: 10.1111x; 1.1299x over previous
#include <cuda_runtime.h>
#include <cuda_bf16.h>
#include <cuda_fp16.h>
#include <math.h>
#include <stdint.h>

#define BATCH 4
#define CDIM  256
#define HW    2304          // n = 48*48
#define MROWS (BATCH*HW)    // 9216
#define NHEAD 8
#define DHEAD 32

typedef unsigned long long u64;
typedef unsigned int u32;
typedef unsigned short u16;

// Scratch (static device memory). All inter-kernel tensors single fp16.
__device__ __align__(16) u16 g_xsh[MROWS*CDIM];   // xs fp16
__device__ __align__(16) u16 g_qh[MROWS*CDIM];    // Q fp16 (scaled by log2e/sqrt(32))
__device__ __align__(16) u16 g_kh[MROWS*CDIM];    // K fp16
__device__ __align__(16) u16 g_vh[MROWS*CDIM];    // V fp16
__device__ __align__(16) u16 g_aoh[MROWS*CDIM];   // attn out fp16
__device__ __align__(16) u16 g_wh[4*CDIM*CDIM];   // weights fp16

// ---------------------------------------------------------------------------
// helpers
// ---------------------------------------------------------------------------
__device__ __forceinline__ u32 hf2(float x0, float x1) {
    u32 r; asm("cvt.rn.f16x2.f32 %0, %1, %2;" : "=r"(r) : "f"(x1), "f"(x0));
    return r;
}
__device__ __forceinline__ u32 ex2h2(u32 v) {
    u32 r; asm("ex2.approx.f16x2 %0, %1;" : "=r"(r) : "r"(v));
    return r;
}
__device__ __forceinline__ u32 hadd2(u32 a, u32 b) {
    u32 r; asm("add.rn.f16x2 %0, %1, %2;" : "=r"(r) : "r"(a), "r"(b));
    return r;
}
__device__ __forceinline__ float2 h22f2(u32 v) {
    __half2 h = *(__half2*)&v;
    return __half22float2(h);
}
__device__ __forceinline__ void mma16816h(float d[4], const u32 a[4], u32 b0, u32 b1) {
    asm volatile("mma.sync.aligned.m16n8k16.row.col.f32.f16.f16.f32 "
        "{%0,%1,%2,%3}, {%4,%5,%6,%7}, {%8,%9}, {%0,%1,%2,%3};"
        : "+f"(d[0]), "+f"(d[1]), "+f"(d[2]), "+f"(d[3])
        : "r"(a[0]), "r"(a[1]), "r"(a[2]), "r"(a[3]), "r"(b0), "r"(b1));
}
// fp16-accumulator MMA: D (2x u32 = 4 halves) += A*B
__device__ __forceinline__ void mma16816hh(u32* d, const u32 a[4], u32 b0, u32 b1) {
    asm volatile("mma.sync.aligned.m16n8k16.row.col.f16.f16.f16.f16 "
        "{%0,%1}, {%2,%3,%4,%5}, {%6,%7}, {%0,%1};"
        : "+r"(d[0]), "+r"(d[1])
        : "r"(a[0]), "r"(a[1]), "r"(a[2]), "r"(a[3]), "r"(b0), "r"(b1));
}
__device__ __forceinline__ u32 smem_u32_(const void* p) {
    u32 a; asm("{ .reg .u64 t; cvta.to.shared.u64 t, %1; cvt.u32.u64 %0, t; }"
               : "=r"(a) : "l"(p)); return a;
}
__device__ __forceinline__ void cpa16(u32 dst, const void* src) {
    asm volatile("cp.async.cg.shared.global [%0], [%1], 16;"
                 :: "r"(dst), "l"(src) : "memory");
}
#define CP_COMMIT() asm volatile("cp.async.commit_group;" ::: "memory")
#define CP_WAIT0()  asm volatile("cp.async.wait_group 0;" ::: "memory")
__device__ __forceinline__ void ldmat4(u32 r[4], u32 addr) {
    asm volatile("ldmatrix.sync.aligned.m8n8.x4.shared.b16 {%0,%1,%2,%3}, [%4];"
        : "=r"(r[0]), "=r"(r[1]), "=r"(r[2]), "=r"(r[3]) : "r"(addr));
}
__device__ __forceinline__ void ldmat4t(u32 r[4], u32 addr) {
    asm volatile("ldmatrix.sync.aligned.m8n8.x4.trans.shared.b16 {%0,%1,%2,%3}, [%4];"
        : "=r"(r[0]), "=r"(r[1]), "=r"(r[2]), "=r"(r[3]) : "r"(addr));
}

// ---------------------------------------------------------------------------
// Kernel 0: convert weight matrices to fp16 once (4 x 256x256)
// ---------------------------------------------------------------------------
__global__ void k_split_w(const float* __restrict__ wq, const float* __restrict__ wk,
                          const float* __restrict__ wv, const float* __restrict__ wo)
{
    int idx = blockIdx.x * 256 + threadIdx.x;
    const float* ws[4] = { wq, wk, wv, wo };
    #pragma unroll
    for (int m = 0; m < 4; m++) {
        __half h = __float2half_rn(ws[m][idx]);
        g_wh[m * 65536 + idx] = *(u16*)&h;
    }
}

// ---------------------------------------------------------------------------
// Kernel 1: x [b,c,h,w] -> xs fp16 [b,n,c] transpose + positional encoding
// ---------------------------------------------------------------------------
__global__ void k_transpose_pe(const float* __restrict__ x)
{
    __shared__ float tile[32][33];
    int b  = blockIdx.z;
    int p0 = blockIdx.x * 32;
    int c0 = blockIdx.y * 32;
    int tx = threadIdx.x, ty = threadIdx.y;

    #pragma unroll
    for (int i = 0; i < 4; i++) {
        int cc = c0 + ty + i * 8;
        tile[ty + i * 8][tx] = x[((size_t)(b * CDIM + cc)) * HW + p0 + tx];
    }
    __syncthreads();
    #pragma unroll
    for (int i = 0; i < 4; i++) {
        int p  = p0 + ty + i * 8;
        int cc = c0 + tx;
        float v = tile[tx][ty + i * 8];
        float pe = 0.0f;
        if (p != 0) {
            float ang = (float)p * powf(10000.0f, -2.0f * (float)cc / 256.0f);
            pe = (cc & 1) ? cosf(ang) : sinf(ang);
        }
        __half hv = __float2half_rn(v + pe);
        g_xsh[((size_t)(b * HW + p)) * CDIM + cc] = *(u16*)&hv;
    }
}

// ---------------------------------------------------------------------------
// Projection GEMM (fp16 1-pass): out = A @ W^T + bias
// Block = 256 thr = 8 warps; tile 128m x 64n; K chunks of 64 double-buffered.
// ---------------------------------------------------------------------------
#define PST   72
#define SA    0
#define SW    9216
#define PSTAGE 13824          // u16 per stage (27648 B); x2 = 55296 B

__device__ __forceinline__ void proj_stage(
    u32 sbase, int buf, int m0, int n0, int k0, int tid,
    const u16* __restrict__ Ag, const u16* __restrict__ Wg)
{
    u32 b0 = sbase + (u32)buf * (PSTAGE * 2);
    #pragma unroll
    for (int it = 0; it < 4; it++) {
        int idx = tid + it * 256;
        int row = idx >> 3, c8 = (idx & 7) * 8;
        size_t gs = (size_t)(m0 + row) * CDIM + k0 + c8;
        cpa16(b0 + SA * 2 + (u32)(row * PST + c8) * 2, Ag + gs);
    }
    #pragma unroll
    for (int it = 0; it < 2; it++) {
        int idx = tid + it * 256;
        int row = idx >> 3, c8 = (idx & 7) * 8;
        size_t gs = (size_t)(n0 + row) * CDIM + k0 + c8;
        cpa16(b0 + SW * 2 + (u32)(row * PST + c8) * 2, Wg + gs);
    }
}

// OUT_MODE: 0 = fp16 (QKV / attn-input), 1 = fp32 transposed (final out)
template<int OUT_MODE>
__device__ __forceinline__ void proj_body(
    const u16* __restrict__ Ag, int widx, const float* __restrict__ bias,
    u16* __restrict__ outh, float* __restrict__ outf, float qs)
{
    extern __shared__ u16 smp[];
    int tid = threadIdx.x;
    int w = tid >> 5, lane = tid & 31;
    int r = lane >> 2, c2 = (lane & 3) * 2;
    int m0 = blockIdx.y * 128, n0 = blockIdx.x * 64;
    u32 sbase = smem_u32_(smp);
    const u16* Wg = g_wh + widx * 65536;

    float o[8][4];
    #pragma unroll
    for (int i = 0; i < 8; i++)
        #pragma unroll
        for (int j = 0; j < 4; j++) o[i][j] = 0.0f;

    proj_stage(sbase, 0, m0, n0, 0, tid, Ag, Wg);
    CP_COMMIT();

    u32 arow = (u32)(w * 16 + (lane & 15));
    u32 acol = (u32)((lane >> 4) << 3);

    for (int c = 0; c < 4; c++) {
        CP_WAIT0();
        __syncthreads();
        if (c < 3) {
            proj_stage(sbase, (c + 1) & 1, m0, n0, (c + 1) * 64, tid, Ag, Wg);
            CP_COMMIT();
        }

        int sb = (c & 1) * PSTAGE;
        const u16* sW = smp + sb + SW;
        u32 abase = sbase + (u32)sb * 2 + (arow * PST + acol) * 2;

        #pragma unroll
        for (int kc = 0; kc < 4; kc++) {
            u32 ah[4];
            ldmat4(ah, abase + (u32)(kc * 16) * 2);
            #pragma unroll
            for (int nc = 0; nc < 8; nc++) {
                int off = (nc * 8 + r) * PST + kc * 16 + c2;
                u32 b0 = *(const u32*)&sW[off];
                u32 b1 = *(const u32*)&sW[off + 8];
                mma16816h(o[nc], ah, b0, b1);
            }
        }
    }

    int mr0 = m0 + w * 16 + r;
    int mr1 = mr0 + 8;
    if (OUT_MODE == 0) {
        size_t r0off = (size_t)mr0 * CDIM + n0;
        size_t r1off = (size_t)mr1 * CDIM + n0;
        #pragma unroll
        for (int nc = 0; nc < 8; nc++) {
            float2 bi = *(const float2*)(bias + n0 + nc * 8 + c2);
            *(u32*)&outh[r0off + nc * 8 + c2] =
                hf2((o[nc][0] + bi.x) * qs, (o[nc][1] + bi.y) * qs);
            *(u32*)&outh[r1off + nc * 8 + c2] =
                hf2((o[nc][2] + bi.x) * qs, (o[nc][3] + bi.y) * qs);
        }
    } else {
        int bb0 = mr0 / HW, pp0 = mr0 % HW;
        int bb1 = mr1 / HW, pp1 = mr1 % HW;
        #pragma unroll
        for (int nc = 0; nc < 8; nc++) {
            float2 bi = *(const float2*)(bias + n0 + nc * 8 + c2);
            int nn = n0 + nc * 8 + c2;
            outf[((size_t)(bb0 * CDIM + nn)) * HW + pp0]     = o[nc][0] + bi.x;
            outf[((size_t)(bb0 * CDIM + nn + 1)) * HW + pp0] = o[nc][1] + bi.y;
            outf[((size_t)(bb1 * CDIM + nn)) * HW + pp1]     = o[nc][2] + bi.x;
            outf[((size_t)(bb1 * CDIM + nn + 1)) * HW + pp1] = o[nc][3] + bi.y;
        }
    }
}

// Q scale folds softmax's log2(e): (1/sqrt(32)) * log2(e)
#define QSCALE 0.25503472316688193f

__global__ void __launch_bounds__(256) k_proj_qkv(
    const float* __restrict__ bq, const float* __restrict__ bk,
    const float* __restrict__ bv)
{
    const float* bias; u16* outh; float qs;
    if (blockIdx.z == 0)      { bias = bq; outh = g_qh; qs = QSCALE; }
    else if (blockIdx.z == 1) { bias = bk; outh = g_kh; qs = 1.0f; }
    else                      { bias = bv; outh = g_vh; qs = 1.0f; }
    proj_body<0>(g_xsh, blockIdx.z, bias, outh, nullptr, qs);
}

__global__ void __launch_bounds__(256) k_proj_out(
    const float* __restrict__ bo, float* __restrict__ out)
{
    proj_body<1>(g_aoh, 3, bo, nullptr, out, 1.0f);
}

// ---------------------------------------------------------------------------
// Kernel 3: flash attention (R14 batched structure — best measured).
// Block = 128 thr = 4 warps; warp owns 32 queries; fp16-acc S with in-place
// ex2 softmax; PV fp32 accumulators; single fp16 output.
// ---------------------------------------------------------------------------
#define KST 40
#define NT  (HW / 64)

__global__ void __launch_bounds__(128, 4) k_attn_mma()
{
    __shared__ u16 sbuf[2][2][64 * KST];

    int tid = threadIdx.x;
    int w = tid >> 5, lane = tid & 31;
    int r = lane >> 2, c2 = (lane & 3) * 2;
    int b = blockIdx.y >> 3, h = blockIdx.y & 7;
    int q0 = blockIdx.x * 128;
    u32 sb = smem_u32_(&sbuf[0][0][0]);

    // staging: 128 threads x 2 chunks per array (rows row0 and row0+32)
    int srow = tid >> 2, sch = (tid & 3) * 8;
    size_t gb0 = ((size_t)(b * HW) + srow) * CDIM + h * DHEAD + sch;
    size_t gb1 = gb0 + (size_t)32 * CDIM;
    u32 sd0 = sb + (u32)(srow * KST + sch) * 2;
    u32 sd1 = sd0 + 32 * KST * 2;

    {   // prologue: stage tile 0
        cpa16(sd0,         g_kh + gb0);
        cpa16(sd0 + 5120,  g_vh + gb0);
        cpa16(sd1,         g_kh + gb1);
        cpa16(sd1 + 5120,  g_vh + gb1);
        CP_COMMIT();
    }

    // Q fragments: two 16-row blocks per warp
    u32 qh[2][2][4];
    #pragma unroll
    for (int qb = 0; qb < 2; qb++) {
        const u16* qhg = g_qh
            + ((size_t)(b * HW + q0 + w * 32 + qb * 16)) * CDIM + h * DHEAD;
        #pragma unroll
        for (int kc = 0; kc < 2; kc++)
            #pragma unroll
            for (int i = 0; i < 4; i++) {
                int rr = r + (i & 1) * 8;
                int cc = kc * 16 + c2 + (i >> 1) * 8;
                qh[qb][kc][i] = *(const u32*)(qhg + (size_t)rr * CDIM + cc);
            }
    }

    float o[2][4][4];
    #pragma unroll
    for (int qb = 0; qb < 2; qb++)
        #pragma unroll
        for (int i = 0; i < 4; i++)
            #pragma unroll
            for (int j = 0; j < 4; j++) o[qb][i][j] = 0.0f;
    float lsum[2][2] = {{0.0f, 0.0f}, {0.0f, 0.0f}};

    // ldmatrix lane addressing
    int vkey = lane & 15;
    int vdim = (lane >> 4) << 3;
    int klrow = ((lane >> 4) << 3) + (lane & 7);
    int kdoff = ((lane >> 3) & 1) * 8;

    for (int kt = 0; kt < NT; kt++) {
        int buf = kt & 1;
        CP_WAIT0();
        __syncthreads();
        if (kt + 1 < NT) {
            size_t off = (size_t)(kt + 1) * 64 * CDIM;
            u32 d0 = sd0 + (u32)((kt + 1) & 1) * 10240;
            u32 d1 = sd1 + (u32)((kt + 1) & 1) * 10240;
            cpa16(d0,         g_kh + gb0 + off);
            cpa16(d0 + 5120,  g_vh + gb0 + off);
            cpa16(d1,         g_kh + gb1 + off);
            cpa16(d1 + 5120,  g_vh + gb1 + off);
            CP_COMMIT();
        }

        u32 kbase = sb + (u32)buf * 10240;

        // ---- S in fp16 accumulators: ph[qb][np] = P fragment directly ----
        u32 ph[2][4][4];
        #pragma unroll
        for (int qb = 0; qb < 2; qb++)
            #pragma unroll
            for (int np = 0; np < 4; np++)
                #pragma unroll
                for (int j = 0; j < 4; j++) ph[qb][np][j] = 0;

        #pragma unroll
        for (int kc = 0; kc < 2; kc++)
            #pragma unroll
            for (int np = 0; np < 4; np++) {
                u32 kb[4];
                u32 addr = kbase +
                    (u32)(((np * 16 + klrow) * KST) + kc * 16 + kdoff) * 2;
                ldmat4(kb, addr);
                mma16816hh(&ph[0][np][0], qh[0][kc], kb[0], kb[1]);
                mma16816hh(&ph[0][np][2], qh[0][kc], kb[2], kb[3]);
                mma16816hh(&ph[1][np][0], qh[1][kc], kb[0], kb[1]);
                mma16816hh(&ph[1][np][2], qh[1][kc], kb[2], kb[3]);
            }

        // ---- softmax: ex2.f16x2 in place; row sums via HADD2 ----
        #pragma unroll
        for (int qb = 0; qb < 2; qb++) {
            u32 acc0 = 0, acc1 = 0;     // rows r / r+8
            #pragma unroll
            for (int np = 0; np < 4; np++) {
                ph[qb][np][0] = ex2h2(ph[qb][np][0]);
                ph[qb][np][1] = ex2h2(ph[qb][np][1]);
                ph[qb][np][2] = ex2h2(ph[qb][np][2]);
                ph[qb][np][3] = ex2h2(ph[qb][np][3]);
                acc0 = hadd2(acc0, ph[qb][np][0]);
                acc0 = hadd2(acc0, ph[qb][np][2]);
                acc1 = hadd2(acc1, ph[qb][np][1]);
                acc1 = hadd2(acc1, ph[qb][np][3]);
            }
            float2 a0 = h22f2(acc0), a1 = h22f2(acc1);
            lsum[qb][0] += a0.x + a0.y;
            lsum[qb][1] += a1.x + a1.y;
        }

        // ---- O += P V : V fragments shared across both q-blocks ----
        u32 vhb = kbase + 5120;
        #pragma unroll
        for (int kc2 = 0; kc2 < 4; kc2++) {
            u32 a0 = (u32)(((kc2 * 16 + vkey) * KST) + vdim) * 2;
            u32 a1 = a0 + 32;
            u32 vh0[4], vh1[4];
            ldmat4t(vh0, vhb + a0);
            ldmat4t(vh1, vhb + a1);
            mma16816h(o[0][0], ph[0][kc2], vh0[0], vh0[1]);
            mma16816h(o[0][1], ph[0][kc2], vh0[2], vh0[3]);
            mma16816h(o[0][2], ph[0][kc2], vh1[0], vh1[1]);
            mma16816h(o[0][3], ph[0][kc2], vh1[2], vh1[3]);
            mma16816h(o[1][0], ph[1][kc2], vh0[0], vh0[1]);
            mma16816h(o[1][1], ph[1][kc2], vh0[2], vh0[3]);
            mma16816h(o[1][2], ph[1][kc2], vh1[0], vh1[1]);
            mma16816h(o[1][3], ph[1][kc2], vh1[2], vh1[3]);
        }
    }

    // ---- epilogue: single fp16 output ----
    #pragma unroll
    for (int qb = 0; qb < 2; qb++) {
        float l0 = lsum[qb][0], l1 = lsum[qb][1];
        l0 += __shfl_xor_sync(0xffffffffu, l0, 1);
        l0 += __shfl_xor_sync(0xffffffffu, l0, 2);
        l1 += __shfl_xor_sync(0xffffffffu, l1, 1);
        l1 += __shfl_xor_sync(0xffffffffu, l1, 2);
        float inv0 = 1.0f / l0, inv1 = 1.0f / l1;

        int row0 = q0 + w * 32 + qb * 16 + r;
        size_t o0 = ((size_t)(b * HW + row0)) * CDIM + h * DHEAD;
        size_t o1 = o0 + 8 * CDIM;
        #pragma unroll
        for (int nc2 = 0; nc2 < 4; nc2++) {
            *(u32*)&g_aoh[o0 + nc2 * 8 + c2] =
                hf2(o[qb][nc2][0] * inv0, o[qb][nc2][1] * inv0);
            *(u32*)&g_aoh[o1 + nc2 * 8 + c2] =
                hf2(o[qb][nc2][2] * inv1, o[qb][nc2][3] * inv1);
        }
    }
}

// ---------------------------------------------------------------------------
extern "C" void kernel_launch(void* const* d_in, const int* in_sizes, int n_in,
                              void* d_out, int out_size)
{
    const float* x  = (const float*)d_in[0];
    const float* wq = (const float*)d_in[1];
    const float* bq = (const float*)d_in[2];
    const float* wk = (const float*)d_in[3];
    const float* bk = (const float*)d_in[4];
    const float* wv = (const float*)d_in[5];
    const float* bv = (const float*)d_in[6];
    const float* wo = (const float*)d_in[7];
    const float* bo = (const float*)d_in[8];

    const int PROJ_SMEM = PSTAGE * 2 * 2;   // 55296 bytes
    cudaFuncSetAttribute(k_proj_qkv, cudaFuncAttributeMaxDynamicSharedMemorySize, PROJ_SMEM);
    cudaFuncSetAttribute(k_proj_out, cudaFuncAttributeMaxDynamicSharedMemorySize, PROJ_SMEM);

    {   // 0) weights -> fp16 once
        k_split_w<<<256, 256>>>(wq, wk, wv, wo);
    }
    {   // 1) transpose + positional encoding -> fp16 xs
        dim3 blk(32, 8);
        dim3 grd(HW / 32, CDIM / 32, BATCH);
        k_transpose_pe<<<grd, blk>>>(x);
    }
    {   // 2) QKV projections (fp16 1-pass)
        dim3 grd(CDIM / 64, MROWS / 128, 3);
        k_proj_qkv<<<grd, 256, PROJ_SMEM>>>(bq, bk, bv);
    }
    {   // 3) flash attention (batched S/softmax/PV — R14 structure)
        dim3 grd(HW / 128, BATCH * NHEAD);
        k_attn_mma<<<grd, 128>>>();
    }
    {   // 4) output projection (fp16 1-pass) + transpose to [b,c,h,w]
        dim3 grd(CDIM / 64, MROWS / 128);
        k_proj_out<<<grd, 256, PROJ_SMEM>>>(bo, (float*)d_out);
    }
}